// round 1
// baseline (speedup 1.0000x reference)
#include <cuda_runtime.h>
#include <cuda_bf16.h>
#include <math.h>

// Problem constants
#define BATCH   4
#define S_LEN   2048
#define D_MODEL 1024
#define NHEAD   16
#define HDIM    64

#define NEG_BIG (-1.0e9f)

// Scratch (static device globals: allowed; no runtime allocation)
__device__ float g_Q[(size_t)BATCH * S_LEN * D_MODEL];
__device__ float g_K[(size_t)BATCH * S_LEN * D_MODEL];
__device__ float g_V[(size_t)BATCH * S_LEN * D_MODEL];
__device__ float g_C[(size_t)BATCH * S_LEN * D_MODEL];

// ---------------------------------------------------------------------------
// SGEMM: C[M,N] = A[M,K] * B[K,N] + bias[N]
// 128x128 block tile, BK=8, 256 threads, 8x8 per-thread microtile (split
// 4+4 register layout for conflict-free float4 smem loads).
// ---------------------------------------------------------------------------
__global__ __launch_bounds__(256) void sgemm_bias_kernel(
    int M, int N, int K,
    const float* __restrict__ A, const float* __restrict__ B,
    const float* __restrict__ bias, float* __restrict__ C)
{
    __shared__ float As[8][128];   // transposed A tile
    __shared__ float Bs[8][128];

    const int tid = threadIdx.x;
    const int bx = blockIdx.x;     // N tile
    const int by = blockIdx.y;     // M tile
    const int tx = tid & 15;
    const int ty = tid >> 4;

    // A tile loads: 128 rows x 8 cols = 1024 floats, 1 float4 per thread
    const int aRow = tid >> 1;          // 0..127
    const int aCol = (tid & 1) * 4;     // 0 or 4
    // B tile loads: 8 rows x 128 cols
    const int bRow = tid >> 5;          // 0..7
    const int bCol = (tid & 31) * 4;    // 0..124

    const float* Ab = A + (size_t)(by * 128) * K;
    const float* Bb = B + bx * 128;

    float acc[8][8];
    #pragma unroll
    for (int i = 0; i < 8; i++)
        #pragma unroll
        for (int j = 0; j < 8; j++)
            acc[i][j] = 0.0f;

    for (int k0 = 0; k0 < K; k0 += 8) {
        float4 a4 = *(const float4*)(Ab + (size_t)aRow * K + k0 + aCol);
        As[aCol + 0][aRow] = a4.x;
        As[aCol + 1][aRow] = a4.y;
        As[aCol + 2][aRow] = a4.z;
        As[aCol + 3][aRow] = a4.w;
        *(float4*)(&Bs[bRow][bCol]) =
            *(const float4*)(Bb + (size_t)(k0 + bRow) * N + bCol);
        __syncthreads();

        #pragma unroll
        for (int k = 0; k < 8; k++) {
            float af[8], bf[8];
            *(float4*)(af)     = *(float4*)(&As[k][ty * 4]);
            *(float4*)(af + 4) = *(float4*)(&As[k][64 + ty * 4]);
            *(float4*)(bf)     = *(float4*)(&Bs[k][tx * 4]);
            *(float4*)(bf + 4) = *(float4*)(&Bs[k][64 + tx * 4]);
            #pragma unroll
            for (int i = 0; i < 8; i++)
                #pragma unroll
                for (int j = 0; j < 8; j++)
                    acc[i][j] += af[i] * bf[j];
        }
        __syncthreads();
    }

    // Write out with bias (float4 stores, rows split r and r+64)
    #pragma unroll
    for (int ih = 0; ih < 2; ih++) {
        #pragma unroll
        for (int i = 0; i < 4; i++) {
            int r = by * 128 + ih * 64 + ty * 4 + i;
            #pragma unroll
            for (int jh = 0; jh < 2; jh++) {
                int c = bx * 128 + jh * 64 + tx * 4;
                float4 bsv = *(const float4*)(bias + c);
                float4 o;
                o.x = acc[ih * 4 + i][jh * 4 + 0] + bsv.x;
                o.y = acc[ih * 4 + i][jh * 4 + 1] + bsv.y;
                o.z = acc[ih * 4 + i][jh * 4 + 2] + bsv.z;
                o.w = acc[ih * 4 + i][jh * 4 + 3] + bsv.w;
                *(float4*)(C + (size_t)r * N + c) = o;
            }
        }
    }
}

// ---------------------------------------------------------------------------
// Flash attention (fp32). One block per (b, h, 64 q-rows).
// BQ=64 q rows, BKV=32 kv rows per iteration, online softmax.
// Q/K/V are [B, S, D] with head h at column offset h*HDIM.
// ---------------------------------------------------------------------------
#define BQ  64
#define BKV 32

__global__ __launch_bounds__(256) void attn_kernel(
    const float* __restrict__ Q, const float* __restrict__ K,
    const float* __restrict__ V, const int* __restrict__ mask,
    float* __restrict__ ctx)
{
    __shared__ float Qs[BQ][HDIM];           // 16 KB
    __shared__ float Kts[HDIM][BKV + 1];     // K transposed, 8.25 KB
    __shared__ float Vs[BKV][HDIM];          // 8 KB
    __shared__ float Ps[BQ][BKV + 1];        // scores/probs, 8.25 KB
    __shared__ float alphaS[BQ];
    __shared__ int   maskS[BKV];

    const int tid = threadIdx.x;
    const int q0 = blockIdx.x * BQ;
    const int h  = blockIdx.y;
    const int b  = blockIdx.z;

    const size_t base = ((size_t)b * S_LEN) * D_MODEL + (size_t)h * HDIM;

    const int tx = tid & 15;   // 0..15
    const int ty = tid >> 4;   // 0..15

    // Load Q tile: 64x64, 4 float4 per thread
    {
        int r  = tid >> 4;          // 0..15
        int c4 = (tid & 15) * 4;    // 0..60
        #pragma unroll
        for (int i = 0; i < 4; i++) {
            int row = r + i * 16;
            *(float4*)(&Qs[row][c4]) =
                *(const float4*)(Q + base + (size_t)(q0 + row) * D_MODEL + c4);
        }
    }

    float o[4][4];
    #pragma unroll
    for (int i = 0; i < 4; i++)
        #pragma unroll
        for (int j = 0; j < 4; j++)
            o[i][j] = 0.0f;

    float m_run = -1e30f, l_run = 0.0f;   // valid for tid < BQ (row = tid)

    for (int kv0 = 0; kv0 < S_LEN; kv0 += BKV) {
        __syncthreads();   // protect Kts/Vs/Ps reuse from previous iteration

        // Load K (transposed into Kts) and V (natural): 32x64 each.
        // 512 float4 per tensor -> 2 per thread.
        #pragma unroll
        for (int it = 0; it < 2; it++) {
            int idx = tid + it * 256;       // 0..511
            int row = idx >> 4;             // 0..31
            int c4  = (idx & 15) * 4;       // 0..60
            float4 kk = *(const float4*)(K + base + (size_t)(kv0 + row) * D_MODEL + c4);
            Kts[c4 + 0][row] = kk.x;
            Kts[c4 + 1][row] = kk.y;
            Kts[c4 + 2][row] = kk.z;
            Kts[c4 + 3][row] = kk.w;
            *(float4*)(&Vs[row][c4]) =
                *(const float4*)(V + base + (size_t)(kv0 + row) * D_MODEL + c4);
        }
        if (tid < BKV) maskS[tid] = mask[(size_t)b * S_LEN + kv0 + tid];
        __syncthreads();

        // Scores: each thread computes s[4 q][2 k]
        float s[4][2];
        #pragma unroll
        for (int i = 0; i < 4; i++) { s[i][0] = 0.0f; s[i][1] = 0.0f; }
        #pragma unroll 8
        for (int d = 0; d < HDIM; d++) {
            float a0 = Qs[ty * 4 + 0][d];
            float a1 = Qs[ty * 4 + 1][d];
            float a2 = Qs[ty * 4 + 2][d];
            float a3 = Qs[ty * 4 + 3][d];
            float b0 = Kts[d][tx * 2 + 0];
            float b1 = Kts[d][tx * 2 + 1];
            s[0][0] += a0 * b0;  s[0][1] += a0 * b1;
            s[1][0] += a1 * b0;  s[1][1] += a1 * b1;
            s[2][0] += a2 * b0;  s[2][1] += a2 * b1;
            s[3][0] += a3 * b0;  s[3][1] += a3 * b1;
        }
        #pragma unroll
        for (int i = 0; i < 4; i++) {
            #pragma unroll
            for (int jj = 0; jj < 2; jj++) {
                int kc = tx * 2 + jj;
                Ps[ty * 4 + i][kc] = maskS[kc] ? s[i][jj] : NEG_BIG;
            }
        }
        __syncthreads();

        // Online softmax: thread r < 64 owns row r
        if (tid < BQ) {
            float mnew = m_run;
            #pragma unroll
            for (int c = 0; c < BKV; c++) mnew = fmaxf(mnew, Ps[tid][c]);
            float alpha = __expf(m_run - mnew);
            float lsum = l_run * alpha;
            #pragma unroll
            for (int c = 0; c < BKV; c++) {
                float p = __expf(Ps[tid][c] - mnew);
                Ps[tid][c] = p;
                lsum += p;
            }
            m_run = mnew;
            l_run = lsum;
            alphaS[tid] = alpha;
        }
        __syncthreads();

        // O update: rescale then accumulate P*V. Thread (ty,tx): 4 q x 4 d.
        #pragma unroll
        for (int i = 0; i < 4; i++) {
            float al = alphaS[ty * 4 + i];
            #pragma unroll
            for (int j = 0; j < 4; j++) o[i][j] *= al;
        }
        #pragma unroll 4
        for (int kc = 0; kc < BKV; kc++) {
            float p0 = Ps[ty * 4 + 0][kc];
            float p1 = Ps[ty * 4 + 1][kc];
            float p2 = Ps[ty * 4 + 2][kc];
            float p3 = Ps[ty * 4 + 3][kc];
            float4 vv = *(float4*)(&Vs[kc][tx * 4]);
            o[0][0] += p0 * vv.x; o[0][1] += p0 * vv.y; o[0][2] += p0 * vv.z; o[0][3] += p0 * vv.w;
            o[1][0] += p1 * vv.x; o[1][1] += p1 * vv.y; o[1][2] += p1 * vv.z; o[1][3] += p1 * vv.w;
            o[2][0] += p2 * vv.x; o[2][1] += p2 * vv.y; o[2][2] += p2 * vv.z; o[2][3] += p2 * vv.w;
            o[3][0] += p3 * vv.x; o[3][1] += p3 * vv.y; o[3][2] += p3 * vv.z; o[3][3] += p3 * vv.w;
        }
    }

    // Finalize: scale by q-row mask / l and write ctx [B,S,D] layout
    __syncthreads();
    if (tid < BQ) {
        int qm = mask[(size_t)b * S_LEN + q0 + tid];
        alphaS[tid] = qm ? (1.0f / l_run) : 0.0f;
    }
    __syncthreads();
    #pragma unroll
    for (int i = 0; i < 4; i++) {
        int row = q0 + ty * 4 + i;
        float sc = alphaS[ty * 4 + i];
        float4 ov;
        ov.x = o[i][0] * sc;
        ov.y = o[i][1] * sc;
        ov.z = o[i][2] * sc;
        ov.w = o[i][3] * sc;
        *(float4*)(ctx + base + (size_t)row * D_MODEL + tx * 4) = ov;
    }
}

// ---------------------------------------------------------------------------
extern "C" void kernel_launch(void* const* d_in, const int* in_sizes, int n_in,
                              void* d_out, int out_size)
{
    (void)in_sizes; (void)n_in; (void)out_size;
    const float* x  = (const float*)d_in[0];
    const int*   pm = (const int*)  d_in[1];
    const float* Wq = (const float*)d_in[2];
    const float* bq = (const float*)d_in[3];
    const float* Wk = (const float*)d_in[4];
    const float* bk = (const float*)d_in[5];
    const float* Wv = (const float*)d_in[6];
    const float* bv = (const float*)d_in[7];
    const float* Wo = (const float*)d_in[8];
    const float* bo = (const float*)d_in[9];
    float* out = (float*)d_out;

    float *Qp, *Kp, *Vp, *Cp;
    cudaGetSymbolAddress((void**)&Qp, g_Q);
    cudaGetSymbolAddress((void**)&Kp, g_K);
    cudaGetSymbolAddress((void**)&Vp, g_V);
    cudaGetSymbolAddress((void**)&Cp, g_C);

    const int M = BATCH * S_LEN;      // 8192
    dim3 gblk(256);
    dim3 ggrid(D_MODEL / 128, M / 128);

    sgemm_bias_kernel<<<ggrid, gblk>>>(M, D_MODEL, D_MODEL, x,  Wq, bq, Qp);
    sgemm_bias_kernel<<<ggrid, gblk>>>(M, D_MODEL, D_MODEL, x,  Wk, bk, Kp);
    sgemm_bias_kernel<<<ggrid, gblk>>>(M, D_MODEL, D_MODEL, x,  Wv, bv, Vp);

    dim3 agrid(S_LEN / BQ, NHEAD, BATCH);
    attn_kernel<<<agrid, 256>>>(Qp, Kp, Vp, pm, Cp);

    sgemm_bias_kernel<<<ggrid, gblk>>>(M, D_MODEL, D_MODEL, Cp, Wo, bo, out);
}

// round 3
// speedup vs baseline: 1.2642x; 1.2642x over previous
#include <cuda_runtime.h>
#include <cuda_bf16.h>
#include <math.h>
#include <stdint.h>

// Problem constants
#define BATCH   4
#define S_LEN   2048
#define D_MODEL 1024
#define NHEAD   16
#define HDIM    64
#define MROWS   (BATCH * S_LEN)     // 8192

#define NEG_BIG (-1.0e9f)

// ---------------------------------------------------------------------------
// Scratch (static device globals)
// ---------------------------------------------------------------------------
__device__ __align__(1024) float g_Q[(size_t)MROWS * D_MODEL];
__device__ __align__(1024) float g_K[(size_t)MROWS * D_MODEL];
__device__ __align__(1024) float g_V[(size_t)MROWS * D_MODEL];
__device__ __align__(1024) float g_C[(size_t)MROWS * D_MODEL];

__device__ __align__(1024) __nv_bfloat16 g_xhi[(size_t)MROWS * D_MODEL];
__device__ __align__(1024) __nv_bfloat16 g_xlo[(size_t)MROWS * D_MODEL];
__device__ __align__(1024) __nv_bfloat16 g_chi[(size_t)MROWS * D_MODEL];
__device__ __align__(1024) __nv_bfloat16 g_clo[(size_t)MROWS * D_MODEL];
__device__ __align__(1024) __nv_bfloat16 g_wthi[4][(size_t)D_MODEL * D_MODEL];
__device__ __align__(1024) __nv_bfloat16 g_wtlo[4][(size_t)D_MODEL * D_MODEL];

// ---------------------------------------------------------------------------
// Helpers
// ---------------------------------------------------------------------------
__device__ __forceinline__ uint32_t smem_u32(const void* p) {
    uint32_t a;
    asm("{ .reg .u64 t; cvta.to.shared.u64 t, %1; cvt.u32.u64 %0, t; }"
        : "=r"(a) : "l"(p));
    return a;
}
__device__ __forceinline__ void cp_async16(uint32_t saddr, const void* gptr) {
    asm volatile("cp.async.cg.shared.global [%0], [%1], 16;"
                 :: "r"(saddr), "l"(__cvta_generic_to_global(gptr)));
}
__device__ __forceinline__ void cp_commit() {
    asm volatile("cp.async.commit_group;" ::: "memory");
}
template <int N>
__device__ __forceinline__ void cp_wait() {
    asm volatile("cp.async.wait_group %0;" :: "n"(N) : "memory");
}

// mma.sync m16n8k16 bf16 -> f32 accumulate (sm_80 PTX — legal at sm_103 target)
__device__ __forceinline__ void mma16816(float* d, const uint32_t* a, const uint32_t* b) {
    asm volatile(
        "mma.sync.aligned.m16n8k16.row.col.f32.bf16.bf16.f32 "
        "{%0,%1,%2,%3}, {%4,%5,%6,%7}, {%8,%9}, {%0,%1,%2,%3};"
        : "+f"(d[0]), "+f"(d[1]), "+f"(d[2]), "+f"(d[3])
        : "r"(a[0]), "r"(a[1]), "r"(a[2]), "r"(a[3]), "r"(b[0]), "r"(b[1]));
}

// ---------------------------------------------------------------------------
// Prep kernels
// ---------------------------------------------------------------------------
__global__ __launch_bounds__(256) void split_kernel(
    const float* __restrict__ in, __nv_bfloat16* __restrict__ hi,
    __nv_bfloat16* __restrict__ lo, int n4)
{
    int i = blockIdx.x * blockDim.x + threadIdx.x;
    if (i >= n4) return;
    float4 v = ((const float4*)in)[i];
    __nv_bfloat16 hx = __float2bfloat16(v.x);
    __nv_bfloat16 hy = __float2bfloat16(v.y);
    __nv_bfloat16 hz = __float2bfloat16(v.z);
    __nv_bfloat16 hw = __float2bfloat16(v.w);
    __nv_bfloat16 lx = __float2bfloat16(v.x - __bfloat162float(hx));
    __nv_bfloat16 ly = __float2bfloat16(v.y - __bfloat162float(hy));
    __nv_bfloat16 lz = __float2bfloat16(v.z - __bfloat162float(hz));
    __nv_bfloat16 lw = __float2bfloat16(v.w - __bfloat162float(hw));
    ((__nv_bfloat162*)hi)[2 * i + 0] = __nv_bfloat162(hx, hy);
    ((__nv_bfloat162*)hi)[2 * i + 1] = __nv_bfloat162(hz, hw);
    ((__nv_bfloat162*)lo)[2 * i + 0] = __nv_bfloat162(lx, ly);
    ((__nv_bfloat162*)lo)[2 * i + 1] = __nv_bfloat162(lz, lw);
}

// W [K,N] fp32 -> Wt hi/lo [N,K] bf16 (K contiguous, i.e. B col-major for mma)
__global__ __launch_bounds__(256) void transpose_split_kernel(
    const float* __restrict__ W, __nv_bfloat16* __restrict__ Thi,
    __nv_bfloat16* __restrict__ Tlo)
{
    __shared__ float t[32][33];
    int tx = threadIdx.x, ty = threadIdx.y;   // (32, 8)
    int n0 = blockIdx.x * 32, k0 = blockIdx.y * 32;
    #pragma unroll
    for (int j = 0; j < 4; j++)
        t[ty + 8 * j][tx] = W[(size_t)(k0 + ty + 8 * j) * D_MODEL + n0 + tx];
    __syncthreads();
    #pragma unroll
    for (int j = 0; j < 4; j++) {
        float v = t[tx][ty + 8 * j];
        __nv_bfloat16 h = __float2bfloat16(v);
        __nv_bfloat16 l = __float2bfloat16(v - __bfloat162float(h));
        size_t o = (size_t)(n0 + ty + 8 * j) * D_MODEL + k0 + tx;
        Thi[o] = h;
        Tlo[o] = l;
    }
}

// ---------------------------------------------------------------------------
// bf16-split GEMM via mma.sync: C[M,1024] = A*W^T + bias
// CTA tile 128x128, BK=32, double-buffered cp.async, 8 warps (2m x 4n),
// warp tile 64x32. 3 products: hi*hi + hi*lo + lo*hi.
// ---------------------------------------------------------------------------
#define ROWB    80                    // 32 bf16 = 64B data + 16B pad
#define TILEB   (128 * ROWB)          // 10240 B
#define STAGEB  (4 * TILEB)           // 40960 B (Ahi, Alo, Bhi, Blo)
#define GEMM_SMEM (2 * STAGEB)        // 81920 B

__global__ __launch_bounds__(256, 1) void gemm_mma_kernel(
    const __nv_bfloat16* __restrict__ Ahi, const __nv_bfloat16* __restrict__ Alo,
    const __nv_bfloat16* __restrict__ Bhi, const __nv_bfloat16* __restrict__ Blo,
    const float* __restrict__ bias, float* __restrict__ C)
{
    extern __shared__ __align__(128) char sm[];
    const int tid  = threadIdx.x;
    const int lane = tid & 31;
    const int w    = tid >> 5;
    const int wm   = w & 1;        // 0..1 (m)
    const int wn   = w >> 1;       // 0..3 (n)
    const int m0 = blockIdx.y * 128;
    const int n0 = blockIdx.x * 128;
    const int g  = lane >> 2;      // 0..7
    const int t4 = lane & 3;       // 0..3

    const __nv_bfloat16* gsrc[4] = {Ahi, Alo, Bhi, Blo};

    float acc[4][4][4];
    #pragma unroll
    for (int mt = 0; mt < 4; mt++)
        #pragma unroll
        for (int nt = 0; nt < 4; nt++)
            #pragma unroll
            for (int r = 0; r < 4; r++)
                acc[mt][nt][r] = 0.0f;

    auto load_stage = [&](int kc, int st) {
        char* base = sm + st * STAGEB;
        #pragma unroll
        for (int t = 0; t < 8; t++) {
            const int tile = t >> 1;                    // compile-time
            const int wi   = tid + (t & 1) * 256;       // 0..511
            const int row  = wi >> 2;
            const int ch   = wi & 3;
            const int rb   = (tile < 2) ? m0 : n0;
            const __nv_bfloat16* src =
                gsrc[tile] + (size_t)(rb + row) * D_MODEL + kc * 32 + ch * 8;
            uint32_t dst = smem_u32(base + tile * TILEB + row * ROWB + ch * 16);
            cp_async16(dst, src);
        }
        cp_commit();
    };

    auto compute_stage = [&](int st) {
        const char* base = sm + st * STAGEB;
        const char* pAh = base;
        const char* pAl = base + TILEB;
        const char* pBh = base + 2 * TILEB;
        const char* pBl = base + 3 * TILEB;
        #pragma unroll
        for (int kk = 0; kk < 2; kk++) {
            const int c = kk * 16 + t4 * 2;   // k element offset
            uint32_t ah[4][4], al[4][4], bh[4][2], bl[4][2];
            #pragma unroll
            for (int mt = 0; mt < 4; mt++) {
                int r = wm * 64 + mt * 16 + g;
                ah[mt][0] = *(const uint32_t*)(pAh + r * ROWB + c * 2);
                ah[mt][1] = *(const uint32_t*)(pAh + (r + 8) * ROWB + c * 2);
                ah[mt][2] = *(const uint32_t*)(pAh + r * ROWB + (c + 8) * 2);
                ah[mt][3] = *(const uint32_t*)(pAh + (r + 8) * ROWB + (c + 8) * 2);
                al[mt][0] = *(const uint32_t*)(pAl + r * ROWB + c * 2);
                al[mt][1] = *(const uint32_t*)(pAl + (r + 8) * ROWB + c * 2);
                al[mt][2] = *(const uint32_t*)(pAl + r * ROWB + (c + 8) * 2);
                al[mt][3] = *(const uint32_t*)(pAl + (r + 8) * ROWB + (c + 8) * 2);
            }
            #pragma unroll
            for (int nt = 0; nt < 4; nt++) {
                int n = wn * 32 + nt * 8 + g;
                bh[nt][0] = *(const uint32_t*)(pBh + n * ROWB + c * 2);
                bh[nt][1] = *(const uint32_t*)(pBh + n * ROWB + (c + 8) * 2);
                bl[nt][0] = *(const uint32_t*)(pBl + n * ROWB + c * 2);
                bl[nt][1] = *(const uint32_t*)(pBl + n * ROWB + (c + 8) * 2);
            }
            #pragma unroll
            for (int mt = 0; mt < 4; mt++)
                #pragma unroll
                for (int nt = 0; nt < 4; nt++) {
                    mma16816(acc[mt][nt], ah[mt], bh[nt]);
                    mma16816(acc[mt][nt], ah[mt], bl[nt]);
                    mma16816(acc[mt][nt], al[mt], bh[nt]);
                }
        }
    };

    load_stage(0, 0);
    const int NIT = D_MODEL / 32;   // 32
    for (int it = 0; it < NIT; it++) {
        int s = it & 1;
        if (it + 1 < NIT) { load_stage(it + 1, s ^ 1); cp_wait<1>(); }
        else              { cp_wait<0>(); }
        __syncthreads();
        compute_stage(s);
        __syncthreads();
    }

    // Epilogue: direct stores + bias
    #pragma unroll
    for (int mt = 0; mt < 4; mt++) {
        int r0 = m0 + wm * 64 + mt * 16 + g;
        #pragma unroll
        for (int nt = 0; nt < 4; nt++) {
            int col = n0 + wn * 32 + nt * 8 + t4 * 2;
            float b0 = bias[col], b1 = bias[col + 1];
            float2 v0 = make_float2(acc[mt][nt][0] + b0, acc[mt][nt][1] + b1);
            float2 v1 = make_float2(acc[mt][nt][2] + b0, acc[mt][nt][3] + b1);
            *(float2*)(C + (size_t)r0 * D_MODEL + col) = v0;
            *(float2*)(C + (size_t)(r0 + 8) * D_MODEL + col) = v1;
        }
    }
}

// ---------------------------------------------------------------------------
// Flash attention (fp32), unchanged from round 1.
// ---------------------------------------------------------------------------
#define BQ  64
#define BKV 32

__global__ __launch_bounds__(256) void attn_kernel(
    const float* __restrict__ Q, const float* __restrict__ K,
    const float* __restrict__ V, const int* __restrict__ mask,
    float* __restrict__ ctx)
{
    __shared__ float Qs[BQ][HDIM];
    __shared__ float Kts[HDIM][BKV + 1];
    __shared__ float Vs[BKV][HDIM];
    __shared__ float Ps[BQ][BKV + 1];
    __shared__ float alphaS[BQ];
    __shared__ int   maskS[BKV];

    const int tid = threadIdx.x;
    const int q0 = blockIdx.x * BQ;
    const int h  = blockIdx.y;
    const int b  = blockIdx.z;

    const size_t base = ((size_t)b * S_LEN) * D_MODEL + (size_t)h * HDIM;

    const int tx = tid & 15;
    const int ty = tid >> 4;

    {
        int r  = tid >> 4;
        int c4 = (tid & 15) * 4;
        #pragma unroll
        for (int i = 0; i < 4; i++) {
            int row = r + i * 16;
            *(float4*)(&Qs[row][c4]) =
                *(const float4*)(Q + base + (size_t)(q0 + row) * D_MODEL + c4);
        }
    }

    float o[4][4];
    #pragma unroll
    for (int i = 0; i < 4; i++)
        #pragma unroll
        for (int j = 0; j < 4; j++)
            o[i][j] = 0.0f;

    float m_run = -1e30f, l_run = 0.0f;

    for (int kv0 = 0; kv0 < S_LEN; kv0 += BKV) {
        __syncthreads();

        #pragma unroll
        for (int it = 0; it < 2; it++) {
            int idx = tid + it * 256;
            int row = idx >> 4;
            int c4  = (idx & 15) * 4;
            float4 kk = *(const float4*)(K + base + (size_t)(kv0 + row) * D_MODEL + c4);
            Kts[c4 + 0][row] = kk.x;
            Kts[c4 + 1][row] = kk.y;
            Kts[c4 + 2][row] = kk.z;
            Kts[c4 + 3][row] = kk.w;
            *(float4*)(&Vs[row][c4]) =
                *(const float4*)(V + base + (size_t)(kv0 + row) * D_MODEL + c4);
        }
        if (tid < BKV) maskS[tid] = mask[(size_t)b * S_LEN + kv0 + tid];
        __syncthreads();

        float s[4][2];
        #pragma unroll
        for (int i = 0; i < 4; i++) { s[i][0] = 0.0f; s[i][1] = 0.0f; }
        #pragma unroll 8
        for (int d = 0; d < HDIM; d++) {
            float a0 = Qs[ty * 4 + 0][d];
            float a1 = Qs[ty * 4 + 1][d];
            float a2 = Qs[ty * 4 + 2][d];
            float a3 = Qs[ty * 4 + 3][d];
            float b0 = Kts[d][tx * 2 + 0];
            float b1 = Kts[d][tx * 2 + 1];
            s[0][0] += a0 * b0;  s[0][1] += a0 * b1;
            s[1][0] += a1 * b0;  s[1][1] += a1 * b1;
            s[2][0] += a2 * b0;  s[2][1] += a2 * b1;
            s[3][0] += a3 * b0;  s[3][1] += a3 * b1;
        }
        #pragma unroll
        for (int i = 0; i < 4; i++) {
            #pragma unroll
            for (int jj = 0; jj < 2; jj++) {
                int kc = tx * 2 + jj;
                Ps[ty * 4 + i][kc] = maskS[kc] ? s[i][jj] : NEG_BIG;
            }
        }
        __syncthreads();

        if (tid < BQ) {
            float mnew = m_run;
            #pragma unroll
            for (int c = 0; c < BKV; c++) mnew = fmaxf(mnew, Ps[tid][c]);
            float alpha = __expf(m_run - mnew);
            float lsum = l_run * alpha;
            #pragma unroll
            for (int c = 0; c < BKV; c++) {
                float p = __expf(Ps[tid][c] - mnew);
                Ps[tid][c] = p;
                lsum += p;
            }
            m_run = mnew;
            l_run = lsum;
            alphaS[tid] = alpha;
        }
        __syncthreads();

        #pragma unroll
        for (int i = 0; i < 4; i++) {
            float al = alphaS[ty * 4 + i];
            #pragma unroll
            for (int j = 0; j < 4; j++) o[i][j] *= al;
        }
        #pragma unroll 4
        for (int kc = 0; kc < BKV; kc++) {
            float p0 = Ps[ty * 4 + 0][kc];
            float p1 = Ps[ty * 4 + 1][kc];
            float p2 = Ps[ty * 4 + 2][kc];
            float p3 = Ps[ty * 4 + 3][kc];
            float4 vv = *(float4*)(&Vs[kc][tx * 4]);
            o[0][0] += p0 * vv.x; o[0][1] += p0 * vv.y; o[0][2] += p0 * vv.z; o[0][3] += p0 * vv.w;
            o[1][0] += p1 * vv.x; o[1][1] += p1 * vv.y; o[1][2] += p1 * vv.z; o[1][3] += p1 * vv.w;
            o[2][0] += p2 * vv.x; o[2][1] += p2 * vv.y; o[2][2] += p2 * vv.z; o[2][3] += p2 * vv.w;
            o[3][0] += p3 * vv.x; o[3][1] += p3 * vv.y; o[3][2] += p3 * vv.z; o[3][3] += p3 * vv.w;
        }
    }

    __syncthreads();
    if (tid < BQ) {
        int qm = mask[(size_t)b * S_LEN + q0 + tid];
        alphaS[tid] = qm ? (1.0f / l_run) : 0.0f;
    }
    __syncthreads();
    #pragma unroll
    for (int i = 0; i < 4; i++) {
        int row = q0 + ty * 4 + i;
        float sc = alphaS[ty * 4 + i];
        float4 ov;
        ov.x = o[i][0] * sc;
        ov.y = o[i][1] * sc;
        ov.z = o[i][2] * sc;
        ov.w = o[i][3] * sc;
        *(float4*)(ctx + base + (size_t)row * D_MODEL + tx * 4) = ov;
    }
}

// ---------------------------------------------------------------------------
extern "C" void kernel_launch(void* const* d_in, const int* in_sizes, int n_in,
                              void* d_out, int out_size)
{
    (void)in_sizes; (void)n_in; (void)out_size;
    const float* x  = (const float*)d_in[0];
    const int*   pm = (const int*)  d_in[1];
    const float* Wq = (const float*)d_in[2];
    const float* bq = (const float*)d_in[3];
    const float* Wk = (const float*)d_in[4];
    const float* bk = (const float*)d_in[5];
    const float* Wv = (const float*)d_in[6];
    const float* bv = (const float*)d_in[7];
    const float* Wo = (const float*)d_in[8];
    const float* bo = (const float*)d_in[9];
    float* out = (float*)d_out;

    float *Qp, *Kp, *Vp, *Cp;
    cudaGetSymbolAddress((void**)&Qp, g_Q);
    cudaGetSymbolAddress((void**)&Kp, g_K);
    cudaGetSymbolAddress((void**)&Vp, g_V);
    cudaGetSymbolAddress((void**)&Cp, g_C);
    __nv_bfloat16 *xhi, *xlo, *chi, *clo, *wthi, *wtlo;
    cudaGetSymbolAddress((void**)&xhi, g_xhi);
    cudaGetSymbolAddress((void**)&xlo, g_xlo);
    cudaGetSymbolAddress((void**)&chi, g_chi);
    cudaGetSymbolAddress((void**)&clo, g_clo);
    cudaGetSymbolAddress((void**)&wthi, g_wthi);
    cudaGetSymbolAddress((void**)&wtlo, g_wtlo);

    cudaFuncSetAttribute(gemm_mma_kernel,
                         cudaFuncAttributeMaxDynamicSharedMemorySize, GEMM_SMEM);

    const size_t WSZ = (size_t)D_MODEL * D_MODEL;
    const int n4 = MROWS * D_MODEL / 4;

    // 1. split activations
    split_kernel<<<(n4 + 255) / 256, 256>>>(x, xhi, xlo, n4);

    // 2. transpose+split weights
    dim3 tgrid(D_MODEL / 32, D_MODEL / 32), tblk(32, 8);
    transpose_split_kernel<<<tgrid, tblk>>>(Wq, wthi + 0 * WSZ, wtlo + 0 * WSZ);
    transpose_split_kernel<<<tgrid, tblk>>>(Wk, wthi + 1 * WSZ, wtlo + 1 * WSZ);
    transpose_split_kernel<<<tgrid, tblk>>>(Wv, wthi + 2 * WSZ, wtlo + 2 * WSZ);
    transpose_split_kernel<<<tgrid, tblk>>>(Wo, wthi + 3 * WSZ, wtlo + 3 * WSZ);

    // 3. Q/K/V projections on tensor cores (mma.sync)
    dim3 ggrid(D_MODEL / 128, MROWS / 128);
    gemm_mma_kernel<<<ggrid, 256, GEMM_SMEM>>>(xhi, xlo, wthi + 0 * WSZ, wtlo + 0 * WSZ, bq, Qp);
    gemm_mma_kernel<<<ggrid, 256, GEMM_SMEM>>>(xhi, xlo, wthi + 1 * WSZ, wtlo + 1 * WSZ, bk, Kp);
    gemm_mma_kernel<<<ggrid, 256, GEMM_SMEM>>>(xhi, xlo, wthi + 2 * WSZ, wtlo + 2 * WSZ, bv, Vp);

    // 4. attention
    dim3 agrid(S_LEN / BQ, NHEAD, BATCH);
    attn_kernel<<<agrid, 256>>>(Qp, Kp, Vp, pm, Cp);

    // 5. output projection
    split_kernel<<<(n4 + 255) / 256, 256>>>(Cp, chi, clo, n4);
    gemm_mma_kernel<<<ggrid, 256, GEMM_SMEM>>>(chi, clo, wthi + 3 * WSZ, wtlo + 3 * WSZ, bo, out);
}

// round 4
// speedup vs baseline: 2.5423x; 2.0110x over previous
#include <cuda_runtime.h>
#include <cuda_bf16.h>
#include <math.h>
#include <stdint.h>

// Problem constants
#define BATCH   4
#define S_LEN   2048
#define D_MODEL 1024
#define NHEAD   16
#define HDIM    64
#define MROWS   (BATCH * S_LEN)     // 8192

#define NEG_BIG (-1.0e9f)

// ---------------------------------------------------------------------------
// Scratch (static device globals)
// ---------------------------------------------------------------------------
__device__ __align__(1024) float g_Q[(size_t)MROWS * D_MODEL];
__device__ __align__(1024) float g_K[(size_t)MROWS * D_MODEL];
__device__ __align__(1024) float g_V[(size_t)MROWS * D_MODEL];
__device__ __align__(1024) float g_C[(size_t)MROWS * D_MODEL];

__device__ __align__(1024) __nv_bfloat16 g_xhi[(size_t)MROWS * D_MODEL];
__device__ __align__(1024) __nv_bfloat16 g_xlo[(size_t)MROWS * D_MODEL];
__device__ __align__(1024) __nv_bfloat16 g_chi[(size_t)MROWS * D_MODEL];
__device__ __align__(1024) __nv_bfloat16 g_clo[(size_t)MROWS * D_MODEL];
__device__ __align__(1024) __nv_bfloat16 g_wthi[4][(size_t)D_MODEL * D_MODEL];
__device__ __align__(1024) __nv_bfloat16 g_wtlo[4][(size_t)D_MODEL * D_MODEL];

// mask compaction
__device__ int g_idx[BATCH][S_LEN];
__device__ int g_cnt[BATCH];

// ---------------------------------------------------------------------------
// Helpers
// ---------------------------------------------------------------------------
__device__ __forceinline__ uint32_t smem_u32(const void* p) {
    uint32_t a;
    asm("{ .reg .u64 t; cvta.to.shared.u64 t, %1; cvt.u32.u64 %0, t; }"
        : "=r"(a) : "l"(p));
    return a;
}
__device__ __forceinline__ void cp_async16(uint32_t saddr, const void* gptr) {
    asm volatile("cp.async.cg.shared.global [%0], [%1], 16;"
                 :: "r"(saddr), "l"(__cvta_generic_to_global(gptr)));
}
__device__ __forceinline__ void cp_commit() {
    asm volatile("cp.async.commit_group;" ::: "memory");
}
template <int N>
__device__ __forceinline__ void cp_wait() {
    asm volatile("cp.async.wait_group %0;" :: "n"(N) : "memory");
}

// mma.sync m16n8k16 bf16 -> f32 accumulate
__device__ __forceinline__ void mma16816(float* d, const uint32_t* a, const uint32_t* b) {
    asm volatile(
        "mma.sync.aligned.m16n8k16.row.col.f32.bf16.bf16.f32 "
        "{%0,%1,%2,%3}, {%4,%5,%6,%7}, {%8,%9}, {%0,%1,%2,%3};"
        : "+f"(d[0]), "+f"(d[1]), "+f"(d[2]), "+f"(d[3])
        : "r"(a[0]), "r"(a[1]), "r"(a[2]), "r"(a[3]), "r"(b[0]), "r"(b[1]));
}

// ---------------------------------------------------------------------------
// Prep kernels
// ---------------------------------------------------------------------------
__global__ __launch_bounds__(256) void split_kernel(
    const float* __restrict__ in, __nv_bfloat16* __restrict__ hi,
    __nv_bfloat16* __restrict__ lo, int n4)
{
    int i = blockIdx.x * blockDim.x + threadIdx.x;
    if (i >= n4) return;
    float4 v = ((const float4*)in)[i];
    __nv_bfloat16 hx = __float2bfloat16(v.x);
    __nv_bfloat16 hy = __float2bfloat16(v.y);
    __nv_bfloat16 hz = __float2bfloat16(v.z);
    __nv_bfloat16 hw = __float2bfloat16(v.w);
    __nv_bfloat16 lx = __float2bfloat16(v.x - __bfloat162float(hx));
    __nv_bfloat16 ly = __float2bfloat16(v.y - __bfloat162float(hy));
    __nv_bfloat16 lz = __float2bfloat16(v.z - __bfloat162float(hz));
    __nv_bfloat16 lw = __float2bfloat16(v.w - __bfloat162float(hw));
    ((__nv_bfloat162*)hi)[2 * i + 0] = __nv_bfloat162(hx, hy);
    ((__nv_bfloat162*)hi)[2 * i + 1] = __nv_bfloat162(hz, hw);
    ((__nv_bfloat162*)lo)[2 * i + 0] = __nv_bfloat162(lx, ly);
    ((__nv_bfloat162*)lo)[2 * i + 1] = __nv_bfloat162(lz, lw);
}

__global__ __launch_bounds__(256) void zero_kernel(float* __restrict__ p, int n4) {
    int i = blockIdx.x * blockDim.x + threadIdx.x;
    if (i < n4) ((float4*)p)[i] = make_float4(0.f, 0.f, 0.f, 0.f);
}

// W [K,N] fp32 -> Wt hi/lo [N,K] bf16
__global__ __launch_bounds__(256) void transpose_split_kernel(
    const float* __restrict__ W, __nv_bfloat16* __restrict__ Thi,
    __nv_bfloat16* __restrict__ Tlo)
{
    __shared__ float t[32][33];
    int tx = threadIdx.x, ty = threadIdx.y;   // (32, 8)
    int n0 = blockIdx.x * 32, k0 = blockIdx.y * 32;
    #pragma unroll
    for (int j = 0; j < 4; j++)
        t[ty + 8 * j][tx] = W[(size_t)(k0 + ty + 8 * j) * D_MODEL + n0 + tx];
    __syncthreads();
    #pragma unroll
    for (int j = 0; j < 4; j++) {
        float v = t[tx][ty + 8 * j];
        __nv_bfloat16 h = __float2bfloat16(v);
        __nv_bfloat16 l = __float2bfloat16(v - __bfloat162float(h));
        size_t o = (size_t)(n0 + ty + 8 * j) * D_MODEL + k0 + tx;
        Thi[o] = h;
        Tlo[o] = l;
    }
}

// Compact valid positions per batch (block scan, 256 threads x 8 elems)
__global__ __launch_bounds__(256) void build_idx_kernel(const int* __restrict__ mask) {
    __shared__ int part[256];
    int b = blockIdx.x, t = threadIdx.x;
    const int* m = mask + (size_t)b * S_LEN;
    int loc[8], s = 0;
    #pragma unroll
    for (int j = 0; j < 8; j++) { loc[j] = (m[t * 8 + j] != 0); s += loc[j]; }
    part[t] = s;
    __syncthreads();
    for (int off = 1; off < 256; off <<= 1) {
        int v = (t >= off) ? part[t - off] : 0;
        __syncthreads();
        part[t] += v;
        __syncthreads();
    }
    int p = part[t] - s;   // exclusive prefix
    #pragma unroll
    for (int j = 0; j < 8; j++)
        if (loc[j]) g_idx[b][p++] = t * 8 + j;
    if (t == 255) g_cnt[b] = part[255];
}

// ---------------------------------------------------------------------------
// bf16-split GEMM via mma.sync, 3-stage cp.async pipeline.
// ---------------------------------------------------------------------------
#define ROWB    80                    // 32 bf16 = 64B + 16B pad
#define TILEB   (128 * ROWB)          // 10240 B
#define STAGEB  (4 * TILEB)           // 40960 B
#define NSTAGE  3
#define GEMM_SMEM (NSTAGE * STAGEB)   // 122880 B

__global__ __launch_bounds__(256, 1) void gemm_mma_kernel(
    const __nv_bfloat16* __restrict__ Ahi, const __nv_bfloat16* __restrict__ Alo,
    const __nv_bfloat16* __restrict__ Bhi, const __nv_bfloat16* __restrict__ Blo,
    const float* __restrict__ bias, float* __restrict__ C)
{
    extern __shared__ __align__(128) char sm[];
    const int tid  = threadIdx.x;
    const int lane = tid & 31;
    const int w    = tid >> 5;
    const int wm   = w & 1;
    const int wn   = w >> 1;
    const int m0 = blockIdx.y * 128;
    const int n0 = blockIdx.x * 128;
    const int g  = lane >> 2;
    const int t4 = lane & 3;

    const __nv_bfloat16* gsrc[4] = {Ahi, Alo, Bhi, Blo};

    float acc[4][4][4];
    #pragma unroll
    for (int mt = 0; mt < 4; mt++)
        #pragma unroll
        for (int nt = 0; nt < 4; nt++)
            #pragma unroll
            for (int r = 0; r < 4; r++)
                acc[mt][nt][r] = 0.0f;

    auto load_stage = [&](int kc, int st) {
        char* base = sm + st * STAGEB;
        #pragma unroll
        for (int t = 0; t < 8; t++) {
            const int tile = t >> 1;
            const int wi   = tid + (t & 1) * 256;
            const int row  = wi >> 2;
            const int ch   = wi & 3;
            const int rb   = (tile < 2) ? m0 : n0;
            const __nv_bfloat16* src =
                gsrc[tile] + (size_t)(rb + row) * D_MODEL + kc * 32 + ch * 8;
            uint32_t dst = smem_u32(base + tile * TILEB + row * ROWB + ch * 16);
            cp_async16(dst, src);
        }
        cp_commit();
    };

    auto compute_stage = [&](int st) {
        const char* base = sm + st * STAGEB;
        const char* pAh = base;
        const char* pAl = base + TILEB;
        const char* pBh = base + 2 * TILEB;
        const char* pBl = base + 3 * TILEB;
        #pragma unroll
        for (int kk = 0; kk < 2; kk++) {
            const int c = kk * 16 + t4 * 2;
            uint32_t ah[4][4], al[4][4], bh[4][2], bl[4][2];
            #pragma unroll
            for (int mt = 0; mt < 4; mt++) {
                int r = wm * 64 + mt * 16 + g;
                ah[mt][0] = *(const uint32_t*)(pAh + r * ROWB + c * 2);
                ah[mt][1] = *(const uint32_t*)(pAh + (r + 8) * ROWB + c * 2);
                ah[mt][2] = *(const uint32_t*)(pAh + r * ROWB + (c + 8) * 2);
                ah[mt][3] = *(const uint32_t*)(pAh + (r + 8) * ROWB + (c + 8) * 2);
                al[mt][0] = *(const uint32_t*)(pAl + r * ROWB + c * 2);
                al[mt][1] = *(const uint32_t*)(pAl + (r + 8) * ROWB + c * 2);
                al[mt][2] = *(const uint32_t*)(pAl + r * ROWB + (c + 8) * 2);
                al[mt][3] = *(const uint32_t*)(pAl + (r + 8) * ROWB + (c + 8) * 2);
            }
            #pragma unroll
            for (int nt = 0; nt < 4; nt++) {
                int n = wn * 32 + nt * 8 + g;
                bh[nt][0] = *(const uint32_t*)(pBh + n * ROWB + c * 2);
                bh[nt][1] = *(const uint32_t*)(pBh + n * ROWB + (c + 8) * 2);
                bl[nt][0] = *(const uint32_t*)(pBl + n * ROWB + c * 2);
                bl[nt][1] = *(const uint32_t*)(pBl + n * ROWB + (c + 8) * 2);
            }
            #pragma unroll
            for (int mt = 0; mt < 4; mt++)
                #pragma unroll
                for (int nt = 0; nt < 4; nt++) {
                    mma16816(acc[mt][nt], ah[mt], bh[nt]);
                    mma16816(acc[mt][nt], ah[mt], bl[nt]);
                    mma16816(acc[mt][nt], al[mt], bh[nt]);
                }
        }
    };

    const int NIT = D_MODEL / 32;   // 32
    load_stage(0, 0);
    load_stage(1, 1);
    for (int it = 0; it < NIT; it++) {
        if (it + 2 < NIT) { load_stage(it + 2, (it + 2) % NSTAGE); cp_wait<2>(); }
        else if (it + 1 < NIT) { cp_wait<1>(); }
        else { cp_wait<0>(); }
        __syncthreads();
        compute_stage(it % NSTAGE);
        __syncthreads();
    }

    #pragma unroll
    for (int mt = 0; mt < 4; mt++) {
        int r0 = m0 + wm * 64 + mt * 16 + g;
        #pragma unroll
        for (int nt = 0; nt < 4; nt++) {
            int col = n0 + wn * 32 + nt * 8 + t4 * 2;
            float b0 = bias[col], b1 = bias[col + 1];
            float2 v0 = make_float2(acc[mt][nt][0] + b0, acc[mt][nt][1] + b1);
            float2 v1 = make_float2(acc[mt][nt][2] + b0, acc[mt][nt][3] + b1);
            *(float2*)(C + (size_t)r0 * D_MODEL + col) = v0;
            *(float2*)(C + (size_t)(r0 + 8) * D_MODEL + col) = v1;
        }
    }
}

// ---------------------------------------------------------------------------
// Flash attention over COMPACTED valid positions.
// Grid covers worst case; blocks beyond valid count exit early.
// ctx must be pre-zeroed (invalid q rows stay 0).
// ---------------------------------------------------------------------------
#define BQ  64
#define BKV 32

__global__ __launch_bounds__(256) void attn_kernel(
    const float* __restrict__ Q, const float* __restrict__ K,
    const float* __restrict__ V, float* __restrict__ ctx)
{
    __shared__ float Qs[BQ][HDIM];
    __shared__ float Kts[HDIM][BKV + 1];
    __shared__ float Vs[BKV][HDIM];
    __shared__ float Ps[BQ][BKV + 1];
    __shared__ float alphaS[BQ];
    __shared__ int   kidxS[BKV];

    const int tid = threadIdx.x;
    const int b   = blockIdx.z;
    const int h   = blockIdx.y;
    const int cnt = g_cnt[b];
    const int q0  = blockIdx.x * BQ;
    if (q0 >= cnt) return;

    const size_t base = ((size_t)b * S_LEN) * D_MODEL + (size_t)h * HDIM;

    const int tx = tid & 15;
    const int ty = tid >> 4;

    // Gather Q tile through index
    {
        int r  = tid >> 4;
        int c4 = (tid & 15) * 4;
        #pragma unroll
        for (int i = 0; i < 4; i++) {
            int row = r + i * 16;
            int qi = (q0 + row < cnt) ? g_idx[b][q0 + row] : g_idx[b][0];
            *(float4*)(&Qs[row][c4]) =
                *(const float4*)(Q + base + (size_t)qi * D_MODEL + c4);
        }
    }

    float o[4][4];
    #pragma unroll
    for (int i = 0; i < 4; i++)
        #pragma unroll
        for (int j = 0; j < 4; j++)
            o[i][j] = 0.0f;

    float m_run = -1e30f, l_run = 0.0f;

    for (int kv0 = 0; kv0 < cnt; kv0 += BKV) {
        __syncthreads();

        if (tid < BKV)
            kidxS[tid] = (kv0 + tid < cnt) ? g_idx[b][kv0 + tid] : g_idx[b][0];
        __syncthreads();

        #pragma unroll
        for (int it = 0; it < 2; it++) {
            int idx = tid + it * 256;
            int row = idx >> 4;
            int c4  = (idx & 15) * 4;
            int ki  = kidxS[row];
            float4 kk = *(const float4*)(K + base + (size_t)ki * D_MODEL + c4);
            Kts[c4 + 0][row] = kk.x;
            Kts[c4 + 1][row] = kk.y;
            Kts[c4 + 2][row] = kk.z;
            Kts[c4 + 3][row] = kk.w;
            *(float4*)(&Vs[row][c4]) =
                *(const float4*)(V + base + (size_t)ki * D_MODEL + c4);
        }
        __syncthreads();

        float s[4][2];
        #pragma unroll
        for (int i = 0; i < 4; i++) { s[i][0] = 0.0f; s[i][1] = 0.0f; }
        #pragma unroll 8
        for (int d = 0; d < HDIM; d++) {
            float a0 = Qs[ty * 4 + 0][d];
            float a1 = Qs[ty * 4 + 1][d];
            float a2 = Qs[ty * 4 + 2][d];
            float a3 = Qs[ty * 4 + 3][d];
            float b0 = Kts[d][tx * 2 + 0];
            float b1 = Kts[d][tx * 2 + 1];
            s[0][0] += a0 * b0;  s[0][1] += a0 * b1;
            s[1][0] += a1 * b0;  s[1][1] += a1 * b1;
            s[2][0] += a2 * b0;  s[2][1] += a2 * b1;
            s[3][0] += a3 * b0;  s[3][1] += a3 * b1;
        }
        #pragma unroll
        for (int i = 0; i < 4; i++) {
            #pragma unroll
            for (int jj = 0; jj < 2; jj++) {
                int kc = tx * 2 + jj;
                Ps[ty * 4 + i][kc] = (kv0 + kc < cnt) ? s[i][jj] : NEG_BIG;
            }
        }
        __syncthreads();

        if (tid < BQ) {
            float mnew = m_run;
            #pragma unroll
            for (int c = 0; c < BKV; c++) mnew = fmaxf(mnew, Ps[tid][c]);
            float alpha = __expf(m_run - mnew);
            float lsum = l_run * alpha;
            #pragma unroll
            for (int c = 0; c < BKV; c++) {
                float p = __expf(Ps[tid][c] - mnew);
                Ps[tid][c] = p;
                lsum += p;
            }
            m_run = mnew;
            l_run = lsum;
            alphaS[tid] = alpha;
        }
        __syncthreads();

        #pragma unroll
        for (int i = 0; i < 4; i++) {
            float al = alphaS[ty * 4 + i];
            #pragma unroll
            for (int j = 0; j < 4; j++) o[i][j] *= al;
        }
        #pragma unroll 4
        for (int kc = 0; kc < BKV; kc++) {
            float p0 = Ps[ty * 4 + 0][kc];
            float p1 = Ps[ty * 4 + 1][kc];
            float p2 = Ps[ty * 4 + 2][kc];
            float p3 = Ps[ty * 4 + 3][kc];
            float4 vv = *(float4*)(&Vs[kc][tx * 4]);
            o[0][0] += p0 * vv.x; o[0][1] += p0 * vv.y; o[0][2] += p0 * vv.z; o[0][3] += p0 * vv.w;
            o[1][0] += p1 * vv.x; o[1][1] += p1 * vv.y; o[1][2] += p1 * vv.z; o[1][3] += p1 * vv.w;
            o[2][0] += p2 * vv.x; o[2][1] += p2 * vv.y; o[2][2] += p2 * vv.z; o[2][3] += p2 * vv.w;
            o[3][0] += p3 * vv.x; o[3][1] += p3 * vv.y; o[3][2] += p3 * vv.z; o[3][3] += p3 * vv.w;
        }
    }

    __syncthreads();
    if (tid < BQ) alphaS[tid] = 1.0f / l_run;
    __syncthreads();
    #pragma unroll
    for (int i = 0; i < 4; i++) {
        int r = ty * 4 + i;
        if (q0 + r < cnt) {
            int qi = g_idx[b][q0 + r];
            float sc = alphaS[r];
            float4 ov;
            ov.x = o[i][0] * sc;
            ov.y = o[i][1] * sc;
            ov.z = o[i][2] * sc;
            ov.w = o[i][3] * sc;
            *(float4*)(ctx + base + (size_t)qi * D_MODEL + tx * 4) = ov;
        }
    }
}

// ---------------------------------------------------------------------------
extern "C" void kernel_launch(void* const* d_in, const int* in_sizes, int n_in,
                              void* d_out, int out_size)
{
    (void)in_sizes; (void)n_in; (void)out_size;
    const float* x  = (const float*)d_in[0];
    const int*   pm = (const int*)  d_in[1];
    const float* Wq = (const float*)d_in[2];
    const float* bq = (const float*)d_in[3];
    const float* Wk = (const float*)d_in[4];
    const float* bk = (const float*)d_in[5];
    const float* Wv = (const float*)d_in[6];
    const float* bv = (const float*)d_in[7];
    const float* Wo = (const float*)d_in[8];
    const float* bo = (const float*)d_in[9];
    float* out = (float*)d_out;

    float *Qp, *Kp, *Vp, *Cp;
    cudaGetSymbolAddress((void**)&Qp, g_Q);
    cudaGetSymbolAddress((void**)&Kp, g_K);
    cudaGetSymbolAddress((void**)&Vp, g_V);
    cudaGetSymbolAddress((void**)&Cp, g_C);
    __nv_bfloat16 *xhi, *xlo, *chi, *clo, *wthi, *wtlo;
    cudaGetSymbolAddress((void**)&xhi, g_xhi);
    cudaGetSymbolAddress((void**)&xlo, g_xlo);
    cudaGetSymbolAddress((void**)&chi, g_chi);
    cudaGetSymbolAddress((void**)&clo, g_clo);
    cudaGetSymbolAddress((void**)&wthi, g_wthi);
    cudaGetSymbolAddress((void**)&wtlo, g_wtlo);

    cudaFuncSetAttribute(gemm_mma_kernel,
                         cudaFuncAttributeMaxDynamicSharedMemorySize, GEMM_SMEM);

    const size_t WSZ = (size_t)D_MODEL * D_MODEL;
    const int n4 = MROWS * D_MODEL / 4;

    // prep: split, indices, zero ctx, transpose weights
    split_kernel<<<(n4 + 255) / 256, 256>>>(x, xhi, xlo, n4);
    build_idx_kernel<<<BATCH, 256>>>(pm);
    zero_kernel<<<(n4 + 255) / 256, 256>>>(Cp, n4);

    dim3 tgrid(D_MODEL / 32, D_MODEL / 32), tblk(32, 8);
    transpose_split_kernel<<<tgrid, tblk>>>(Wq, wthi + 0 * WSZ, wtlo + 0 * WSZ);
    transpose_split_kernel<<<tgrid, tblk>>>(Wk, wthi + 1 * WSZ, wtlo + 1 * WSZ);
    transpose_split_kernel<<<tgrid, tblk>>>(Wv, wthi + 2 * WSZ, wtlo + 2 * WSZ);
    transpose_split_kernel<<<tgrid, tblk>>>(Wo, wthi + 3 * WSZ, wtlo + 3 * WSZ);

    // projections
    dim3 ggrid(D_MODEL / 128, MROWS / 128);
    gemm_mma_kernel<<<ggrid, 256, GEMM_SMEM>>>(xhi, xlo, wthi + 0 * WSZ, wtlo + 0 * WSZ, bq, Qp);
    gemm_mma_kernel<<<ggrid, 256, GEMM_SMEM>>>(xhi, xlo, wthi + 1 * WSZ, wtlo + 1 * WSZ, bk, Kp);
    gemm_mma_kernel<<<ggrid, 256, GEMM_SMEM>>>(xhi, xlo, wthi + 2 * WSZ, wtlo + 2 * WSZ, bv, Vp);

    // attention on compacted positions
    dim3 agrid(S_LEN / BQ, NHEAD, BATCH);
    attn_kernel<<<agrid, 256>>>(Qp, Kp, Vp, Cp);

    // output projection
    split_kernel<<<(n4 + 255) / 256, 256>>>(Cp, chi, clo, n4);
    gemm_mma_kernel<<<ggrid, 256, GEMM_SMEM>>>(chi, clo, wthi + 3 * WSZ, wtlo + 3 * WSZ, bo, out);
}

// round 6
// speedup vs baseline: 3.4784x; 1.3682x over previous
#include <cuda_runtime.h>
#include <cuda_bf16.h>
#include <math.h>
#include <stdint.h>

// Problem constants
#define BATCH   4
#define S_LEN   2048
#define D_MODEL 1024
#define NHEAD   16
#define HDIM    64
#define MROWS   (BATCH * S_LEN)     // 8192

#define NEG_BIG (-1.0e9f)

// ---------------------------------------------------------------------------
// Scratch (static device globals)
// ---------------------------------------------------------------------------
__device__ __align__(1024) float g_Q[(size_t)MROWS * D_MODEL];   // compacted
__device__ __align__(1024) float g_K[(size_t)MROWS * D_MODEL];   // compacted
__device__ __align__(1024) float g_V[(size_t)MROWS * D_MODEL];   // compacted
__device__ __align__(1024) float g_C[(size_t)MROWS * D_MODEL];   // compacted ctx

__device__ __align__(1024) __nv_bfloat16 g_xhi[(size_t)MROWS * D_MODEL];
__device__ __align__(1024) __nv_bfloat16 g_xlo[(size_t)MROWS * D_MODEL];
__device__ __align__(1024) __nv_bfloat16 g_chi[(size_t)MROWS * D_MODEL];
__device__ __align__(1024) __nv_bfloat16 g_clo[(size_t)MROWS * D_MODEL];
__device__ __align__(1024) __nv_bfloat16 g_wthi[4][(size_t)D_MODEL * D_MODEL];
__device__ __align__(1024) __nv_bfloat16 g_wtlo[4][(size_t)D_MODEL * D_MODEL];

// mask compaction
__device__ int g_idx[BATCH][S_LEN];    // per-batch valid s positions
__device__ int g_cnt[BATCH];
__device__ int g_off[BATCH + 1];       // batch offsets; g_off[BATCH] = total
__device__ int g_gidx[MROWS];          // global valid row list (b*S + s)

// ---------------------------------------------------------------------------
// Helpers
// ---------------------------------------------------------------------------
__device__ __forceinline__ uint32_t smem_u32(const void* p) {
    uint32_t a;
    asm("{ .reg .u64 t; cvta.to.shared.u64 t, %1; cvt.u32.u64 %0, t; }"
        : "=r"(a) : "l"(p));
    return a;
}
__device__ __forceinline__ void cp_async16(uint32_t saddr, const void* gptr) {
    asm volatile("cp.async.cg.shared.global [%0], [%1], 16;"
                 :: "r"(saddr), "l"(__cvta_generic_to_global(gptr)));
}
__device__ __forceinline__ void cp_commit() {
    asm volatile("cp.async.commit_group;" ::: "memory");
}
template <int N>
__device__ __forceinline__ void cp_wait() {
    asm volatile("cp.async.wait_group %0;" :: "n"(N) : "memory");
}

// mma.sync m16n8k16 bf16 -> f32 accumulate
__device__ __forceinline__ void mma16816(float* d, const uint32_t* a, const uint32_t* b) {
    asm volatile(
        "mma.sync.aligned.m16n8k16.row.col.f32.bf16.bf16.f32 "
        "{%0,%1,%2,%3}, {%4,%5,%6,%7}, {%8,%9}, {%0,%1,%2,%3};"
        : "+f"(d[0]), "+f"(d[1]), "+f"(d[2]), "+f"(d[3])
        : "r"(a[0]), "r"(a[1]), "r"(a[2]), "r"(a[3]), "r"(b[0]), "r"(b[1]));
}

// ---------------------------------------------------------------------------
// Prep kernels
// ---------------------------------------------------------------------------
__global__ __launch_bounds__(256) void split_kernel(
    const float* __restrict__ in, __nv_bfloat16* __restrict__ hi,
    __nv_bfloat16* __restrict__ lo, int n4)
{
    int i = blockIdx.x * blockDim.x + threadIdx.x;
    if (i >= n4) return;
    float4 v = ((const float4*)in)[i];
    __nv_bfloat16 hx = __float2bfloat16(v.x);
    __nv_bfloat16 hy = __float2bfloat16(v.y);
    __nv_bfloat16 hz = __float2bfloat16(v.z);
    __nv_bfloat16 hw = __float2bfloat16(v.w);
    __nv_bfloat16 lx = __float2bfloat16(v.x - __bfloat162float(hx));
    __nv_bfloat16 ly = __float2bfloat16(v.y - __bfloat162float(hy));
    __nv_bfloat16 lz = __float2bfloat16(v.z - __bfloat162float(hz));
    __nv_bfloat16 lw = __float2bfloat16(v.w - __bfloat162float(hw));
    ((__nv_bfloat162*)hi)[2 * i + 0] = __nv_bfloat162(hx, hy);
    ((__nv_bfloat162*)hi)[2 * i + 1] = __nv_bfloat162(hz, hw);
    ((__nv_bfloat162*)lo)[2 * i + 0] = __nv_bfloat162(lx, ly);
    ((__nv_bfloat162*)lo)[2 * i + 1] = __nv_bfloat162(lz, lw);
}

// same but bounded by compacted row count (for ctx split)
__global__ __launch_bounds__(256) void split_cnt_kernel(
    const float* __restrict__ in, __nv_bfloat16* __restrict__ hi,
    __nv_bfloat16* __restrict__ lo)
{
    int n4 = g_off[BATCH] * (D_MODEL / 4);
    int i = blockIdx.x * blockDim.x + threadIdx.x;
    if (i >= n4) return;
    float4 v = ((const float4*)in)[i];
    __nv_bfloat16 hx = __float2bfloat16(v.x);
    __nv_bfloat16 hy = __float2bfloat16(v.y);
    __nv_bfloat16 hz = __float2bfloat16(v.z);
    __nv_bfloat16 hw = __float2bfloat16(v.w);
    __nv_bfloat16 lx = __float2bfloat16(v.x - __bfloat162float(hx));
    __nv_bfloat16 ly = __float2bfloat16(v.y - __bfloat162float(hy));
    __nv_bfloat16 lz = __float2bfloat16(v.z - __bfloat162float(hz));
    __nv_bfloat16 lw = __float2bfloat16(v.w - __bfloat162float(hw));
    ((__nv_bfloat162*)hi)[2 * i + 0] = __nv_bfloat162(hx, hy);
    ((__nv_bfloat162*)hi)[2 * i + 1] = __nv_bfloat162(hz, hw);
    ((__nv_bfloat162*)lo)[2 * i + 0] = __nv_bfloat162(lx, ly);
    ((__nv_bfloat162*)lo)[2 * i + 1] = __nv_bfloat162(lz, lw);
}

// fill out with broadcast bias (covers invalid rows exactly: ctx row = 0)
__global__ __launch_bounds__(256) void bias_fill_kernel(
    const float* __restrict__ bias, float* __restrict__ out)
{
    int i = blockIdx.x * blockDim.x + threadIdx.x;   // float4 index
    int c = (i & (D_MODEL / 4 - 1)) * 4;
    ((float4*)out)[i] = *(const float4*)(bias + c);
}

// W [K,N] fp32 -> Wt hi/lo [N,K] bf16
__global__ __launch_bounds__(256) void transpose_split_kernel(
    const float* __restrict__ W, __nv_bfloat16* __restrict__ Thi,
    __nv_bfloat16* __restrict__ Tlo)
{
    __shared__ float t[32][33];
    int tx = threadIdx.x, ty = threadIdx.y;   // (32, 8)
    int n0 = blockIdx.x * 32, k0 = blockIdx.y * 32;
    #pragma unroll
    for (int j = 0; j < 4; j++)
        t[ty + 8 * j][tx] = W[(size_t)(k0 + ty + 8 * j) * D_MODEL + n0 + tx];
    __syncthreads();
    #pragma unroll
    for (int j = 0; j < 4; j++) {
        float v = t[tx][ty + 8 * j];
        __nv_bfloat16 h = __float2bfloat16(v);
        __nv_bfloat16 l = __float2bfloat16(v - __bfloat162float(h));
        size_t o = (size_t)(n0 + ty + 8 * j) * D_MODEL + k0 + tx;
        Thi[o] = h;
        Tlo[o] = l;
    }
}

// Compact valid positions per batch (block scan, 256 threads x 8 elems)
__global__ __launch_bounds__(256) void build_idx_kernel(const int* __restrict__ mask) {
    __shared__ int part[256];
    int b = blockIdx.x, t = threadIdx.x;
    const int* m = mask + (size_t)b * S_LEN;
    int loc[8], s = 0;
    #pragma unroll
    for (int j = 0; j < 8; j++) { loc[j] = (m[t * 8 + j] != 0); s += loc[j]; }
    part[t] = s;
    __syncthreads();
    for (int off = 1; off < 256; off <<= 1) {
        int v = (t >= off) ? part[t - off] : 0;
        __syncthreads();
        part[t] += v;
        __syncthreads();
    }
    int p = part[t] - s;
    #pragma unroll
    for (int j = 0; j < 8; j++)
        if (loc[j]) g_idx[b][p++] = t * 8 + j;
    if (t == 255) g_cnt[b] = part[255];
}

// offsets + global row list
__global__ __launch_bounds__(256) void build_gidx_kernel() {
    __shared__ int off[BATCH + 1];
    if (threadIdx.x == 0) {
        off[0] = 0;
        for (int b = 0; b < BATCH; b++) off[b + 1] = off[b] + g_cnt[b];
        for (int b = 0; b <= BATCH; b++) g_off[b] = off[b];
    }
    __syncthreads();
    for (int b = 0; b < BATCH; b++) {
        int c = g_cnt[b], o = off[b];
        for (int i = threadIdx.x; i < c; i += 256)
            g_gidx[o + i] = b * S_LEN + g_idx[b][i];
    }
}

// ---------------------------------------------------------------------------
// bf16-split GEMM via mma.sync, 3-stage pipeline.
// sidx ALWAYS caches the scattered (global) row id g_gidx[m0+r];
// gatherA selects it for A loads, scatterC selects it for C stores.
// ---------------------------------------------------------------------------
#define ROWB    80
#define TILEB   (128 * ROWB)
#define STAGEB  (4 * TILEB)
#define NSTAGE  3
#define GEMM_SMEM (NSTAGE * STAGEB + 512)

__global__ __launch_bounds__(256, 1) void gemm_mma_kernel(
    const __nv_bfloat16* __restrict__ Ahi, const __nv_bfloat16* __restrict__ Alo,
    const __nv_bfloat16* __restrict__ Bhi, const __nv_bfloat16* __restrict__ Blo,
    const float* __restrict__ bias, float* __restrict__ C,
    int gatherA, int scatterC)
{
    extern __shared__ __align__(128) char sm[];
    int* sidx = (int*)(sm + NSTAGE * STAGEB);

    const int cnt = g_off[BATCH];
    const int m0 = blockIdx.y * 128;
    if (m0 >= cnt) return;
    const int n0 = blockIdx.x * 128;

    const int tid  = threadIdx.x;
    const int lane = tid & 31;
    const int w    = tid >> 5;
    const int wm   = w & 1;
    const int wn   = w >> 1;
    const int g    = lane >> 2;
    const int t4   = lane & 3;

    // cache scattered row ids (valid rows only; clamp tail to 0)
    if (tid < 128) {
        int r = tid;
        sidx[r] = (m0 + r < cnt) ? g_gidx[m0 + r] : g_gidx[0];
    }
    __syncthreads();

    const __nv_bfloat16* gsrc[4] = {Ahi, Alo, Bhi, Blo};

    float acc[4][4][4];
    #pragma unroll
    for (int mt = 0; mt < 4; mt++)
        #pragma unroll
        for (int nt = 0; nt < 4; nt++)
            #pragma unroll
            for (int r = 0; r < 4; r++)
                acc[mt][nt][r] = 0.0f;

    auto load_stage = [&](int kc, int st) {
        char* base = sm + st * STAGEB;
        #pragma unroll
        for (int t = 0; t < 8; t++) {
            const int tile = t >> 1;
            const int wi   = tid + (t & 1) * 256;
            const int row  = wi >> 2;
            const int ch   = wi & 3;
            int grow;
            if (tile < 2) {
                int ar = m0 + row;
                if (ar >= cnt) ar = m0;          // clamped valid compacted row
                grow = gatherA ? sidx[row] : ar;
            } else {
                grow = n0 + row;
            }
            const __nv_bfloat16* src =
                gsrc[tile] + (size_t)grow * D_MODEL + kc * 32 + ch * 8;
            uint32_t dst = smem_u32(base + tile * TILEB + row * ROWB + ch * 16);
            cp_async16(dst, src);
        }
        cp_commit();
    };

    auto compute_stage = [&](int st) {
        const char* base = sm + st * STAGEB;
        const char* pAh = base;
        const char* pAl = base + TILEB;
        const char* pBh = base + 2 * TILEB;
        const char* pBl = base + 3 * TILEB;
        #pragma unroll
        for (int kk = 0; kk < 2; kk++) {
            const int c = kk * 16 + t4 * 2;
            uint32_t ah[4][4], al[4][4], bh[4][2], bl[4][2];
            #pragma unroll
            for (int mt = 0; mt < 4; mt++) {
                int r = wm * 64 + mt * 16 + g;
                ah[mt][0] = *(const uint32_t*)(pAh + r * ROWB + c * 2);
                ah[mt][1] = *(const uint32_t*)(pAh + (r + 8) * ROWB + c * 2);
                ah[mt][2] = *(const uint32_t*)(pAh + r * ROWB + (c + 8) * 2);
                ah[mt][3] = *(const uint32_t*)(pAh + (r + 8) * ROWB + (c + 8) * 2);
                al[mt][0] = *(const uint32_t*)(pAl + r * ROWB + c * 2);
                al[mt][1] = *(const uint32_t*)(pAl + (r + 8) * ROWB + c * 2);
                al[mt][2] = *(const uint32_t*)(pAl + r * ROWB + (c + 8) * 2);
                al[mt][3] = *(const uint32_t*)(pAl + (r + 8) * ROWB + (c + 8) * 2);
            }
            #pragma unroll
            for (int nt = 0; nt < 4; nt++) {
                int n = wn * 32 + nt * 8 + g;
                bh[nt][0] = *(const uint32_t*)(pBh + n * ROWB + c * 2);
                bh[nt][1] = *(const uint32_t*)(pBh + n * ROWB + (c + 8) * 2);
                bl[nt][0] = *(const uint32_t*)(pBl + n * ROWB + c * 2);
                bl[nt][1] = *(const uint32_t*)(pBl + n * ROWB + (c + 8) * 2);
            }
            #pragma unroll
            for (int mt = 0; mt < 4; mt++)
                #pragma unroll
                for (int nt = 0; nt < 4; nt++) {
                    mma16816(acc[mt][nt], ah[mt], bh[nt]);
                    mma16816(acc[mt][nt], ah[mt], bl[nt]);
                    mma16816(acc[mt][nt], al[mt], bh[nt]);
                }
        }
    };

    const int NIT = D_MODEL / 32;
    load_stage(0, 0);
    load_stage(1, 1);
    for (int it = 0; it < NIT; it++) {
        if (it + 2 < NIT) { load_stage(it + 2, (it + 2) % NSTAGE); cp_wait<2>(); }
        else if (it + 1 < NIT) { cp_wait<1>(); }
        else { cp_wait<0>(); }
        __syncthreads();
        compute_stage(it % NSTAGE);
        __syncthreads();
    }

    #pragma unroll
    for (int mt = 0; mt < 4; mt++) {
        int rl = wm * 64 + mt * 16 + g;
        #pragma unroll
        for (int nt = 0; nt < 4; nt++) {
            int col = n0 + wn * 32 + nt * 8 + t4 * 2;
            float b0 = bias[col], b1 = bias[col + 1];
            if (m0 + rl < cnt) {
                int r = scatterC ? sidx[rl] : (m0 + rl);
                float2 v0 = make_float2(acc[mt][nt][0] + b0, acc[mt][nt][1] + b1);
                *(float2*)(C + (size_t)r * D_MODEL + col) = v0;
            }
            if (m0 + rl + 8 < cnt) {
                int r = scatterC ? sidx[rl + 8] : (m0 + rl + 8);
                float2 v1 = make_float2(acc[mt][nt][2] + b0, acc[mt][nt][3] + b1);
                *(float2*)(C + (size_t)r * D_MODEL + col) = v1;
            }
        }
    }
}

// ---------------------------------------------------------------------------
// Flash attention over compacted Q/K/V (contiguous rows per batch at g_off[b]).
// ---------------------------------------------------------------------------
#define BQ  64
#define BKV 32

__global__ __launch_bounds__(256) void attn_kernel(
    const float* __restrict__ Q, const float* __restrict__ K,
    const float* __restrict__ V, float* __restrict__ ctx)
{
    __shared__ float Qs[BQ][HDIM];
    __shared__ float Kts[HDIM][BKV + 1];
    __shared__ float Vs[BKV][HDIM];
    __shared__ float Ps[BQ][BKV + 1];
    __shared__ float alphaS[BQ];

    const int tid = threadIdx.x;
    const int b   = blockIdx.z;
    const int h   = blockIdx.y;
    const int cnt = g_cnt[b];
    const int off = g_off[b];
    const int q0  = blockIdx.x * BQ;
    if (q0 >= cnt) return;

    const size_t hcol = (size_t)h * HDIM;

    const int tx = tid & 15;
    const int ty = tid >> 4;

    {
        int r  = tid >> 4;
        int c4 = (tid & 15) * 4;
        #pragma unroll
        for (int i = 0; i < 4; i++) {
            int row = r + i * 16;
            int qi = (q0 + row < cnt) ? (off + q0 + row) : off;
            *(float4*)(&Qs[row][c4]) =
                *(const float4*)(Q + (size_t)qi * D_MODEL + hcol + c4);
        }
    }

    float o[4][4];
    #pragma unroll
    for (int i = 0; i < 4; i++)
        #pragma unroll
        for (int j = 0; j < 4; j++)
            o[i][j] = 0.0f;

    float m_run = -1e30f, l_run = 0.0f;

    for (int kv0 = 0; kv0 < cnt; kv0 += BKV) {
        __syncthreads();

        #pragma unroll
        for (int it = 0; it < 2; it++) {
            int idx = tid + it * 256;
            int row = idx >> 4;
            int c4  = (idx & 15) * 4;
            int ki  = (kv0 + row < cnt) ? (off + kv0 + row) : off;
            float4 kk = *(const float4*)(K + (size_t)ki * D_MODEL + hcol + c4);
            Kts[c4 + 0][row] = kk.x;
            Kts[c4 + 1][row] = kk.y;
            Kts[c4 + 2][row] = kk.z;
            Kts[c4 + 3][row] = kk.w;
            *(float4*)(&Vs[row][c4]) =
                *(const float4*)(V + (size_t)ki * D_MODEL + hcol + c4);
        }
        __syncthreads();

        float s[4][2];
        #pragma unroll
        for (int i = 0; i < 4; i++) { s[i][0] = 0.0f; s[i][1] = 0.0f; }
        #pragma unroll 8
        for (int d = 0; d < HDIM; d++) {
            float a0 = Qs[ty * 4 + 0][d];
            float a1 = Qs[ty * 4 + 1][d];
            float a2 = Qs[ty * 4 + 2][d];
            float a3 = Qs[ty * 4 + 3][d];
            float b0 = Kts[d][tx * 2 + 0];
            float b1 = Kts[d][tx * 2 + 1];
            s[0][0] += a0 * b0;  s[0][1] += a0 * b1;
            s[1][0] += a1 * b0;  s[1][1] += a1 * b1;
            s[2][0] += a2 * b0;  s[2][1] += a2 * b1;
            s[3][0] += a3 * b0;  s[3][1] += a3 * b1;
        }
        #pragma unroll
        for (int i = 0; i < 4; i++) {
            #pragma unroll
            for (int jj = 0; jj < 2; jj++) {
                int kc = tx * 2 + jj;
                Ps[ty * 4 + i][kc] = (kv0 + kc < cnt) ? s[i][jj] : NEG_BIG;
            }
        }
        __syncthreads();

        if (tid < BQ) {
            float mnew = m_run;
            #pragma unroll
            for (int c = 0; c < BKV; c++) mnew = fmaxf(mnew, Ps[tid][c]);
            float alpha = __expf(m_run - mnew);
            float lsum = l_run * alpha;
            #pragma unroll
            for (int c = 0; c < BKV; c++) {
                float p = __expf(Ps[tid][c] - mnew);
                Ps[tid][c] = p;
                lsum += p;
            }
            m_run = mnew;
            l_run = lsum;
            alphaS[tid] = alpha;
        }
        __syncthreads();

        #pragma unroll
        for (int i = 0; i < 4; i++) {
            float al = alphaS[ty * 4 + i];
            #pragma unroll
            for (int j = 0; j < 4; j++) o[i][j] *= al;
        }
        #pragma unroll 4
        for (int kc = 0; kc < BKV; kc++) {
            float p0 = Ps[ty * 4 + 0][kc];
            float p1 = Ps[ty * 4 + 1][kc];
            float p2 = Ps[ty * 4 + 2][kc];
            float p3 = Ps[ty * 4 + 3][kc];
            float4 vv = *(float4*)(&Vs[kc][tx * 4]);
            o[0][0] += p0 * vv.x; o[0][1] += p0 * vv.y; o[0][2] += p0 * vv.z; o[0][3] += p0 * vv.w;
            o[1][0] += p1 * vv.x; o[1][1] += p1 * vv.y; o[1][2] += p1 * vv.z; o[1][3] += p1 * vv.w;
            o[2][0] += p2 * vv.x; o[2][1] += p2 * vv.y; o[2][2] += p2 * vv.z; o[2][3] += p2 * vv.w;
            o[3][0] += p3 * vv.x; o[3][1] += p3 * vv.y; o[3][2] += p3 * vv.z; o[3][3] += p3 * vv.w;
        }
    }

    __syncthreads();
    if (tid < BQ) alphaS[tid] = 1.0f / l_run;
    __syncthreads();
    #pragma unroll
    for (int i = 0; i < 4; i++) {
        int r = ty * 4 + i;
        if (q0 + r < cnt) {
            float sc = alphaS[r];
            float4 ov;
            ov.x = o[i][0] * sc;
            ov.y = o[i][1] * sc;
            ov.z = o[i][2] * sc;
            ov.w = o[i][3] * sc;
            *(float4*)(ctx + (size_t)(off + q0 + r) * D_MODEL + hcol + tx * 4) = ov;
        }
    }
}

// ---------------------------------------------------------------------------
extern "C" void kernel_launch(void* const* d_in, const int* in_sizes, int n_in,
                              void* d_out, int out_size)
{
    (void)in_sizes; (void)n_in; (void)out_size;
    const float* x  = (const float*)d_in[0];
    const int*   pm = (const int*)  d_in[1];
    const float* Wq = (const float*)d_in[2];
    const float* bq = (const float*)d_in[3];
    const float* Wk = (const float*)d_in[4];
    const float* bk = (const float*)d_in[5];
    const float* Wv = (const float*)d_in[6];
    const float* bv = (const float*)d_in[7];
    const float* Wo = (const float*)d_in[8];
    const float* bo = (const float*)d_in[9];
    float* out = (float*)d_out;

    float *Qp, *Kp, *Vp, *Cp;
    cudaGetSymbolAddress((void**)&Qp, g_Q);
    cudaGetSymbolAddress((void**)&Kp, g_K);
    cudaGetSymbolAddress((void**)&Vp, g_V);
    cudaGetSymbolAddress((void**)&Cp, g_C);
    __nv_bfloat16 *xhi, *xlo, *chi, *clo, *wthi, *wtlo;
    cudaGetSymbolAddress((void**)&xhi, g_xhi);
    cudaGetSymbolAddress((void**)&xlo, g_xlo);
    cudaGetSymbolAddress((void**)&chi, g_chi);
    cudaGetSymbolAddress((void**)&clo, g_clo);
    cudaGetSymbolAddress((void**)&wthi, g_wthi);
    cudaGetSymbolAddress((void**)&wtlo, g_wtlo);

    cudaFuncSetAttribute(gemm_mma_kernel,
                         cudaFuncAttributeMaxDynamicSharedMemorySize, GEMM_SMEM);

    const size_t WSZ = (size_t)D_MODEL * D_MODEL;
    const int n4 = MROWS * D_MODEL / 4;

    // prep
    split_kernel<<<(n4 + 255) / 256, 256>>>(x, xhi, xlo, n4);
    build_idx_kernel<<<BATCH, 256>>>(pm);
    build_gidx_kernel<<<1, 256>>>();
    bias_fill_kernel<<<n4 / 256, 256>>>(bo, out);

    dim3 tgrid(D_MODEL / 32, D_MODEL / 32), tblk(32, 8);
    transpose_split_kernel<<<tgrid, tblk>>>(Wq, wthi + 0 * WSZ, wtlo + 0 * WSZ);
    transpose_split_kernel<<<tgrid, tblk>>>(Wk, wthi + 1 * WSZ, wtlo + 1 * WSZ);
    transpose_split_kernel<<<tgrid, tblk>>>(Wv, wthi + 2 * WSZ, wtlo + 2 * WSZ);
    transpose_split_kernel<<<tgrid, tblk>>>(Wo, wthi + 3 * WSZ, wtlo + 3 * WSZ);

    // Q/K/V projections: gather valid rows, write compacted
    dim3 ggrid(D_MODEL / 128, MROWS / 128);
    gemm_mma_kernel<<<ggrid, 256, GEMM_SMEM>>>(xhi, xlo, wthi + 0 * WSZ, wtlo + 0 * WSZ, bq, Qp, 1, 0);
    gemm_mma_kernel<<<ggrid, 256, GEMM_SMEM>>>(xhi, xlo, wthi + 1 * WSZ, wtlo + 1 * WSZ, bk, Kp, 1, 0);
    gemm_mma_kernel<<<ggrid, 256, GEMM_SMEM>>>(xhi, xlo, wthi + 2 * WSZ, wtlo + 2 * WSZ, bv, Vp, 1, 0);

    // attention on compacted layout
    dim3 agrid(S_LEN / BQ, NHEAD, BATCH);
    attn_kernel<<<agrid, 256>>>(Qp, Kp, Vp, Cp);

    // output projection: compacted ctx in, scatter to out (invalid rows = bias)
    split_cnt_kernel<<<(n4 + 255) / 256, 256>>>(Cp, chi, clo);
    gemm_mma_kernel<<<ggrid, 256, GEMM_SMEM>>>(chi, clo, wthi + 3 * WSZ, wtlo + 3 * WSZ, bo, out, 0, 1);
}

// round 8
// speedup vs baseline: 3.6898x; 1.0608x over previous
#include <cuda_runtime.h>
#include <cuda_bf16.h>
#include <math.h>
#include <stdint.h>

#define BATCH   4
#define S_LEN   2048
#define D_MODEL 1024
#define NHEAD   16
#define HDIM    64
#define MROWS   (BATCH * S_LEN)

#define NEG_BIG (-1.0e9f)
typedef __nv_bfloat16 bf16;

// ---------------------------------------------------------------------------
// Scratch
// ---------------------------------------------------------------------------
__device__ __align__(1024) float g_Q[(size_t)MROWS * D_MODEL];   // compacted fp32
__device__ __align__(1024) float g_K[(size_t)MROWS * D_MODEL];
__device__ __align__(1024) float g_V[(size_t)MROWS * D_MODEL];
__device__ __align__(1024) float g_C[(size_t)MROWS * D_MODEL];   // compacted ctx

__device__ __align__(1024) bf16 g_xhi[(size_t)MROWS * D_MODEL];
__device__ __align__(1024) bf16 g_xlo[(size_t)MROWS * D_MODEL];
__device__ __align__(1024) bf16 g_chi[(size_t)MROWS * D_MODEL];
__device__ __align__(1024) bf16 g_clo[(size_t)MROWS * D_MODEL];
__device__ __align__(1024) bf16 g_wthi[4][(size_t)D_MODEL * D_MODEL];
__device__ __align__(1024) bf16 g_wtlo[4][(size_t)D_MODEL * D_MODEL];

__device__ int g_idx[BATCH][S_LEN];
__device__ int g_cnt[BATCH];
__device__ int g_off[BATCH + 1];
__device__ int g_gidx[MROWS];

// ---------------------------------------------------------------------------
// Helpers
// ---------------------------------------------------------------------------
__device__ __forceinline__ uint32_t smem_u32(const void* p) {
    uint32_t a;
    asm("{ .reg .u64 t; cvta.to.shared.u64 t, %1; cvt.u32.u64 %0, t; }"
        : "=r"(a) : "l"(p));
    return a;
}
__device__ __forceinline__ void cp_async16(uint32_t saddr, const void* gptr) {
    asm volatile("cp.async.cg.shared.global [%0], [%1], 16;"
                 :: "r"(saddr), "l"(__cvta_generic_to_global(gptr)));
}
__device__ __forceinline__ void cp_commit() {
    asm volatile("cp.async.commit_group;" ::: "memory");
}
template <int N>
__device__ __forceinline__ void cp_wait() {
    asm volatile("cp.async.wait_group %0;" :: "n"(N) : "memory");
}
__device__ __forceinline__ void mma16816(float* d, const uint32_t* a,
                                         uint32_t b0, uint32_t b1) {
    asm volatile(
        "mma.sync.aligned.m16n8k16.row.col.f32.bf16.bf16.f32 "
        "{%0,%1,%2,%3}, {%4,%5,%6,%7}, {%8,%9}, {%0,%1,%2,%3};"
        : "+f"(d[0]), "+f"(d[1]), "+f"(d[2]), "+f"(d[3])
        : "r"(a[0]), "r"(a[1]), "r"(a[2]), "r"(a[3]), "r"(b0), "r"(b1));
}

// ---------------------------------------------------------------------------
// Prep kernels
// ---------------------------------------------------------------------------
__global__ __launch_bounds__(256) void split_kernel(
    const float* __restrict__ in, bf16* __restrict__ hi,
    bf16* __restrict__ lo, int n4)
{
    int i = blockIdx.x * blockDim.x + threadIdx.x;
    if (i >= n4) return;
    float4 v = ((const float4*)in)[i];
    bf16 hx = __float2bfloat16(v.x), hy = __float2bfloat16(v.y);
    bf16 hz = __float2bfloat16(v.z), hw = __float2bfloat16(v.w);
    bf16 lx = __float2bfloat16(v.x - __bfloat162float(hx));
    bf16 ly = __float2bfloat16(v.y - __bfloat162float(hy));
    bf16 lz = __float2bfloat16(v.z - __bfloat162float(hz));
    bf16 lw = __float2bfloat16(v.w - __bfloat162float(hw));
    ((__nv_bfloat162*)hi)[2 * i + 0] = __nv_bfloat162(hx, hy);
    ((__nv_bfloat162*)hi)[2 * i + 1] = __nv_bfloat162(hz, hw);
    ((__nv_bfloat162*)lo)[2 * i + 0] = __nv_bfloat162(lx, ly);
    ((__nv_bfloat162*)lo)[2 * i + 1] = __nv_bfloat162(lz, lw);
}

__global__ __launch_bounds__(256) void split_cnt_kernel(
    const float* __restrict__ in, bf16* __restrict__ hi, bf16* __restrict__ lo)
{
    int n4 = g_off[BATCH] * (D_MODEL / 4);
    int i = blockIdx.x * blockDim.x + threadIdx.x;
    if (i >= n4) return;
    float4 v = ((const float4*)in)[i];
    bf16 hx = __float2bfloat16(v.x), hy = __float2bfloat16(v.y);
    bf16 hz = __float2bfloat16(v.z), hw = __float2bfloat16(v.w);
    bf16 lx = __float2bfloat16(v.x - __bfloat162float(hx));
    bf16 ly = __float2bfloat16(v.y - __bfloat162float(hy));
    bf16 lz = __float2bfloat16(v.z - __bfloat162float(hz));
    bf16 lw = __float2bfloat16(v.w - __bfloat162float(hw));
    ((__nv_bfloat162*)hi)[2 * i + 0] = __nv_bfloat162(hx, hy);
    ((__nv_bfloat162*)hi)[2 * i + 1] = __nv_bfloat162(hz, hw);
    ((__nv_bfloat162*)lo)[2 * i + 0] = __nv_bfloat162(lx, ly);
    ((__nv_bfloat162*)lo)[2 * i + 1] = __nv_bfloat162(lz, lw);
}

__global__ __launch_bounds__(256) void bias_fill_kernel(
    const float* __restrict__ bias, float* __restrict__ out)
{
    int i = blockIdx.x * blockDim.x + threadIdx.x;
    int c = (i & (D_MODEL / 4 - 1)) * 4;
    ((float4*)out)[i] = *(const float4*)(bias + c);
}

__global__ __launch_bounds__(256) void transpose_split_kernel(
    const float* __restrict__ W, bf16* __restrict__ Thi, bf16* __restrict__ Tlo)
{
    __shared__ float t[32][33];
    int tx = threadIdx.x, ty = threadIdx.y;
    int n0 = blockIdx.x * 32, k0 = blockIdx.y * 32;
    #pragma unroll
    for (int j = 0; j < 4; j++)
        t[ty + 8 * j][tx] = W[(size_t)(k0 + ty + 8 * j) * D_MODEL + n0 + tx];
    __syncthreads();
    #pragma unroll
    for (int j = 0; j < 4; j++) {
        float v = t[tx][ty + 8 * j];
        bf16 h = __float2bfloat16(v);
        bf16 l = __float2bfloat16(v - __bfloat162float(h));
        size_t o = (size_t)(n0 + ty + 8 * j) * D_MODEL + k0 + tx;
        Thi[o] = h;
        Tlo[o] = l;
    }
}

__global__ __launch_bounds__(256) void build_idx_kernel(const int* __restrict__ mask) {
    __shared__ int part[256];
    int b = blockIdx.x, t = threadIdx.x;
    const int* m = mask + (size_t)b * S_LEN;
    int loc[8], s = 0;
    #pragma unroll
    for (int j = 0; j < 8; j++) { loc[j] = (m[t * 8 + j] != 0); s += loc[j]; }
    part[t] = s;
    __syncthreads();
    for (int off = 1; off < 256; off <<= 1) {
        int v = (t >= off) ? part[t - off] : 0;
        __syncthreads();
        part[t] += v;
        __syncthreads();
    }
    int p = part[t] - s;
    #pragma unroll
    for (int j = 0; j < 8; j++)
        if (loc[j]) g_idx[b][p++] = t * 8 + j;
    if (t == 255) g_cnt[b] = part[255];
}

__global__ __launch_bounds__(256) void build_gidx_kernel() {
    __shared__ int off[BATCH + 1];
    if (threadIdx.x == 0) {
        off[0] = 0;
        for (int b = 0; b < BATCH; b++) off[b + 1] = off[b] + g_cnt[b];
        for (int b = 0; b <= BATCH; b++) g_off[b] = off[b];
    }
    __syncthreads();
    for (int b = 0; b < BATCH; b++) {
        int c = g_cnt[b], o = off[b];
        for (int i = threadIdx.x; i < c; i += 256)
            g_gidx[o + i] = b * S_LEN + g_idx[b][i];
    }
}

// ---------------------------------------------------------------------------
// GEMM: 2-stage cp.async pipeline, occupancy 2 (launch_bounds 256,2).
// MODE 0: fused QKV — gather A rows via g_gidx; z picks W/bias/output;
//         epilogue writes fp32 (compacted rows).
// MODE 1: O projection — A compacted chi/clo; epilogue scatters fp32 via g_gidx.
// ---------------------------------------------------------------------------
#define ROWB    80
#define TILEB   (128 * ROWB)
#define STAGEB  (4 * TILEB)
#define GEMM_SMEM (2 * STAGEB + 512)

template<int MODE>
__global__ __launch_bounds__(256, 2) void gemm_kernel(
    const bf16* __restrict__ Ahi, const bf16* __restrict__ Alo,
    const bf16* __restrict__ Whi_base, const bf16* __restrict__ Wlo_base,
    const float* __restrict__ bias0, const float* __restrict__ bias1,
    const float* __restrict__ bias2,
    float* __restrict__ O0, float* __restrict__ O1, float* __restrict__ O2)
{
    extern __shared__ __align__(128) char sm[];
    int* sidx = (int*)(sm + 2 * STAGEB);

    const int cnt = g_off[BATCH];
    const int m0 = blockIdx.y * 128;
    if (m0 >= cnt) return;
    const int n0 = blockIdx.x * 128;
    const int z  = (MODE == 0) ? blockIdx.z : 0;

    const bf16* Bhi = Whi_base + (size_t)z * D_MODEL * D_MODEL;
    const bf16* Blo = Wlo_base + (size_t)z * D_MODEL * D_MODEL;
    const float* bias = (z == 0 ? bias0 : (z == 1 ? bias1 : bias2));
    float* Cout = (z == 0 ? O0 : (z == 1 ? O1 : O2));

    const int tid  = threadIdx.x;
    const int lane = tid & 31;
    const int w    = tid >> 5;
    const int wm   = w & 1;
    const int wn   = w >> 1;
    const int g    = lane >> 2;
    const int t4   = lane & 3;

    if (tid < 128)
        sidx[tid] = (m0 + tid < cnt) ? g_gidx[m0 + tid] : g_gidx[0];
    __syncthreads();

    const bf16* gsrc[4] = {Ahi, Alo, Bhi, Blo};

    float acc[4][4][4];
    #pragma unroll
    for (int mt = 0; mt < 4; mt++)
        #pragma unroll
        for (int nt = 0; nt < 4; nt++)
            #pragma unroll
            for (int r = 0; r < 4; r++)
                acc[mt][nt][r] = 0.0f;

    auto load_stage = [&](int kc, int st) {
        char* base = sm + st * STAGEB;
        #pragma unroll
        for (int t = 0; t < 8; t++) {
            const int tile = t >> 1;
            const int wi   = tid + (t & 1) * 256;
            const int row  = wi >> 2;
            const int ch   = wi & 3;
            int grow;
            if (tile < 2) {
                if (MODE == 0) grow = sidx[row];
                else { int ar = m0 + row; grow = (ar < cnt) ? ar : m0; }
            } else grow = n0 + row;
            const bf16* src = gsrc[tile] + (size_t)grow * D_MODEL + kc * 32 + ch * 8;
            uint32_t dst = smem_u32(base + tile * TILEB + row * ROWB + ch * 16);
            cp_async16(dst, src);
        }
        cp_commit();
    };

    auto compute_stage = [&](int st) {
        const char* base = sm + st * STAGEB;
        const char* pAh = base;
        const char* pAl = base + TILEB;
        const char* pBh = base + 2 * TILEB;
        const char* pBl = base + 3 * TILEB;
        #pragma unroll
        for (int kk = 0; kk < 2; kk++) {
            const int c = kk * 16 + t4 * 2;
            uint32_t ah[4][4], al[4][4], bh[4][2], bl[4][2];
            #pragma unroll
            for (int mt = 0; mt < 4; mt++) {
                int r = wm * 64 + mt * 16 + g;
                ah[mt][0] = *(const uint32_t*)(pAh + r * ROWB + c * 2);
                ah[mt][1] = *(const uint32_t*)(pAh + (r + 8) * ROWB + c * 2);
                ah[mt][2] = *(const uint32_t*)(pAh + r * ROWB + (c + 8) * 2);
                ah[mt][3] = *(const uint32_t*)(pAh + (r + 8) * ROWB + (c + 8) * 2);
                al[mt][0] = *(const uint32_t*)(pAl + r * ROWB + c * 2);
                al[mt][1] = *(const uint32_t*)(pAl + (r + 8) * ROWB + c * 2);
                al[mt][2] = *(const uint32_t*)(pAl + r * ROWB + (c + 8) * 2);
                al[mt][3] = *(const uint32_t*)(pAl + (r + 8) * ROWB + (c + 8) * 2);
            }
            #pragma unroll
            for (int nt = 0; nt < 4; nt++) {
                int n = wn * 32 + nt * 8 + g;
                bh[nt][0] = *(const uint32_t*)(pBh + n * ROWB + c * 2);
                bh[nt][1] = *(const uint32_t*)(pBh + n * ROWB + (c + 8) * 2);
                bl[nt][0] = *(const uint32_t*)(pBl + n * ROWB + c * 2);
                bl[nt][1] = *(const uint32_t*)(pBl + n * ROWB + (c + 8) * 2);
            }
            #pragma unroll
            for (int mt = 0; mt < 4; mt++)
                #pragma unroll
                for (int nt = 0; nt < 4; nt++) {
                    mma16816(acc[mt][nt], ah[mt], bh[nt][0], bh[nt][1]);
                    mma16816(acc[mt][nt], ah[mt], bl[nt][0], bl[nt][1]);
                    mma16816(acc[mt][nt], al[mt], bh[nt][0], bh[nt][1]);
                }
        }
    };

    const int NIT = D_MODEL / 32;
    load_stage(0, 0);
    load_stage(1, 1);
    for (int it = 0; it < NIT; it++) {
        if (it + 1 < NIT) cp_wait<1>(); else cp_wait<0>();
        __syncthreads();
        compute_stage(it & 1);
        __syncthreads();
        if (it + 2 < NIT) load_stage(it + 2, it & 1);
    }

    #pragma unroll
    for (int mt = 0; mt < 4; mt++) {
        int rl = wm * 64 + mt * 16 + g;
        #pragma unroll
        for (int nt = 0; nt < 4; nt++) {
            int col = n0 + wn * 32 + nt * 8 + t4 * 2;
            float b0 = bias[col], b1 = bias[col + 1];
            float v00 = acc[mt][nt][0] + b0, v01 = acc[mt][nt][1] + b1;
            float v10 = acc[mt][nt][2] + b0, v11 = acc[mt][nt][3] + b1;
            if (m0 + rl < cnt) {
                int r = (MODE == 1) ? sidx[rl] : (m0 + rl);
                *(float2*)(Cout + (size_t)r * D_MODEL + col) = make_float2(v00, v01);
            }
            if (m0 + rl + 8 < cnt) {
                int r = (MODE == 1) ? sidx[rl + 8] : (m0 + rl + 8);
                *(float2*)(Cout + (size_t)r * D_MODEL + col) = make_float2(v10, v11);
            }
        }
    }
}

// ---------------------------------------------------------------------------
// Flash attention over compacted fp32 Q/K/V (proven R6 kernel, verbatim).
// ---------------------------------------------------------------------------
#define BQ  64
#define BKV 32

__global__ __launch_bounds__(256) void attn_kernel(
    const float* __restrict__ Q, const float* __restrict__ K,
    const float* __restrict__ V, float* __restrict__ ctx)
{
    __shared__ float Qs[BQ][HDIM];
    __shared__ float Kts[HDIM][BKV + 1];
    __shared__ float Vs[BKV][HDIM];
    __shared__ float Ps[BQ][BKV + 1];
    __shared__ float alphaS[BQ];

    const int tid = threadIdx.x;
    const int b   = blockIdx.z;
    const int h   = blockIdx.y;
    const int cnt = g_cnt[b];
    const int off = g_off[b];
    const int q0  = blockIdx.x * BQ;
    if (q0 >= cnt) return;

    const size_t hcol = (size_t)h * HDIM;

    const int tx = tid & 15;
    const int ty = tid >> 4;

    {
        int r  = tid >> 4;
        int c4 = (tid & 15) * 4;
        #pragma unroll
        for (int i = 0; i < 4; i++) {
            int row = r + i * 16;
            int qi = (q0 + row < cnt) ? (off + q0 + row) : off;
            *(float4*)(&Qs[row][c4]) =
                *(const float4*)(Q + (size_t)qi * D_MODEL + hcol + c4);
        }
    }

    float o[4][4];
    #pragma unroll
    for (int i = 0; i < 4; i++)
        #pragma unroll
        for (int j = 0; j < 4; j++)
            o[i][j] = 0.0f;

    float m_run = -1e30f, l_run = 0.0f;

    for (int kv0 = 0; kv0 < cnt; kv0 += BKV) {
        __syncthreads();

        #pragma unroll
        for (int it = 0; it < 2; it++) {
            int idx = tid + it * 256;
            int row = idx >> 4;
            int c4  = (idx & 15) * 4;
            int ki  = (kv0 + row < cnt) ? (off + kv0 + row) : off;
            float4 kk = *(const float4*)(K + (size_t)ki * D_MODEL + hcol + c4);
            Kts[c4 + 0][row] = kk.x;
            Kts[c4 + 1][row] = kk.y;
            Kts[c4 + 2][row] = kk.z;
            Kts[c4 + 3][row] = kk.w;
            *(float4*)(&Vs[row][c4]) =
                *(const float4*)(V + (size_t)ki * D_MODEL + hcol + c4);
        }
        __syncthreads();

        float s[4][2];
        #pragma unroll
        for (int i = 0; i < 4; i++) { s[i][0] = 0.0f; s[i][1] = 0.0f; }
        #pragma unroll 8
        for (int d = 0; d < HDIM; d++) {
            float a0 = Qs[ty * 4 + 0][d];
            float a1 = Qs[ty * 4 + 1][d];
            float a2 = Qs[ty * 4 + 2][d];
            float a3 = Qs[ty * 4 + 3][d];
            float b0 = Kts[d][tx * 2 + 0];
            float b1 = Kts[d][tx * 2 + 1];
            s[0][0] += a0 * b0;  s[0][1] += a0 * b1;
            s[1][0] += a1 * b0;  s[1][1] += a1 * b1;
            s[2][0] += a2 * b0;  s[2][1] += a2 * b1;
            s[3][0] += a3 * b0;  s[3][1] += a3 * b1;
        }
        #pragma unroll
        for (int i = 0; i < 4; i++) {
            #pragma unroll
            for (int jj = 0; jj < 2; jj++) {
                int kc = tx * 2 + jj;
                Ps[ty * 4 + i][kc] = (kv0 + kc < cnt) ? s[i][jj] : NEG_BIG;
            }
        }
        __syncthreads();

        if (tid < BQ) {
            float mnew = m_run;
            #pragma unroll
            for (int c = 0; c < BKV; c++) mnew = fmaxf(mnew, Ps[tid][c]);
            float alpha = __expf(m_run - mnew);
            float lsum = l_run * alpha;
            #pragma unroll
            for (int c = 0; c < BKV; c++) {
                float p = __expf(Ps[tid][c] - mnew);
                Ps[tid][c] = p;
                lsum += p;
            }
            m_run = mnew;
            l_run = lsum;
            alphaS[tid] = alpha;
        }
        __syncthreads();

        #pragma unroll
        for (int i = 0; i < 4; i++) {
            float al = alphaS[ty * 4 + i];
            #pragma unroll
            for (int j = 0; j < 4; j++) o[i][j] *= al;
        }
        #pragma unroll 4
        for (int kc = 0; kc < BKV; kc++) {
            float p0 = Ps[ty * 4 + 0][kc];
            float p1 = Ps[ty * 4 + 1][kc];
            float p2 = Ps[ty * 4 + 2][kc];
            float p3 = Ps[ty * 4 + 3][kc];
            float4 vv = *(float4*)(&Vs[kc][tx * 4]);
            o[0][0] += p0 * vv.x; o[0][1] += p0 * vv.y; o[0][2] += p0 * vv.z; o[0][3] += p0 * vv.w;
            o[1][0] += p1 * vv.x; o[1][1] += p1 * vv.y; o[1][2] += p1 * vv.z; o[1][3] += p1 * vv.w;
            o[2][0] += p2 * vv.x; o[2][1] += p2 * vv.y; o[2][2] += p2 * vv.z; o[2][3] += p2 * vv.w;
            o[3][0] += p3 * vv.x; o[3][1] += p3 * vv.y; o[3][2] += p3 * vv.z; o[3][3] += p3 * vv.w;
        }
    }

    __syncthreads();
    if (tid < BQ) alphaS[tid] = 1.0f / l_run;
    __syncthreads();
    #pragma unroll
    for (int i = 0; i < 4; i++) {
        int r = ty * 4 + i;
        if (q0 + r < cnt) {
            float sc = alphaS[r];
            float4 ov;
            ov.x = o[i][0] * sc;
            ov.y = o[i][1] * sc;
            ov.z = o[i][2] * sc;
            ov.w = o[i][3] * sc;
            *(float4*)(ctx + (size_t)(off + q0 + r) * D_MODEL + hcol + tx * 4) = ov;
        }
    }
}

// ---------------------------------------------------------------------------
extern "C" void kernel_launch(void* const* d_in, const int* in_sizes, int n_in,
                              void* d_out, int out_size)
{
    (void)in_sizes; (void)n_in; (void)out_size;
    const float* x  = (const float*)d_in[0];
    const int*   pm = (const int*)  d_in[1];
    const float* Wq = (const float*)d_in[2];
    const float* bq = (const float*)d_in[3];
    const float* Wk = (const float*)d_in[4];
    const float* bk = (const float*)d_in[5];
    const float* Wv = (const float*)d_in[6];
    const float* bv = (const float*)d_in[7];
    const float* Wo = (const float*)d_in[8];
    const float* bo = (const float*)d_in[9];
    float* out = (float*)d_out;

    float *Qp, *Kp, *Vp, *Cp;
    cudaGetSymbolAddress((void**)&Qp, g_Q);
    cudaGetSymbolAddress((void**)&Kp, g_K);
    cudaGetSymbolAddress((void**)&Vp, g_V);
    cudaGetSymbolAddress((void**)&Cp, g_C);
    bf16 *xhi, *xlo, *chi, *clo, *wthi, *wtlo;
    cudaGetSymbolAddress((void**)&xhi, g_xhi);
    cudaGetSymbolAddress((void**)&xlo, g_xlo);
    cudaGetSymbolAddress((void**)&chi, g_chi);
    cudaGetSymbolAddress((void**)&clo, g_clo);
    cudaGetSymbolAddress((void**)&wthi, g_wthi);
    cudaGetSymbolAddress((void**)&wtlo, g_wtlo);

    cudaFuncSetAttribute(gemm_kernel<0>,
                         cudaFuncAttributeMaxDynamicSharedMemorySize, GEMM_SMEM);
    cudaFuncSetAttribute(gemm_kernel<1>,
                         cudaFuncAttributeMaxDynamicSharedMemorySize, GEMM_SMEM);

    const size_t WSZ = (size_t)D_MODEL * D_MODEL;
    const int n4 = MROWS * D_MODEL / 4;

    split_kernel<<<(n4 + 255) / 256, 256>>>(x, xhi, xlo, n4);
    build_idx_kernel<<<BATCH, 256>>>(pm);
    build_gidx_kernel<<<1, 256>>>();
    bias_fill_kernel<<<n4 / 256, 256>>>(bo, out);

    dim3 tgrid(D_MODEL / 32, D_MODEL / 32), tblk(32, 8);
    transpose_split_kernel<<<tgrid, tblk>>>(Wq, wthi + 0 * WSZ, wtlo + 0 * WSZ);
    transpose_split_kernel<<<tgrid, tblk>>>(Wk, wthi + 1 * WSZ, wtlo + 1 * WSZ);
    transpose_split_kernel<<<tgrid, tblk>>>(Wv, wthi + 2 * WSZ, wtlo + 2 * WSZ);
    transpose_split_kernel<<<tgrid, tblk>>>(Wo, wthi + 3 * WSZ, wtlo + 3 * WSZ);

    // fused Q/K/V projections (z = 0,1,2), fp32 compacted outputs
    dim3 qkvgrid(D_MODEL / 128, MROWS / 128, 3);
    gemm_kernel<0><<<qkvgrid, 256, GEMM_SMEM>>>(
        xhi, xlo, wthi, wtlo, bq, bk, bv, Qp, Kp, Vp);

    // attention (fp32, compacted)
    dim3 agrid(S_LEN / BQ, NHEAD, BATCH);
    attn_kernel<<<agrid, 256>>>(Qp, Kp, Vp, Cp);

    // output projection: split ctx, scatter fp32 out
    split_cnt_kernel<<<(n4 + 255) / 256, 256>>>(Cp, chi, clo);
    dim3 ogrid(D_MODEL / 128, MROWS / 128, 1);
    gemm_kernel<1><<<ogrid, 256, GEMM_SMEM>>>(
        chi, clo, wthi + 3 * WSZ, wtlo + 3 * WSZ, bo, nullptr, nullptr,
        out, nullptr, nullptr);
}

// round 10
// speedup vs baseline: 3.9553x; 1.0719x over previous
#include <cuda_runtime.h>
#include <cuda_bf16.h>
#include <cuda_fp16.h>
#include <math.h>
#include <stdint.h>

#define BATCH   4
#define S_LEN   2048
#define D_MODEL 1024
#define NHEAD   16
#define HDIM    64
#define MROWS   (BATCH * S_LEN)

#define NEG_BIG (-1.0e9f)
typedef __nv_bfloat16 bf16;

// ---------------------------------------------------------------------------
// Scratch
// ---------------------------------------------------------------------------
__device__ __align__(1024) float g_Q[(size_t)MROWS * D_MODEL];
__device__ __align__(1024) float g_K[(size_t)MROWS * D_MODEL];
__device__ __align__(1024) float g_V[(size_t)MROWS * D_MODEL];
__device__ __align__(1024) float g_C[(size_t)MROWS * D_MODEL];

__device__ __align__(1024) bf16   g_xbh[(size_t)MROWS * D_MODEL];   // x bf16 hi
__device__ __align__(1024) bf16   g_xbl[(size_t)MROWS * D_MODEL];   // x bf16 lo
__device__ __align__(1024) __half g_xh16[(size_t)MROWS * D_MODEL];  // x fp16
__device__ __align__(1024) __half g_chh[(size_t)MROWS * D_MODEL];   // ctx fp16 hi
__device__ __align__(1024) __half g_chl[(size_t)MROWS * D_MODEL];   // ctx fp16 lo
__device__ __align__(1024) bf16   g_wqk_h[2][(size_t)D_MODEL * D_MODEL];
__device__ __align__(1024) bf16   g_wqk_l[2][(size_t)D_MODEL * D_MODEL];
__device__ __align__(1024) __half g_wv16[(size_t)D_MODEL * D_MODEL];
__device__ __align__(1024) __half g_wo16[(size_t)D_MODEL * D_MODEL];

__device__ int g_idx[BATCH][S_LEN];
__device__ int g_cnt[BATCH];
__device__ int g_off[BATCH + 1];
__device__ int g_gidx[MROWS];

// ---------------------------------------------------------------------------
// Helpers
// ---------------------------------------------------------------------------
__device__ __forceinline__ uint32_t smem_u32(const void* p) {
    uint32_t a;
    asm("{ .reg .u64 t; cvta.to.shared.u64 t, %1; cvt.u32.u64 %0, t; }"
        : "=r"(a) : "l"(p));
    return a;
}
__device__ __forceinline__ void cp_async16(uint32_t saddr, const void* gptr) {
    asm volatile("cp.async.cg.shared.global [%0], [%1], 16;"
                 :: "r"(saddr), "l"(__cvta_generic_to_global(gptr)));
}
__device__ __forceinline__ void cp_commit() {
    asm volatile("cp.async.commit_group;" ::: "memory");
}
template <int N>
__device__ __forceinline__ void cp_wait() {
    asm volatile("cp.async.wait_group %0;" :: "n"(N) : "memory");
}
__device__ __forceinline__ void mma_bf16(float* d, const uint32_t* a,
                                         uint32_t b0, uint32_t b1) {
    asm volatile(
        "mma.sync.aligned.m16n8k16.row.col.f32.bf16.bf16.f32 "
        "{%0,%1,%2,%3}, {%4,%5,%6,%7}, {%8,%9}, {%0,%1,%2,%3};"
        : "+f"(d[0]), "+f"(d[1]), "+f"(d[2]), "+f"(d[3])
        : "r"(a[0]), "r"(a[1]), "r"(a[2]), "r"(a[3]), "r"(b0), "r"(b1));
}
__device__ __forceinline__ void mma_fp16(float* d, const uint32_t* a,
                                         uint32_t b0, uint32_t b1) {
    asm volatile(
        "mma.sync.aligned.m16n8k16.row.col.f32.f16.f16.f32 "
        "{%0,%1,%2,%3}, {%4,%5,%6,%7}, {%8,%9}, {%0,%1,%2,%3};"
        : "+f"(d[0]), "+f"(d[1]), "+f"(d[2]), "+f"(d[3])
        : "r"(a[0]), "r"(a[1]), "r"(a[2]), "r"(a[3]), "r"(b0), "r"(b1));
}

// ---------------------------------------------------------------------------
// Prep kernels
// ---------------------------------------------------------------------------
__global__ __launch_bounds__(256) void split_bf16_kernel(
    const float* __restrict__ in, bf16* __restrict__ hi,
    bf16* __restrict__ lo, int n4)
{
    int i = blockIdx.x * blockDim.x + threadIdx.x;
    if (i >= n4) return;
    float4 v = ((const float4*)in)[i];
    bf16 hx = __float2bfloat16(v.x), hy = __float2bfloat16(v.y);
    bf16 hz = __float2bfloat16(v.z), hw = __float2bfloat16(v.w);
    bf16 lx = __float2bfloat16(v.x - __bfloat162float(hx));
    bf16 ly = __float2bfloat16(v.y - __bfloat162float(hy));
    bf16 lz = __float2bfloat16(v.z - __bfloat162float(hz));
    bf16 lw = __float2bfloat16(v.w - __bfloat162float(hw));
    ((__nv_bfloat162*)hi)[2 * i + 0] = __nv_bfloat162(hx, hy);
    ((__nv_bfloat162*)hi)[2 * i + 1] = __nv_bfloat162(hz, hw);
    ((__nv_bfloat162*)lo)[2 * i + 0] = __nv_bfloat162(lx, ly);
    ((__nv_bfloat162*)lo)[2 * i + 1] = __nv_bfloat162(lz, lw);
}

__global__ __launch_bounds__(256) void tohalf_kernel(
    const float* __restrict__ in, __half* __restrict__ out, int n4)
{
    int i = blockIdx.x * blockDim.x + threadIdx.x;
    if (i >= n4) return;
    float4 v = ((const float4*)in)[i];
    ((__half2*)out)[2 * i + 0] = __floats2half2_rn(v.x, v.y);
    ((__half2*)out)[2 * i + 1] = __floats2half2_rn(v.z, v.w);
}

// ctx -> fp16 hi/lo (bounded by compacted count)
__global__ __launch_bounds__(256) void split_half_cnt_kernel(
    const float* __restrict__ in, __half* __restrict__ hi, __half* __restrict__ lo)
{
    int n4 = g_off[BATCH] * (D_MODEL / 4);
    int i = blockIdx.x * blockDim.x + threadIdx.x;
    if (i >= n4) return;
    float4 v = ((const float4*)in)[i];
    __half hx = __float2half_rn(v.x), hy = __float2half_rn(v.y);
    __half hz = __float2half_rn(v.z), hw = __float2half_rn(v.w);
    __half lx = __float2half_rn(v.x - __half2float(hx));
    __half ly = __float2half_rn(v.y - __half2float(hy));
    __half lz = __float2half_rn(v.z - __half2float(hz));
    __half lw = __float2half_rn(v.w - __half2float(hw));
    ((__half2*)hi)[2 * i + 0] = __half2(hx, hy);
    ((__half2*)hi)[2 * i + 1] = __half2(hz, hw);
    ((__half2*)lo)[2 * i + 0] = __half2(lx, ly);
    ((__half2*)lo)[2 * i + 1] = __half2(lz, lw);
}

__global__ __launch_bounds__(256) void bias_fill_kernel(
    const float* __restrict__ bias, float* __restrict__ out)
{
    int i = blockIdx.x * blockDim.x + threadIdx.x;
    int c = (i & (D_MODEL / 4 - 1)) * 4;
    ((float4*)out)[i] = *(const float4*)(bias + c);
}

__global__ __launch_bounds__(256) void transpose_split_bf16_kernel(
    const float* __restrict__ W, bf16* __restrict__ Thi, bf16* __restrict__ Tlo)
{
    __shared__ float t[32][33];
    int tx = threadIdx.x, ty = threadIdx.y;
    int n0 = blockIdx.x * 32, k0 = blockIdx.y * 32;
    #pragma unroll
    for (int j = 0; j < 4; j++)
        t[ty + 8 * j][tx] = W[(size_t)(k0 + ty + 8 * j) * D_MODEL + n0 + tx];
    __syncthreads();
    #pragma unroll
    for (int j = 0; j < 4; j++) {
        float v = t[tx][ty + 8 * j];
        bf16 h = __float2bfloat16(v);
        bf16 l = __float2bfloat16(v - __bfloat162float(h));
        size_t o = (size_t)(n0 + ty + 8 * j) * D_MODEL + k0 + tx;
        Thi[o] = h;
        Tlo[o] = l;
    }
}

__global__ __launch_bounds__(256) void transpose_half_kernel(
    const float* __restrict__ W, __half* __restrict__ T)
{
    __shared__ float t[32][33];
    int tx = threadIdx.x, ty = threadIdx.y;
    int n0 = blockIdx.x * 32, k0 = blockIdx.y * 32;
    #pragma unroll
    for (int j = 0; j < 4; j++)
        t[ty + 8 * j][tx] = W[(size_t)(k0 + ty + 8 * j) * D_MODEL + n0 + tx];
    __syncthreads();
    #pragma unroll
    for (int j = 0; j < 4; j++)
        T[(size_t)(n0 + ty + 8 * j) * D_MODEL + k0 + tx] =
            __float2half_rn(t[tx][ty + 8 * j]);
}

__global__ __launch_bounds__(256) void build_idx_kernel(const int* __restrict__ mask) {
    __shared__ int part[256];
    int b = blockIdx.x, t = threadIdx.x;
    const int* m = mask + (size_t)b * S_LEN;
    int loc[8], s = 0;
    #pragma unroll
    for (int j = 0; j < 8; j++) { loc[j] = (m[t * 8 + j] != 0); s += loc[j]; }
    part[t] = s;
    __syncthreads();
    for (int off = 1; off < 256; off <<= 1) {
        int v = (t >= off) ? part[t - off] : 0;
        __syncthreads();
        part[t] += v;
        __syncthreads();
    }
    int p = part[t] - s;
    #pragma unroll
    for (int j = 0; j < 8; j++)
        if (loc[j]) g_idx[b][p++] = t * 8 + j;
    if (t == 255) g_cnt[b] = part[255];
}

__global__ __launch_bounds__(256) void build_gidx_kernel() {
    __shared__ int off[BATCH + 1];
    if (threadIdx.x == 0) {
        off[0] = 0;
        for (int b = 0; b < BATCH; b++) off[b + 1] = off[b] + g_cnt[b];
        for (int b = 0; b <= BATCH; b++) g_off[b] = off[b];
    }
    __syncthreads();
    for (int b = 0; b < BATCH; b++) {
        int c = g_cnt[b], o = off[b];
        for (int i = threadIdx.x; i < c; i += 256)
            g_gidx[o + i] = b * S_LEN + g_idx[b][i];
    }
}

// ---------------------------------------------------------------------------
#define ROWB    80
#define TILEB   (128 * ROWB)          // 10240

// ========== Q,K GEMM: bf16 3-pass split, 2-stage (R8 verbatim structure) ====
#define QK_STAGEB  (4 * TILEB)
#define QK_SMEM    (2 * QK_STAGEB + 512)

__global__ __launch_bounds__(256, 2) void gemm_qk_kernel(
    const bf16* __restrict__ Ahi, const bf16* __restrict__ Alo,
    const bf16* __restrict__ Whi_base, const bf16* __restrict__ Wlo_base,
    const float* __restrict__ bias0, const float* __restrict__ bias1,
    float* __restrict__ O0, float* __restrict__ O1)
{
    extern __shared__ __align__(128) char sm[];
    int* sidx = (int*)(sm + 2 * QK_STAGEB);

    const int cnt = g_off[BATCH];
    const int m0 = blockIdx.y * 128;
    if (m0 >= cnt) return;
    const int n0 = blockIdx.x * 128;
    const int z  = blockIdx.z;

    const bf16* Bhi = Whi_base + (size_t)z * D_MODEL * D_MODEL;
    const bf16* Blo = Wlo_base + (size_t)z * D_MODEL * D_MODEL;
    const float* bias = (z == 0 ? bias0 : bias1);
    float* Cout = (z == 0 ? O0 : O1);

    const int tid  = threadIdx.x;
    const int lane = tid & 31;
    const int w    = tid >> 5;
    const int wm   = w & 1;
    const int wn   = w >> 1;
    const int g    = lane >> 2;
    const int t4   = lane & 3;

    if (tid < 128)
        sidx[tid] = (m0 + tid < cnt) ? g_gidx[m0 + tid] : g_gidx[0];
    __syncthreads();

    const bf16* gsrc[4] = {Ahi, Alo, Bhi, Blo};

    float acc[4][4][4];
    #pragma unroll
    for (int mt = 0; mt < 4; mt++)
        #pragma unroll
        for (int nt = 0; nt < 4; nt++)
            #pragma unroll
            for (int r = 0; r < 4; r++)
                acc[mt][nt][r] = 0.0f;

    auto load_stage = [&](int kc, int st) {
        char* base = sm + st * QK_STAGEB;
        #pragma unroll
        for (int t = 0; t < 8; t++) {
            const int tile = t >> 1;
            const int wi   = tid + (t & 1) * 256;
            const int row  = wi >> 2;
            const int ch   = wi & 3;
            int grow = (tile < 2) ? sidx[row] : (n0 + row);
            const bf16* src = gsrc[tile] + (size_t)grow * D_MODEL + kc * 32 + ch * 8;
            uint32_t dst = smem_u32(base + tile * TILEB + row * ROWB + ch * 16);
            cp_async16(dst, src);
        }
        cp_commit();
    };

    auto compute_stage = [&](int st) {
        const char* base = sm + st * QK_STAGEB;
        const char* pAh = base;
        const char* pAl = base + TILEB;
        const char* pBh = base + 2 * TILEB;
        const char* pBl = base + 3 * TILEB;
        #pragma unroll
        for (int kk = 0; kk < 2; kk++) {
            const int c = kk * 16 + t4 * 2;
            uint32_t ah[4][4], al[4][4], bh[4][2], bl[4][2];
            #pragma unroll
            for (int mt = 0; mt < 4; mt++) {
                int r = wm * 64 + mt * 16 + g;
                ah[mt][0] = *(const uint32_t*)(pAh + r * ROWB + c * 2);
                ah[mt][1] = *(const uint32_t*)(pAh + (r + 8) * ROWB + c * 2);
                ah[mt][2] = *(const uint32_t*)(pAh + r * ROWB + (c + 8) * 2);
                ah[mt][3] = *(const uint32_t*)(pAh + (r + 8) * ROWB + (c + 8) * 2);
                al[mt][0] = *(const uint32_t*)(pAl + r * ROWB + c * 2);
                al[mt][1] = *(const uint32_t*)(pAl + (r + 8) * ROWB + c * 2);
                al[mt][2] = *(const uint32_t*)(pAl + r * ROWB + (c + 8) * 2);
                al[mt][3] = *(const uint32_t*)(pAl + (r + 8) * ROWB + (c + 8) * 2);
            }
            #pragma unroll
            for (int nt = 0; nt < 4; nt++) {
                int n = wn * 32 + nt * 8 + g;
                bh[nt][0] = *(const uint32_t*)(pBh + n * ROWB + c * 2);
                bh[nt][1] = *(const uint32_t*)(pBh + n * ROWB + (c + 8) * 2);
                bl[nt][0] = *(const uint32_t*)(pBl + n * ROWB + c * 2);
                bl[nt][1] = *(const uint32_t*)(pBl + n * ROWB + (c + 8) * 2);
            }
            #pragma unroll
            for (int mt = 0; mt < 4; mt++)
                #pragma unroll
                for (int nt = 0; nt < 4; nt++) {
                    mma_bf16(acc[mt][nt], ah[mt], bh[nt][0], bh[nt][1]);
                    mma_bf16(acc[mt][nt], ah[mt], bl[nt][0], bl[nt][1]);
                    mma_bf16(acc[mt][nt], al[mt], bh[nt][0], bh[nt][1]);
                }
        }
    };

    const int NIT = D_MODEL / 32;
    load_stage(0, 0);
    load_stage(1, 1);
    for (int it = 0; it < NIT; it++) {
        if (it + 1 < NIT) cp_wait<1>(); else cp_wait<0>();
        __syncthreads();
        compute_stage(it & 1);
        __syncthreads();
        if (it + 2 < NIT) load_stage(it + 2, it & 1);
    }

    #pragma unroll
    for (int mt = 0; mt < 4; mt++) {
        int rl = wm * 64 + mt * 16 + g;
        #pragma unroll
        for (int nt = 0; nt < 4; nt++) {
            int col = n0 + wn * 32 + nt * 8 + t4 * 2;
            float b0 = bias[col], b1 = bias[col + 1];
            if (m0 + rl < cnt)
                *(float2*)(Cout + (size_t)(m0 + rl) * D_MODEL + col) =
                    make_float2(acc[mt][nt][0] + b0, acc[mt][nt][1] + b1);
            if (m0 + rl + 8 < cnt)
                *(float2*)(Cout + (size_t)(m0 + rl + 8) * D_MODEL + col) =
                    make_float2(acc[mt][nt][2] + b0, acc[mt][nt][3] + b1);
        }
    }
}

// ========== V GEMM: fp16 single-pass, 3-stage (R9 structure) ===============
#define V_STAGEB  (2 * TILEB)
#define V_NSTAGE  3
#define V_SMEM    (V_NSTAGE * V_STAGEB + 512)

__global__ __launch_bounds__(256, 2) void gemm_v_kernel(
    const __half* __restrict__ A, const __half* __restrict__ B,
    const float* __restrict__ bias, float* __restrict__ Cout)
{
    extern __shared__ __align__(128) char sm[];
    int* sidx = (int*)(sm + V_NSTAGE * V_STAGEB);

    const int cnt = g_off[BATCH];
    const int m0 = blockIdx.y * 128;
    if (m0 >= cnt) return;
    const int n0 = blockIdx.x * 128;

    const int tid  = threadIdx.x;
    const int lane = tid & 31;
    const int w    = tid >> 5;
    const int wm   = w & 1;
    const int wn   = w >> 1;
    const int g    = lane >> 2;
    const int t4   = lane & 3;

    if (tid < 128)
        sidx[tid] = (m0 + tid < cnt) ? g_gidx[m0 + tid] : g_gidx[0];
    __syncthreads();

    float acc[4][4][4];
    #pragma unroll
    for (int mt = 0; mt < 4; mt++)
        #pragma unroll
        for (int nt = 0; nt < 4; nt++)
            #pragma unroll
            for (int r = 0; r < 4; r++)
                acc[mt][nt][r] = 0.0f;

    auto load_stage = [&](int kc, int st) {
        char* base = sm + st * V_STAGEB;
        #pragma unroll
        for (int t = 0; t < 4; t++) {
            const int tile = t >> 1;
            const int wi   = tid + (t & 1) * 256;
            const int row  = wi >> 2;
            const int ch   = wi & 3;
            int grow = (tile == 0) ? sidx[row] : (n0 + row);
            const __half* src = (tile == 0 ? A : B) +
                                (size_t)grow * D_MODEL + kc * 32 + ch * 8;
            uint32_t dst = smem_u32(base + tile * TILEB + row * ROWB + ch * 16);
            cp_async16(dst, src);
        }
        cp_commit();
    };

    auto compute_stage = [&](int st) {
        const char* base = sm + st * V_STAGEB;
        const char* pA = base;
        const char* pB = base + TILEB;
        #pragma unroll
        for (int kk = 0; kk < 2; kk++) {
            const int c = kk * 16 + t4 * 2;
            uint32_t a[4][4], b[4][2];
            #pragma unroll
            for (int mt = 0; mt < 4; mt++) {
                int r = wm * 64 + mt * 16 + g;
                a[mt][0] = *(const uint32_t*)(pA + r * ROWB + c * 2);
                a[mt][1] = *(const uint32_t*)(pA + (r + 8) * ROWB + c * 2);
                a[mt][2] = *(const uint32_t*)(pA + r * ROWB + (c + 8) * 2);
                a[mt][3] = *(const uint32_t*)(pA + (r + 8) * ROWB + (c + 8) * 2);
            }
            #pragma unroll
            for (int nt = 0; nt < 4; nt++) {
                int n = wn * 32 + nt * 8 + g;
                b[nt][0] = *(const uint32_t*)(pB + n * ROWB + c * 2);
                b[nt][1] = *(const uint32_t*)(pB + n * ROWB + (c + 8) * 2);
            }
            #pragma unroll
            for (int mt = 0; mt < 4; mt++)
                #pragma unroll
                for (int nt = 0; nt < 4; nt++)
                    mma_fp16(acc[mt][nt], a[mt], b[nt][0], b[nt][1]);
        }
    };

    const int NIT = D_MODEL / 32;
    load_stage(0, 0);
    load_stage(1, 1);
    for (int it = 0; it < NIT; it++) {
        if (it + 2 < NIT) { load_stage(it + 2, (it + 2) % V_NSTAGE); cp_wait<2>(); }
        else if (it + 1 < NIT) { cp_wait<1>(); }
        else { cp_wait<0>(); }
        __syncthreads();
        compute_stage(it % V_NSTAGE);
        __syncthreads();
    }

    #pragma unroll
    for (int mt = 0; mt < 4; mt++) {
        int rl = wm * 64 + mt * 16 + g;
        #pragma unroll
        for (int nt = 0; nt < 4; nt++) {
            int col = n0 + wn * 32 + nt * 8 + t4 * 2;
            float b0 = bias[col], b1 = bias[col + 1];
            if (m0 + rl < cnt)
                *(float2*)(Cout + (size_t)(m0 + rl) * D_MODEL + col) =
                    make_float2(acc[mt][nt][0] + b0, acc[mt][nt][1] + b1);
            if (m0 + rl + 8 < cnt)
                *(float2*)(Cout + (size_t)(m0 + rl + 8) * D_MODEL + col) =
                    make_float2(acc[mt][nt][2] + b0, acc[mt][nt][3] + b1);
        }
    }
}

// ========== O GEMM: fp16 2-pass A-split, 2-stage, scatter epilogue =========
#define O_STAGEB  (3 * TILEB)
#define O_SMEM    (2 * O_STAGEB + 512)

__global__ __launch_bounds__(256, 2) void gemm_o_kernel(
    const __half* __restrict__ Ahi, const __half* __restrict__ Alo,
    const __half* __restrict__ B,
    const float* __restrict__ bias, float* __restrict__ Cout)
{
    extern __shared__ __align__(128) char sm[];
    int* sidx = (int*)(sm + 2 * O_STAGEB);

    const int cnt = g_off[BATCH];
    const int m0 = blockIdx.y * 128;
    if (m0 >= cnt) return;
    const int n0 = blockIdx.x * 128;

    const int tid  = threadIdx.x;
    const int lane = tid & 31;
    const int w    = tid >> 5;
    const int wm   = w & 1;
    const int wn   = w >> 1;
    const int g    = lane >> 2;
    const int t4   = lane & 3;

    if (tid < 128)
        sidx[tid] = (m0 + tid < cnt) ? g_gidx[m0 + tid] : g_gidx[0];
    __syncthreads();

    const __half* gsrc[3] = {Ahi, Alo, B};

    float acc[4][4][4];
    #pragma unroll
    for (int mt = 0; mt < 4; mt++)
        #pragma unroll
        for (int nt = 0; nt < 4; nt++)
            #pragma unroll
            for (int r = 0; r < 4; r++)
                acc[mt][nt][r] = 0.0f;

    auto load_stage = [&](int kc, int st) {
        char* base = sm + st * O_STAGEB;
        #pragma unroll
        for (int t = 0; t < 6; t++) {
            const int tile = t >> 1;
            const int wi   = tid + (t & 1) * 256;
            const int row  = wi >> 2;
            const int ch   = wi & 3;
            int grow;
            if (tile < 2) { int ar = m0 + row; grow = (ar < cnt) ? ar : m0; }
            else grow = n0 + row;
            const __half* src = gsrc[tile] + (size_t)grow * D_MODEL + kc * 32 + ch * 8;
            uint32_t dst = smem_u32(base + tile * TILEB + row * ROWB + ch * 16);
            cp_async16(dst, src);
        }
        cp_commit();
    };

    auto compute_stage = [&](int st) {
        const char* base = sm + st * O_STAGEB;
        const char* pAh = base;
        const char* pAl = base + TILEB;
        const char* pB  = base + 2 * TILEB;
        #pragma unroll
        for (int kk = 0; kk < 2; kk++) {
            const int c = kk * 16 + t4 * 2;
            uint32_t ah[4][4], al[4][4], b[4][2];
            #pragma unroll
            for (int mt = 0; mt < 4; mt++) {
                int r = wm * 64 + mt * 16 + g;
                ah[mt][0] = *(const uint32_t*)(pAh + r * ROWB + c * 2);
                ah[mt][1] = *(const uint32_t*)(pAh + (r + 8) * ROWB + c * 2);
                ah[mt][2] = *(const uint32_t*)(pAh + r * ROWB + (c + 8) * 2);
                ah[mt][3] = *(const uint32_t*)(pAh + (r + 8) * ROWB + (c + 8) * 2);
                al[mt][0] = *(const uint32_t*)(pAl + r * ROWB + c * 2);
                al[mt][1] = *(const uint32_t*)(pAl + (r + 8) * ROWB + c * 2);
                al[mt][2] = *(const uint32_t*)(pAl + r * ROWB + (c + 8) * 2);
                al[mt][3] = *(const uint32_t*)(pAl + (r + 8) * ROWB + (c + 8) * 2);
            }
            #pragma unroll
            for (int nt = 0; nt < 4; nt++) {
                int n = wn * 32 + nt * 8 + g;
                b[nt][0] = *(const uint32_t*)(pB + n * ROWB + c * 2);
                b[nt][1] = *(const uint32_t*)(pB + n * ROWB + (c + 8) * 2);
            }
            #pragma unroll
            for (int mt = 0; mt < 4; mt++)
                #pragma unroll
                for (int nt = 0; nt < 4; nt++) {
                    mma_fp16(acc[mt][nt], ah[mt], b[nt][0], b[nt][1]);
                    mma_fp16(acc[mt][nt], al[mt], b[nt][0], b[nt][1]);
                }
        }
    };

    const int NIT = D_MODEL / 32;
    load_stage(0, 0);
    load_stage(1, 1);
    for (int it = 0; it < NIT; it++) {
        if (it + 1 < NIT) cp_wait<1>(); else cp_wait<0>();
        __syncthreads();
        compute_stage(it & 1);
        __syncthreads();
        if (it + 2 < NIT) load_stage(it + 2, it & 1);
    }

    #pragma unroll
    for (int mt = 0; mt < 4; mt++) {
        int rl = wm * 64 + mt * 16 + g;
        #pragma unroll
        for (int nt = 0; nt < 4; nt++) {
            int col = n0 + wn * 32 + nt * 8 + t4 * 2;
            float b0 = bias[col], b1 = bias[col + 1];
            if (m0 + rl < cnt)
                *(float2*)(Cout + (size_t)sidx[rl] * D_MODEL + col) =
                    make_float2(acc[mt][nt][0] + b0, acc[mt][nt][1] + b1);
            if (m0 + rl + 8 < cnt)
                *(float2*)(Cout + (size_t)sidx[rl + 8] * D_MODEL + col) =
                    make_float2(acc[mt][nt][2] + b0, acc[mt][nt][3] + b1);
        }
    }
}

// ---------------------------------------------------------------------------
// Flash attention (proven R6/R8 kernel, verbatim)
// ---------------------------------------------------------------------------
#define BQ  64
#define BKV 32

__global__ __launch_bounds__(256) void attn_kernel(
    const float* __restrict__ Q, const float* __restrict__ K,
    const float* __restrict__ V, float* __restrict__ ctx)
{
    __shared__ float Qs[BQ][HDIM];
    __shared__ float Kts[HDIM][BKV + 1];
    __shared__ float Vs[BKV][HDIM];
    __shared__ float Ps[BQ][BKV + 1];
    __shared__ float alphaS[BQ];

    const int tid = threadIdx.x;
    const int b   = blockIdx.z;
    const int h   = blockIdx.y;
    const int cnt = g_cnt[b];
    const int off = g_off[b];
    const int q0  = blockIdx.x * BQ;
    if (q0 >= cnt) return;

    const size_t hcol = (size_t)h * HDIM;

    const int tx = tid & 15;
    const int ty = tid >> 4;

    {
        int r  = tid >> 4;
        int c4 = (tid & 15) * 4;
        #pragma unroll
        for (int i = 0; i < 4; i++) {
            int row = r + i * 16;
            int qi = (q0 + row < cnt) ? (off + q0 + row) : off;
            *(float4*)(&Qs[row][c4]) =
                *(const float4*)(Q + (size_t)qi * D_MODEL + hcol + c4);
        }
    }

    float o[4][4];
    #pragma unroll
    for (int i = 0; i < 4; i++)
        #pragma unroll
        for (int j = 0; j < 4; j++)
            o[i][j] = 0.0f;

    float m_run = -1e30f, l_run = 0.0f;

    for (int kv0 = 0; kv0 < cnt; kv0 += BKV) {
        __syncthreads();

        #pragma unroll
        for (int it = 0; it < 2; it++) {
            int idx = tid + it * 256;
            int row = idx >> 4;
            int c4  = (idx & 15) * 4;
            int ki  = (kv0 + row < cnt) ? (off + kv0 + row) : off;
            float4 kk = *(const float4*)(K + (size_t)ki * D_MODEL + hcol + c4);
            Kts[c4 + 0][row] = kk.x;
            Kts[c4 + 1][row] = kk.y;
            Kts[c4 + 2][row] = kk.z;
            Kts[c4 + 3][row] = kk.w;
            *(float4*)(&Vs[row][c4]) =
                *(const float4*)(V + (size_t)ki * D_MODEL + hcol + c4);
        }
        __syncthreads();

        float s[4][2];
        #pragma unroll
        for (int i = 0; i < 4; i++) { s[i][0] = 0.0f; s[i][1] = 0.0f; }
        #pragma unroll 8
        for (int d = 0; d < HDIM; d++) {
            float a0 = Qs[ty * 4 + 0][d];
            float a1 = Qs[ty * 4 + 1][d];
            float a2 = Qs[ty * 4 + 2][d];
            float a3 = Qs[ty * 4 + 3][d];
            float b0 = Kts[d][tx * 2 + 0];
            float b1 = Kts[d][tx * 2 + 1];
            s[0][0] += a0 * b0;  s[0][1] += a0 * b1;
            s[1][0] += a1 * b0;  s[1][1] += a1 * b1;
            s[2][0] += a2 * b0;  s[2][1] += a2 * b1;
            s[3][0] += a3 * b0;  s[3][1] += a3 * b1;
        }
        #pragma unroll
        for (int i = 0; i < 4; i++) {
            #pragma unroll
            for (int jj = 0; jj < 2; jj++) {
                int kc = tx * 2 + jj;
                Ps[ty * 4 + i][kc] = (kv0 + kc < cnt) ? s[i][jj] : NEG_BIG;
            }
        }
        __syncthreads();

        if (tid < BQ) {
            float mnew = m_run;
            #pragma unroll
            for (int c = 0; c < BKV; c++) mnew = fmaxf(mnew, Ps[tid][c]);
            float alpha = __expf(m_run - mnew);
            float lsum = l_run * alpha;
            #pragma unroll
            for (int c = 0; c < BKV; c++) {
                float p = __expf(Ps[tid][c] - mnew);
                Ps[tid][c] = p;
                lsum += p;
            }
            m_run = mnew;
            l_run = lsum;
            alphaS[tid] = alpha;
        }
        __syncthreads();

        #pragma unroll
        for (int i = 0; i < 4; i++) {
            float al = alphaS[ty * 4 + i];
            #pragma unroll
            for (int j = 0; j < 4; j++) o[i][j] *= al;
        }
        #pragma unroll 4
        for (int kc = 0; kc < BKV; kc++) {
            float p0 = Ps[ty * 4 + 0][kc];
            float p1 = Ps[ty * 4 + 1][kc];
            float p2 = Ps[ty * 4 + 2][kc];
            float p3 = Ps[ty * 4 + 3][kc];
            float4 vv = *(float4*)(&Vs[kc][tx * 4]);
            o[0][0] += p0 * vv.x; o[0][1] += p0 * vv.y; o[0][2] += p0 * vv.z; o[0][3] += p0 * vv.w;
            o[1][0] += p1 * vv.x; o[1][1] += p1 * vv.y; o[1][2] += p1 * vv.z; o[1][3] += p1 * vv.w;
            o[2][0] += p2 * vv.x; o[2][1] += p2 * vv.y; o[2][2] += p2 * vv.z; o[2][3] += p2 * vv.w;
            o[3][0] += p3 * vv.x; o[3][1] += p3 * vv.y; o[3][2] += p3 * vv.z; o[3][3] += p3 * vv.w;
        }
    }

    __syncthreads();
    if (tid < BQ) alphaS[tid] = 1.0f / l_run;
    __syncthreads();
    #pragma unroll
    for (int i = 0; i < 4; i++) {
        int r = ty * 4 + i;
        if (q0 + r < cnt) {
            float sc = alphaS[r];
            float4 ov;
            ov.x = o[i][0] * sc;
            ov.y = o[i][1] * sc;
            ov.z = o[i][2] * sc;
            ov.w = o[i][3] * sc;
            *(float4*)(ctx + (size_t)(off + q0 + r) * D_MODEL + hcol + tx * 4) = ov;
        }
    }
}

// ---------------------------------------------------------------------------
extern "C" void kernel_launch(void* const* d_in, const int* in_sizes, int n_in,
                              void* d_out, int out_size)
{
    (void)in_sizes; (void)n_in; (void)out_size;
    const float* x  = (const float*)d_in[0];
    const int*   pm = (const int*)  d_in[1];
    const float* Wq = (const float*)d_in[2];
    const float* bq = (const float*)d_in[3];
    const float* Wk = (const float*)d_in[4];
    const float* bk = (const float*)d_in[5];
    const float* Wv = (const float*)d_in[6];
    const float* bv = (const float*)d_in[7];
    const float* Wo = (const float*)d_in[8];
    const float* bo = (const float*)d_in[9];
    float* out = (float*)d_out;

    float *Qp, *Kp, *Vp, *Cp;
    cudaGetSymbolAddress((void**)&Qp, g_Q);
    cudaGetSymbolAddress((void**)&Kp, g_K);
    cudaGetSymbolAddress((void**)&Vp, g_V);
    cudaGetSymbolAddress((void**)&Cp, g_C);
    bf16 *xbh, *xbl, *wqkh, *wqkl;
    __half *xh16, *chh, *chl, *wv16, *wo16;
    cudaGetSymbolAddress((void**)&xbh, g_xbh);
    cudaGetSymbolAddress((void**)&xbl, g_xbl);
    cudaGetSymbolAddress((void**)&wqkh, g_wqk_h);
    cudaGetSymbolAddress((void**)&wqkl, g_wqk_l);
    cudaGetSymbolAddress((void**)&xh16, g_xh16);
    cudaGetSymbolAddress((void**)&chh, g_chh);
    cudaGetSymbolAddress((void**)&chl, g_chl);
    cudaGetSymbolAddress((void**)&wv16, g_wv16);
    cudaGetSymbolAddress((void**)&wo16, g_wo16);

    cudaFuncSetAttribute(gemm_qk_kernel,
                         cudaFuncAttributeMaxDynamicSharedMemorySize, QK_SMEM);
    cudaFuncSetAttribute(gemm_v_kernel,
                         cudaFuncAttributeMaxDynamicSharedMemorySize, V_SMEM);
    cudaFuncSetAttribute(gemm_o_kernel,
                         cudaFuncAttributeMaxDynamicSharedMemorySize, O_SMEM);

    const size_t WSZ = (size_t)D_MODEL * D_MODEL;
    const int n4 = MROWS * D_MODEL / 4;

    split_bf16_kernel<<<(n4 + 255) / 256, 256>>>(x, xbh, xbl, n4);
    tohalf_kernel<<<(n4 + 255) / 256, 256>>>(x, xh16, n4);
    build_idx_kernel<<<BATCH, 256>>>(pm);
    build_gidx_kernel<<<1, 256>>>();
    bias_fill_kernel<<<n4 / 256, 256>>>(bo, out);

    dim3 tgrid(D_MODEL / 32, D_MODEL / 32), tblk(32, 8);
    transpose_split_bf16_kernel<<<tgrid, tblk>>>(Wq, wqkh + 0 * WSZ, wqkl + 0 * WSZ);
    transpose_split_bf16_kernel<<<tgrid, tblk>>>(Wk, wqkh + 1 * WSZ, wqkl + 1 * WSZ);
    transpose_half_kernel<<<tgrid, tblk>>>(Wv, wv16);
    transpose_half_kernel<<<tgrid, tblk>>>(Wo, wo16);

    // Q,K projections: bf16 3-pass (softmax-sensitive)
    dim3 qkgrid(D_MODEL / 128, MROWS / 128, 2);
    gemm_qk_kernel<<<qkgrid, 256, QK_SMEM>>>(xbh, xbl, wqkh, wqkl, bq, bk, Qp, Kp);

    // V projection: fp16 single-pass (linear path)
    dim3 vgrid(D_MODEL / 128, MROWS / 128);
    gemm_v_kernel<<<vgrid, 256, V_SMEM>>>(xh16, wv16, bv, Vp);

    // attention (fp32, compacted)
    dim3 agrid(S_LEN / BQ, NHEAD, BATCH);
    attn_kernel<<<agrid, 256>>>(Qp, Kp, Vp, Cp);

    // O projection: fp16 2-pass A-split, scatter to out
    split_half_cnt_kernel<<<(n4 + 255) / 256, 256>>>(Cp, chh, chl);
    dim3 ogrid(D_MODEL / 128, MROWS / 128);
    gemm_o_kernel<<<ogrid, 256, O_SMEM>>>(chh, chl, wo16, bo, out);
}

// round 11
// speedup vs baseline: 7.7066x; 1.9484x over previous
#include <cuda_runtime.h>
#include <cuda_bf16.h>
#include <cuda_fp16.h>
#include <math.h>
#include <stdint.h>

#define BATCH   4
#define S_LEN   2048
#define D_MODEL 1024
#define NHEAD   16
#define HDIM    64
#define MROWS   (BATCH * S_LEN)

#define NEG_BIG (-1.0e9f)
typedef __nv_bfloat16 bf16;

// ---------------------------------------------------------------------------
// Scratch
// ---------------------------------------------------------------------------
__device__ __align__(1024) float g_Q[(size_t)MROWS * D_MODEL];
__device__ __align__(1024) float g_K[(size_t)MROWS * D_MODEL];
__device__ __align__(1024) float g_V[(size_t)MROWS * D_MODEL];
__device__ __align__(1024) float g_C[(size_t)MROWS * D_MODEL];

__device__ __align__(1024) bf16   g_xbh[(size_t)MROWS * D_MODEL];
__device__ __align__(1024) bf16   g_xbl[(size_t)MROWS * D_MODEL];
__device__ __align__(1024) __half g_xh16[(size_t)MROWS * D_MODEL];
__device__ __align__(1024) __half g_chh[(size_t)MROWS * D_MODEL];
__device__ __align__(1024) __half g_chl[(size_t)MROWS * D_MODEL];
__device__ __align__(1024) __half g_qh16[(size_t)MROWS * D_MODEL];
__device__ __align__(1024) __half g_ql16[(size_t)MROWS * D_MODEL];
__device__ __align__(1024) __half g_kh16[(size_t)MROWS * D_MODEL];
__device__ __align__(1024) __half g_kl16[(size_t)MROWS * D_MODEL];
__device__ __align__(1024) __half g_v16[(size_t)MROWS * D_MODEL];
__device__ __align__(1024) bf16   g_wqk_h[2][(size_t)D_MODEL * D_MODEL];
__device__ __align__(1024) bf16   g_wqk_l[2][(size_t)D_MODEL * D_MODEL];
__device__ __align__(1024) __half g_wv16[(size_t)D_MODEL * D_MODEL];
__device__ __align__(1024) __half g_wo16[(size_t)D_MODEL * D_MODEL];

__device__ int g_idx[BATCH][S_LEN];
__device__ int g_cnt[BATCH];
__device__ int g_off[BATCH + 1];
__device__ int g_gidx[MROWS];

// ---------------------------------------------------------------------------
// Helpers
// ---------------------------------------------------------------------------
__device__ __forceinline__ uint32_t smem_u32(const void* p) {
    uint32_t a;
    asm("{ .reg .u64 t; cvta.to.shared.u64 t, %1; cvt.u32.u64 %0, t; }"
        : "=r"(a) : "l"(p));
    return a;
}
__device__ __forceinline__ void cp_async16(uint32_t saddr, const void* gptr) {
    asm volatile("cp.async.cg.shared.global [%0], [%1], 16;"
                 :: "r"(saddr), "l"(__cvta_generic_to_global(gptr)));
}
__device__ __forceinline__ void cp_commit() {
    asm volatile("cp.async.commit_group;" ::: "memory");
}
template <int N>
__device__ __forceinline__ void cp_wait() {
    asm volatile("cp.async.wait_group %0;" :: "n"(N) : "memory");
}
__device__ __forceinline__ void mma_bf16(float* d, const uint32_t* a,
                                         uint32_t b0, uint32_t b1) {
    asm volatile(
        "mma.sync.aligned.m16n8k16.row.col.f32.bf16.bf16.f32 "
        "{%0,%1,%2,%3}, {%4,%5,%6,%7}, {%8,%9}, {%0,%1,%2,%3};"
        : "+f"(d[0]), "+f"(d[1]), "+f"(d[2]), "+f"(d[3])
        : "r"(a[0]), "r"(a[1]), "r"(a[2]), "r"(a[3]), "r"(b0), "r"(b1));
}
__device__ __forceinline__ void mma_fp16(float* d, const uint32_t* a,
                                         uint32_t b0, uint32_t b1) {
    asm volatile(
        "mma.sync.aligned.m16n8k16.row.col.f32.f16.f16.f32 "
        "{%0,%1,%2,%3}, {%4,%5,%6,%7}, {%8,%9}, {%0,%1,%2,%3};"
        : "+f"(d[0]), "+f"(d[1]), "+f"(d[2]), "+f"(d[3])
        : "r"(a[0]), "r"(a[1]), "r"(a[2]), "r"(a[3]), "r"(b0), "r"(b1));
}
__device__ __forceinline__ void ldmatrix_x4_trans(uint32_t* r, uint32_t addr) {
    asm volatile(
        "ldmatrix.sync.aligned.m8n8.x4.trans.shared.b16 {%0,%1,%2,%3}, [%4];"
        : "=r"(r[0]), "=r"(r[1]), "=r"(r[2]), "=r"(r[3]) : "r"(addr));
}
__device__ __forceinline__ uint32_t pack_h(float a, float b) {
    __half2 t = __floats2half2_rn(a, b);   // a -> low, b -> high
    return *(uint32_t*)&t;
}

// ---------------------------------------------------------------------------
// Prep kernels
// ---------------------------------------------------------------------------
__global__ __launch_bounds__(256) void split_bf16_kernel(
    const float* __restrict__ in, bf16* __restrict__ hi,
    bf16* __restrict__ lo, int n4)
{
    int i = blockIdx.x * blockDim.x + threadIdx.x;
    if (i >= n4) return;
    float4 v = ((const float4*)in)[i];
    bf16 hx = __float2bfloat16(v.x), hy = __float2bfloat16(v.y);
    bf16 hz = __float2bfloat16(v.z), hw = __float2bfloat16(v.w);
    bf16 lx = __float2bfloat16(v.x - __bfloat162float(hx));
    bf16 ly = __float2bfloat16(v.y - __bfloat162float(hy));
    bf16 lz = __float2bfloat16(v.z - __bfloat162float(hz));
    bf16 lw = __float2bfloat16(v.w - __bfloat162float(hw));
    ((__nv_bfloat162*)hi)[2 * i + 0] = __nv_bfloat162(hx, hy);
    ((__nv_bfloat162*)hi)[2 * i + 1] = __nv_bfloat162(hz, hw);
    ((__nv_bfloat162*)lo)[2 * i + 0] = __nv_bfloat162(lx, ly);
    ((__nv_bfloat162*)lo)[2 * i + 1] = __nv_bfloat162(lz, lw);
}

__global__ __launch_bounds__(256) void tohalf_kernel(
    const float* __restrict__ in, __half* __restrict__ out, int n4)
{
    int i = blockIdx.x * blockDim.x + threadIdx.x;
    if (i >= n4) return;
    float4 v = ((const float4*)in)[i];
    ((__half2*)out)[2 * i + 0] = __floats2half2_rn(v.x, v.y);
    ((__half2*)out)[2 * i + 1] = __floats2half2_rn(v.z, v.w);
}

__global__ __launch_bounds__(256) void tohalf_cnt_kernel(
    const float* __restrict__ in, __half* __restrict__ out)
{
    int n4 = g_off[BATCH] * (D_MODEL / 4);
    int i = blockIdx.x * blockDim.x + threadIdx.x;
    if (i >= n4) return;
    float4 v = ((const float4*)in)[i];
    ((__half2*)out)[2 * i + 0] = __floats2half2_rn(v.x, v.y);
    ((__half2*)out)[2 * i + 1] = __floats2half2_rn(v.z, v.w);
}

__global__ __launch_bounds__(256) void split_half_cnt_kernel(
    const float* __restrict__ in, __half* __restrict__ hi, __half* __restrict__ lo)
{
    int n4 = g_off[BATCH] * (D_MODEL / 4);
    int i = blockIdx.x * blockDim.x + threadIdx.x;
    if (i >= n4) return;
    float4 v = ((const float4*)in)[i];
    __half hx = __float2half_rn(v.x), hy = __float2half_rn(v.y);
    __half hz = __float2half_rn(v.z), hw = __float2half_rn(v.w);
    __half lx = __float2half_rn(v.x - __half2float(hx));
    __half ly = __float2half_rn(v.y - __half2float(hy));
    __half lz = __float2half_rn(v.z - __half2float(hz));
    __half lw = __float2half_rn(v.w - __half2float(hw));
    ((__half2*)hi)[2 * i + 0] = __half2(hx, hy);
    ((__half2*)hi)[2 * i + 1] = __half2(hz, hw);
    ((__half2*)lo)[2 * i + 0] = __half2(lx, ly);
    ((__half2*)lo)[2 * i + 1] = __half2(lz, lw);
}

__global__ __launch_bounds__(256) void bias_fill_kernel(
    const float* __restrict__ bias, float* __restrict__ out)
{
    int i = blockIdx.x * blockDim.x + threadIdx.x;
    int c = (i & (D_MODEL / 4 - 1)) * 4;
    ((float4*)out)[i] = *(const float4*)(bias + c);
}

__global__ __launch_bounds__(256) void transpose_split_bf16_kernel(
    const float* __restrict__ W, bf16* __restrict__ Thi, bf16* __restrict__ Tlo)
{
    __shared__ float t[32][33];
    int tx = threadIdx.x, ty = threadIdx.y;
    int n0 = blockIdx.x * 32, k0 = blockIdx.y * 32;
    #pragma unroll
    for (int j = 0; j < 4; j++)
        t[ty + 8 * j][tx] = W[(size_t)(k0 + ty + 8 * j) * D_MODEL + n0 + tx];
    __syncthreads();
    #pragma unroll
    for (int j = 0; j < 4; j++) {
        float v = t[tx][ty + 8 * j];
        bf16 h = __float2bfloat16(v);
        bf16 l = __float2bfloat16(v - __bfloat162float(h));
        size_t o = (size_t)(n0 + ty + 8 * j) * D_MODEL + k0 + tx;
        Thi[o] = h;
        Tlo[o] = l;
    }
}

__global__ __launch_bounds__(256) void transpose_half_kernel(
    const float* __restrict__ W, __half* __restrict__ T)
{
    __shared__ float t[32][33];
    int tx = threadIdx.x, ty = threadIdx.y;
    int n0 = blockIdx.x * 32, k0 = blockIdx.y * 32;
    #pragma unroll
    for (int j = 0; j < 4; j++)
        t[ty + 8 * j][tx] = W[(size_t)(k0 + ty + 8 * j) * D_MODEL + n0 + tx];
    __syncthreads();
    #pragma unroll
    for (int j = 0; j < 4; j++)
        T[(size_t)(n0 + ty + 8 * j) * D_MODEL + k0 + tx] =
            __float2half_rn(t[tx][ty + 8 * j]);
}

__global__ __launch_bounds__(256) void build_idx_kernel(const int* __restrict__ mask) {
    __shared__ int part[256];
    int b = blockIdx.x, t = threadIdx.x;
    const int* m = mask + (size_t)b * S_LEN;
    int loc[8], s = 0;
    #pragma unroll
    for (int j = 0; j < 8; j++) { loc[j] = (m[t * 8 + j] != 0); s += loc[j]; }
    part[t] = s;
    __syncthreads();
    for (int off = 1; off < 256; off <<= 1) {
        int v = (t >= off) ? part[t - off] : 0;
        __syncthreads();
        part[t] += v;
        __syncthreads();
    }
    int p = part[t] - s;
    #pragma unroll
    for (int j = 0; j < 8; j++)
        if (loc[j]) g_idx[b][p++] = t * 8 + j;
    if (t == 255) g_cnt[b] = part[255];
}

__global__ __launch_bounds__(256) void build_gidx_kernel() {
    __shared__ int off[BATCH + 1];
    if (threadIdx.x == 0) {
        off[0] = 0;
        for (int b = 0; b < BATCH; b++) off[b + 1] = off[b] + g_cnt[b];
        for (int b = 0; b <= BATCH; b++) g_off[b] = off[b];
    }
    __syncthreads();
    for (int b = 0; b < BATCH; b++) {
        int c = g_cnt[b], o = off[b];
        for (int i = threadIdx.x; i < c; i += 256)
            g_gidx[o + i] = b * S_LEN + g_idx[b][i];
    }
}

// ---------------------------------------------------------------------------
#define ROWB    80
#define TILEB   (128 * ROWB)

// ========== Q,K GEMM: bf16 3-pass split, 2-stage (R10 verbatim) ============
#define QK_STAGEB  (4 * TILEB)
#define QK_SMEM    (2 * QK_STAGEB + 512)

__global__ __launch_bounds__(256, 2) void gemm_qk_kernel(
    const bf16* __restrict__ Ahi, const bf16* __restrict__ Alo,
    const bf16* __restrict__ Whi_base, const bf16* __restrict__ Wlo_base,
    const float* __restrict__ bias0, const float* __restrict__ bias1,
    float* __restrict__ O0, float* __restrict__ O1)
{
    extern __shared__ __align__(128) char sm[];
    int* sidx = (int*)(sm + 2 * QK_STAGEB);

    const int cnt = g_off[BATCH];
    const int m0 = blockIdx.y * 128;
    if (m0 >= cnt) return;
    const int n0 = blockIdx.x * 128;
    const int z  = blockIdx.z;

    const bf16* Bhi = Whi_base + (size_t)z * D_MODEL * D_MODEL;
    const bf16* Blo = Wlo_base + (size_t)z * D_MODEL * D_MODEL;
    const float* bias = (z == 0 ? bias0 : bias1);
    float* Cout = (z == 0 ? O0 : O1);

    const int tid  = threadIdx.x;
    const int lane = tid & 31;
    const int w    = tid >> 5;
    const int wm   = w & 1;
    const int wn   = w >> 1;
    const int g    = lane >> 2;
    const int t4   = lane & 3;

    if (tid < 128)
        sidx[tid] = (m0 + tid < cnt) ? g_gidx[m0 + tid] : g_gidx[0];
    __syncthreads();

    const bf16* gsrc[4] = {Ahi, Alo, Bhi, Blo};

    float acc[4][4][4];
    #pragma unroll
    for (int mt = 0; mt < 4; mt++)
        #pragma unroll
        for (int nt = 0; nt < 4; nt++)
            #pragma unroll
            for (int r = 0; r < 4; r++)
                acc[mt][nt][r] = 0.0f;

    auto load_stage = [&](int kc, int st) {
        char* base = sm + st * QK_STAGEB;
        #pragma unroll
        for (int t = 0; t < 8; t++) {
            const int tile = t >> 1;
            const int wi   = tid + (t & 1) * 256;
            const int row  = wi >> 2;
            const int ch   = wi & 3;
            int grow = (tile < 2) ? sidx[row] : (n0 + row);
            const bf16* src = gsrc[tile] + (size_t)grow * D_MODEL + kc * 32 + ch * 8;
            uint32_t dst = smem_u32(base + tile * TILEB + row * ROWB + ch * 16);
            cp_async16(dst, src);
        }
        cp_commit();
    };

    auto compute_stage = [&](int st) {
        const char* base = sm + st * QK_STAGEB;
        const char* pAh = base;
        const char* pAl = base + TILEB;
        const char* pBh = base + 2 * TILEB;
        const char* pBl = base + 3 * TILEB;
        #pragma unroll
        for (int kk = 0; kk < 2; kk++) {
            const int c = kk * 16 + t4 * 2;
            uint32_t ah[4][4], al[4][4], bh[4][2], bl[4][2];
            #pragma unroll
            for (int mt = 0; mt < 4; mt++) {
                int r = wm * 64 + mt * 16 + g;
                ah[mt][0] = *(const uint32_t*)(pAh + r * ROWB + c * 2);
                ah[mt][1] = *(const uint32_t*)(pAh + (r + 8) * ROWB + c * 2);
                ah[mt][2] = *(const uint32_t*)(pAh + r * ROWB + (c + 8) * 2);
                ah[mt][3] = *(const uint32_t*)(pAh + (r + 8) * ROWB + (c + 8) * 2);
                al[mt][0] = *(const uint32_t*)(pAl + r * ROWB + c * 2);
                al[mt][1] = *(const uint32_t*)(pAl + (r + 8) * ROWB + c * 2);
                al[mt][2] = *(const uint32_t*)(pAl + r * ROWB + (c + 8) * 2);
                al[mt][3] = *(const uint32_t*)(pAl + (r + 8) * ROWB + (c + 8) * 2);
            }
            #pragma unroll
            for (int nt = 0; nt < 4; nt++) {
                int n = wn * 32 + nt * 8 + g;
                bh[nt][0] = *(const uint32_t*)(pBh + n * ROWB + c * 2);
                bh[nt][1] = *(const uint32_t*)(pBh + n * ROWB + (c + 8) * 2);
                bl[nt][0] = *(const uint32_t*)(pBl + n * ROWB + c * 2);
                bl[nt][1] = *(const uint32_t*)(pBl + n * ROWB + (c + 8) * 2);
            }
            #pragma unroll
            for (int mt = 0; mt < 4; mt++)
                #pragma unroll
                for (int nt = 0; nt < 4; nt++) {
                    mma_bf16(acc[mt][nt], ah[mt], bh[nt][0], bh[nt][1]);
                    mma_bf16(acc[mt][nt], ah[mt], bl[nt][0], bl[nt][1]);
                    mma_bf16(acc[mt][nt], al[mt], bh[nt][0], bh[nt][1]);
                }
        }
    };

    const int NIT = D_MODEL / 32;
    load_stage(0, 0);
    load_stage(1, 1);
    for (int it = 0; it < NIT; it++) {
        if (it + 1 < NIT) cp_wait<1>(); else cp_wait<0>();
        __syncthreads();
        compute_stage(it & 1);
        __syncthreads();
        if (it + 2 < NIT) load_stage(it + 2, it & 1);
    }

    #pragma unroll
    for (int mt = 0; mt < 4; mt++) {
        int rl = wm * 64 + mt * 16 + g;
        #pragma unroll
        for (int nt = 0; nt < 4; nt++) {
            int col = n0 + wn * 32 + nt * 8 + t4 * 2;
            float b0 = bias[col], b1 = bias[col + 1];
            if (m0 + rl < cnt)
                *(float2*)(Cout + (size_t)(m0 + rl) * D_MODEL + col) =
                    make_float2(acc[mt][nt][0] + b0, acc[mt][nt][1] + b1);
            if (m0 + rl + 8 < cnt)
                *(float2*)(Cout + (size_t)(m0 + rl + 8) * D_MODEL + col) =
                    make_float2(acc[mt][nt][2] + b0, acc[mt][nt][3] + b1);
        }
    }
}

// ========== V GEMM: fp16 single-pass, 3-stage (R10 verbatim) ===============
#define V_STAGEB  (2 * TILEB)
#define V_NSTAGE  3
#define V_SMEM    (V_NSTAGE * V_STAGEB + 512)

__global__ __launch_bounds__(256, 2) void gemm_v_kernel(
    const __half* __restrict__ A, const __half* __restrict__ B,
    const float* __restrict__ bias, float* __restrict__ Cout)
{
    extern __shared__ __align__(128) char sm[];
    int* sidx = (int*)(sm + V_NSTAGE * V_STAGEB);

    const int cnt = g_off[BATCH];
    const int m0 = blockIdx.y * 128;
    if (m0 >= cnt) return;
    const int n0 = blockIdx.x * 128;

    const int tid  = threadIdx.x;
    const int lane = tid & 31;
    const int w    = tid >> 5;
    const int wm   = w & 1;
    const int wn   = w >> 1;
    const int g    = lane >> 2;
    const int t4   = lane & 3;

    if (tid < 128)
        sidx[tid] = (m0 + tid < cnt) ? g_gidx[m0 + tid] : g_gidx[0];
    __syncthreads();

    float acc[4][4][4];
    #pragma unroll
    for (int mt = 0; mt < 4; mt++)
        #pragma unroll
        for (int nt = 0; nt < 4; nt++)
            #pragma unroll
            for (int r = 0; r < 4; r++)
                acc[mt][nt][r] = 0.0f;

    auto load_stage = [&](int kc, int st) {
        char* base = sm + st * V_STAGEB;
        #pragma unroll
        for (int t = 0; t < 4; t++) {
            const int tile = t >> 1;
            const int wi   = tid + (t & 1) * 256;
            const int row  = wi >> 2;
            const int ch   = wi & 3;
            int grow = (tile == 0) ? sidx[row] : (n0 + row);
            const __half* src = (tile == 0 ? A : B) +
                                (size_t)grow * D_MODEL + kc * 32 + ch * 8;
            uint32_t dst = smem_u32(base + tile * TILEB + row * ROWB + ch * 16);
            cp_async16(dst, src);
        }
        cp_commit();
    };

    auto compute_stage = [&](int st) {
        const char* base = sm + st * V_STAGEB;
        const char* pA = base;
        const char* pB = base + TILEB;
        #pragma unroll
        for (int kk = 0; kk < 2; kk++) {
            const int c = kk * 16 + t4 * 2;
            uint32_t a[4][4], b[4][2];
            #pragma unroll
            for (int mt = 0; mt < 4; mt++) {
                int r = wm * 64 + mt * 16 + g;
                a[mt][0] = *(const uint32_t*)(pA + r * ROWB + c * 2);
                a[mt][1] = *(const uint32_t*)(pA + (r + 8) * ROWB + c * 2);
                a[mt][2] = *(const uint32_t*)(pA + r * ROWB + (c + 8) * 2);
                a[mt][3] = *(const uint32_t*)(pA + (r + 8) * ROWB + (c + 8) * 2);
            }
            #pragma unroll
            for (int nt = 0; nt < 4; nt++) {
                int n = wn * 32 + nt * 8 + g;
                b[nt][0] = *(const uint32_t*)(pB + n * ROWB + c * 2);
                b[nt][1] = *(const uint32_t*)(pB + n * ROWB + (c + 8) * 2);
            }
            #pragma unroll
            for (int mt = 0; mt < 4; mt++)
                #pragma unroll
                for (int nt = 0; nt < 4; nt++)
                    mma_fp16(acc[mt][nt], a[mt], b[nt][0], b[nt][1]);
        }
    };

    const int NIT = D_MODEL / 32;
    load_stage(0, 0);
    load_stage(1, 1);
    for (int it = 0; it < NIT; it++) {
        if (it + 2 < NIT) { load_stage(it + 2, (it + 2) % V_NSTAGE); cp_wait<2>(); }
        else if (it + 1 < NIT) { cp_wait<1>(); }
        else { cp_wait<0>(); }
        __syncthreads();
        compute_stage(it % V_NSTAGE);
        __syncthreads();
    }

    #pragma unroll
    for (int mt = 0; mt < 4; mt++) {
        int rl = wm * 64 + mt * 16 + g;
        #pragma unroll
        for (int nt = 0; nt < 4; nt++) {
            int col = n0 + wn * 32 + nt * 8 + t4 * 2;
            float b0 = bias[col], b1 = bias[col + 1];
            if (m0 + rl < cnt)
                *(float2*)(Cout + (size_t)(m0 + rl) * D_MODEL + col) =
                    make_float2(acc[mt][nt][0] + b0, acc[mt][nt][1] + b1);
            if (m0 + rl + 8 < cnt)
                *(float2*)(Cout + (size_t)(m0 + rl + 8) * D_MODEL + col) =
                    make_float2(acc[mt][nt][2] + b0, acc[mt][nt][3] + b1);
        }
    }
}

// ========== O GEMM: fp16 2-pass A-split, 2-stage, scatter (R10 verbatim) ===
#define O_STAGEB  (3 * TILEB)
#define O_SMEM    (2 * O_STAGEB + 512)

__global__ __launch_bounds__(256, 2) void gemm_o_kernel(
    const __half* __restrict__ Ahi, const __half* __restrict__ Alo,
    const __half* __restrict__ B,
    const float* __restrict__ bias, float* __restrict__ Cout)
{
    extern __shared__ __align__(128) char sm[];
    int* sidx = (int*)(sm + 2 * O_STAGEB);

    const int cnt = g_off[BATCH];
    const int m0 = blockIdx.y * 128;
    if (m0 >= cnt) return;
    const int n0 = blockIdx.x * 128;

    const int tid  = threadIdx.x;
    const int lane = tid & 31;
    const int w    = tid >> 5;
    const int wm   = w & 1;
    const int wn   = w >> 1;
    const int g    = lane >> 2;
    const int t4   = lane & 3;

    if (tid < 128)
        sidx[tid] = (m0 + tid < cnt) ? g_gidx[m0 + tid] : g_gidx[0];
    __syncthreads();

    const __half* gsrc[3] = {Ahi, Alo, B};

    float acc[4][4][4];
    #pragma unroll
    for (int mt = 0; mt < 4; mt++)
        #pragma unroll
        for (int nt = 0; nt < 4; nt++)
            #pragma unroll
            for (int r = 0; r < 4; r++)
                acc[mt][nt][r] = 0.0f;

    auto load_stage = [&](int kc, int st) {
        char* base = sm + st * O_STAGEB;
        #pragma unroll
        for (int t = 0; t < 6; t++) {
            const int tile = t >> 1;
            const int wi   = tid + (t & 1) * 256;
            const int row  = wi >> 2;
            const int ch   = wi & 3;
            int grow;
            if (tile < 2) { int ar = m0 + row; grow = (ar < cnt) ? ar : m0; }
            else grow = n0 + row;
            const __half* src = gsrc[tile] + (size_t)grow * D_MODEL + kc * 32 + ch * 8;
            uint32_t dst = smem_u32(base + tile * TILEB + row * ROWB + ch * 16);
            cp_async16(dst, src);
        }
        cp_commit();
    };

    auto compute_stage = [&](int st) {
        const char* base = sm + st * O_STAGEB;
        const char* pAh = base;
        const char* pAl = base + TILEB;
        const char* pB  = base + 2 * TILEB;
        #pragma unroll
        for (int kk = 0; kk < 2; kk++) {
            const int c = kk * 16 + t4 * 2;
            uint32_t ah[4][4], al[4][4], b[4][2];
            #pragma unroll
            for (int mt = 0; mt < 4; mt++) {
                int r = wm * 64 + mt * 16 + g;
                ah[mt][0] = *(const uint32_t*)(pAh + r * ROWB + c * 2);
                ah[mt][1] = *(const uint32_t*)(pAh + (r + 8) * ROWB + c * 2);
                ah[mt][2] = *(const uint32_t*)(pAh + r * ROWB + (c + 8) * 2);
                ah[mt][3] = *(const uint32_t*)(pAh + (r + 8) * ROWB + (c + 8) * 2);
                al[mt][0] = *(const uint32_t*)(pAl + r * ROWB + c * 2);
                al[mt][1] = *(const uint32_t*)(pAl + (r + 8) * ROWB + c * 2);
                al[mt][2] = *(const uint32_t*)(pAl + r * ROWB + (c + 8) * 2);
                al[mt][3] = *(const uint32_t*)(pAl + (r + 8) * ROWB + (c + 8) * 2);
            }
            #pragma unroll
            for (int nt = 0; nt < 4; nt++) {
                int n = wn * 32 + nt * 8 + g;
                b[nt][0] = *(const uint32_t*)(pB + n * ROWB + c * 2);
                b[nt][1] = *(const uint32_t*)(pB + n * ROWB + (c + 8) * 2);
            }
            #pragma unroll
            for (int mt = 0; mt < 4; mt++)
                #pragma unroll
                for (int nt = 0; nt < 4; nt++) {
                    mma_fp16(acc[mt][nt], ah[mt], b[nt][0], b[nt][1]);
                    mma_fp16(acc[mt][nt], al[mt], b[nt][0], b[nt][1]);
                }
        }
    };

    const int NIT = D_MODEL / 32;
    load_stage(0, 0);
    load_stage(1, 1);
    for (int it = 0; it < NIT; it++) {
        if (it + 1 < NIT) cp_wait<1>(); else cp_wait<0>();
        __syncthreads();
        compute_stage(it & 1);
        __syncthreads();
        if (it + 2 < NIT) load_stage(it + 2, it & 1);
    }

    #pragma unroll
    for (int mt = 0; mt < 4; mt++) {
        int rl = wm * 64 + mt * 16 + g;
        #pragma unroll
        for (int nt = 0; nt < 4; nt++) {
            int col = n0 + wn * 32 + nt * 8 + t4 * 2;
            float b0 = bias[col], b1 = bias[col + 1];
            if (m0 + rl < cnt)
                *(float2*)(Cout + (size_t)sidx[rl] * D_MODEL + col) =
                    make_float2(acc[mt][nt][0] + b0, acc[mt][nt][1] + b1);
            if (m0 + rl + 8 < cnt)
                *(float2*)(Cout + (size_t)sidx[rl + 8] * D_MODEL + col) =
                    make_float2(acc[mt][nt][2] + b0, acc[mt][nt][3] + b1);
        }
    }
}

// ---------------------------------------------------------------------------
// Tensor-core flash attention. 128 threads = 4 warps; warp owns 16 q rows.
// BQ=64, BKV=64. S = QK^T via fp16 hi/lo 3-pass; softmax fp32; PV fp16 1-pass.
// ---------------------------------------------------------------------------
#define AROW   72                    // 64 halfs + 8 pad (144 B/row)
#define QTILE  (64 * AROW)           // 4608 elems
#define OFF_QH 0
#define OFF_QL QTILE
#define OFF_KV(st, a) (2 * QTILE + ((st) * 3 + (a)) * QTILE)   // a: 0=Kh 1=Kl 2=V
#define ATTN_SMEM (8 * QTILE * 2)    // 73728 B

__global__ __launch_bounds__(128) void attn_mma_kernel(
    const __half* __restrict__ Qh, const __half* __restrict__ Ql,
    const __half* __restrict__ Kh, const __half* __restrict__ Kl,
    const __half* __restrict__ V, float* __restrict__ ctx)
{
    extern __shared__ __align__(128) char smc[];
    const uint32_t smb = smem_u32(smc);

    const int tid = threadIdx.x;
    const int b   = blockIdx.z;
    const int h   = blockIdx.y;
    const int bcnt = g_cnt[b];
    const int boff = g_off[b];
    const int q0   = blockIdx.x * 64;
    if (q0 >= bcnt) return;

    const int lane = tid & 31;
    const int w    = tid >> 5;
    const int g    = lane >> 2;
    const int t4   = lane & 3;
    const int wr   = w * 16;
    const size_t hcol = (size_t)h * HDIM;

    // ---- load Q hi/lo once: 1024 16B-chunks, 8 per thread
    #pragma unroll
    for (int t = 0; t < 8; t++) {
        int i   = tid + t * 128;
        int arr = i >> 9;            // 0: hi, 1: lo
        int rem = i & 511;
        int row = rem >> 3;
        int ch  = rem & 7;
        int gr  = (q0 + row < bcnt) ? (boff + q0 + row) : boff;
        const __half* src = (arr ? Ql : Qh) + (size_t)gr * D_MODEL + hcol + ch * 8;
        cp_async16(smb + ((arr ? OFF_QL : OFF_QH) + row * AROW + ch * 8) * 2, src);
    }
    cp_commit();

    auto load_kv = [&](int kv0, int st) {
        #pragma unroll
        for (int t = 0; t < 12; t++) {
            int i   = tid + t * 128;
            int arr = i / 512;           // 0..2
            int rem = i & 511;
            int row = rem >> 3;
            int ch  = rem & 7;
            int gr  = (kv0 + row < bcnt) ? (boff + kv0 + row) : boff;
            const __half* base = (arr == 0) ? Kh : (arr == 1 ? Kl : V);
            cp_async16(smb + (OFF_KV(st, arr) + row * AROW + ch * 8) * 2,
                       base + (size_t)gr * D_MODEL + hcol + ch * 8);
        }
        cp_commit();
    };

    float o[8][4];
    #pragma unroll
    for (int nt = 0; nt < 8; nt++)
        #pragma unroll
        for (int r = 0; r < 4; r++) o[nt][r] = 0.0f;
    float m0r = -1e30f, m1r = -1e30f, l0r = 0.0f, l1r = 0.0f;

    const int nit = (bcnt + 63) >> 6;
    load_kv(0, 0);

    for (int it = 0; it < nit; it++) {
        if (it + 1 < nit) { load_kv((it + 1) << 6, (it + 1) & 1); cp_wait<1>(); }
        else              { cp_wait<0>(); }
        __syncthreads();

        const int st  = it & 1;
        const int kv0 = it << 6;
        const char* pQH = smc + OFF_QH * 2;
        const char* pQL = smc + OFF_QL * 2;
        const char* pKH = smc + OFF_KV(st, 0) * 2;
        const char* pKL = smc + OFF_KV(st, 1) * 2;
        const uint32_t pV = smb + OFF_KV(st, 2) * 2;

        // ---- S = Q K^T (fp16 hi/lo, 3 passes)
        float sacc[8][4];
        #pragma unroll
        for (int nt = 0; nt < 8; nt++)
            #pragma unroll
            for (int r = 0; r < 4; r++) sacc[nt][r] = 0.0f;

        #pragma unroll
        for (int kt = 0; kt < 4; kt++) {
            const int kc = kt * 16 + t4 * 2;
            uint32_t ah[4], al[4];
            {
                int r0 = (wr + g) * AROW + kc;
                int r1 = (wr + g + 8) * AROW + kc;
                ah[0] = *(const uint32_t*)(pQH + r0 * 2);
                ah[1] = *(const uint32_t*)(pQH + r1 * 2);
                ah[2] = *(const uint32_t*)(pQH + (r0 + 8) * 2);
                ah[3] = *(const uint32_t*)(pQH + (r1 + 8) * 2);
                al[0] = *(const uint32_t*)(pQL + r0 * 2);
                al[1] = *(const uint32_t*)(pQL + r1 * 2);
                al[2] = *(const uint32_t*)(pQL + (r0 + 8) * 2);
                al[3] = *(const uint32_t*)(pQL + (r1 + 8) * 2);
            }
            #pragma unroll
            for (int nt = 0; nt < 8; nt++) {
                int rk = (nt * 8 + g) * AROW + kc;
                uint32_t bh0 = *(const uint32_t*)(pKH + rk * 2);
                uint32_t bh1 = *(const uint32_t*)(pKH + (rk + 8) * 2);
                uint32_t bl0 = *(const uint32_t*)(pKL + rk * 2);
                uint32_t bl1 = *(const uint32_t*)(pKL + (rk + 8) * 2);
                mma_fp16(sacc[nt], ah, bh0, bh1);
                mma_fp16(sacc[nt], ah, bl0, bl1);
                mma_fp16(sacc[nt], al, bh0, bh1);
            }
        }

        // ---- mask + online softmax (rows wr+g, wr+g+8)
        float mx0 = -1e30f, mx1 = -1e30f;
        #pragma unroll
        for (int nt = 0; nt < 8; nt++) {
            int c0 = kv0 + nt * 8 + 2 * t4;
            if (c0 >= bcnt)     { sacc[nt][0] = NEG_BIG; sacc[nt][2] = NEG_BIG; }
            if (c0 + 1 >= bcnt) { sacc[nt][1] = NEG_BIG; sacc[nt][3] = NEG_BIG; }
            mx0 = fmaxf(mx0, fmaxf(sacc[nt][0], sacc[nt][1]));
            mx1 = fmaxf(mx1, fmaxf(sacc[nt][2], sacc[nt][3]));
        }
        mx0 = fmaxf(mx0, __shfl_xor_sync(0xffffffffu, mx0, 1));
        mx0 = fmaxf(mx0, __shfl_xor_sync(0xffffffffu, mx0, 2));
        mx1 = fmaxf(mx1, __shfl_xor_sync(0xffffffffu, mx1, 1));
        mx1 = fmaxf(mx1, __shfl_xor_sync(0xffffffffu, mx1, 2));

        float mn0 = fmaxf(m0r, mx0), mn1 = fmaxf(m1r, mx1);
        float al0 = __expf(m0r - mn0), al1 = __expf(m1r - mn1);
        float ls0 = 0.0f, ls1 = 0.0f;
        #pragma unroll
        for (int nt = 0; nt < 8; nt++) {
            sacc[nt][0] = __expf(sacc[nt][0] - mn0);
            sacc[nt][1] = __expf(sacc[nt][1] - mn0);
            sacc[nt][2] = __expf(sacc[nt][2] - mn1);
            sacc[nt][3] = __expf(sacc[nt][3] - mn1);
            ls0 += sacc[nt][0] + sacc[nt][1];
            ls1 += sacc[nt][2] + sacc[nt][3];
        }
        ls0 += __shfl_xor_sync(0xffffffffu, ls0, 1);
        ls0 += __shfl_xor_sync(0xffffffffu, ls0, 2);
        ls1 += __shfl_xor_sync(0xffffffffu, ls1, 1);
        ls1 += __shfl_xor_sync(0xffffffffu, ls1, 2);
        l0r = l0r * al0 + ls0;  m0r = mn0;
        l1r = l1r * al1 + ls1;  m1r = mn1;
        #pragma unroll
        for (int nt = 0; nt < 8; nt++) {
            o[nt][0] *= al0; o[nt][1] *= al0;
            o[nt][2] *= al1; o[nt][3] *= al1;
        }

        // ---- PV: P fp16 from registers, V via ldmatrix.trans
        #pragma unroll
        for (int kt = 0; kt < 4; kt++) {
            uint32_t pa[4];
            pa[0] = pack_h(sacc[2 * kt][0],     sacc[2 * kt][1]);
            pa[1] = pack_h(sacc[2 * kt][2],     sacc[2 * kt][3]);
            pa[2] = pack_h(sacc[2 * kt + 1][0], sacc[2 * kt + 1][1]);
            pa[3] = pack_h(sacc[2 * kt + 1][2], sacc[2 * kt + 1][3]);
            #pragma unroll
            for (int ntp = 0; ntp < 4; ntp++) {
                int mat = lane >> 3, r = lane & 7;
                int vrow = kt * 16 + (mat & 1) * 8 + r;
                int vcol = ntp * 16 + (mat >> 1) * 8;
                uint32_t vb[4];
                ldmatrix_x4_trans(vb, pV + (vrow * AROW + vcol) * 2);
                mma_fp16(o[2 * ntp],     pa, vb[0], vb[1]);
                mma_fp16(o[2 * ntp + 1], pa, vb[2], vb[3]);
            }
        }
        __syncthreads();
    }

    // ---- epilogue: scale by 1/l, write fp32 ctx (compacted)
    float inv0 = 1.0f / l0r, inv1 = 1.0f / l1r;
    int row0 = q0 + wr + g, row1 = row0 + 8;
    #pragma unroll
    for (int nt = 0; nt < 8; nt++) {
        int col = (int)hcol + nt * 8 + 2 * t4;
        if (row0 < bcnt)
            *(float2*)(ctx + (size_t)(boff + row0) * D_MODEL + col) =
                make_float2(o[nt][0] * inv0, o[nt][1] * inv0);
        if (row1 < bcnt)
            *(float2*)(ctx + (size_t)(boff + row1) * D_MODEL + col) =
                make_float2(o[nt][2] * inv1, o[nt][3] * inv1);
    }
}

// ---------------------------------------------------------------------------
extern "C" void kernel_launch(void* const* d_in, const int* in_sizes, int n_in,
                              void* d_out, int out_size)
{
    (void)in_sizes; (void)n_in; (void)out_size;
    const float* x  = (const float*)d_in[0];
    const int*   pm = (const int*)  d_in[1];
    const float* Wq = (const float*)d_in[2];
    const float* bq = (const float*)d_in[3];
    const float* Wk = (const float*)d_in[4];
    const float* bk = (const float*)d_in[5];
    const float* Wv = (const float*)d_in[6];
    const float* bv = (const float*)d_in[7];
    const float* Wo = (const float*)d_in[8];
    const float* bo = (const float*)d_in[9];
    float* out = (float*)d_out;

    float *Qp, *Kp, *Vp, *Cp;
    cudaGetSymbolAddress((void**)&Qp, g_Q);
    cudaGetSymbolAddress((void**)&Kp, g_K);
    cudaGetSymbolAddress((void**)&Vp, g_V);
    cudaGetSymbolAddress((void**)&Cp, g_C);
    bf16 *xbh, *xbl, *wqkh, *wqkl;
    __half *xh16, *chh, *chl, *wv16, *wo16, *qh16, *ql16, *kh16, *kl16, *v16;
    cudaGetSymbolAddress((void**)&xbh, g_xbh);
    cudaGetSymbolAddress((void**)&xbl, g_xbl);
    cudaGetSymbolAddress((void**)&wqkh, g_wqk_h);
    cudaGetSymbolAddress((void**)&wqkl, g_wqk_l);
    cudaGetSymbolAddress((void**)&xh16, g_xh16);
    cudaGetSymbolAddress((void**)&chh, g_chh);
    cudaGetSymbolAddress((void**)&chl, g_chl);
    cudaGetSymbolAddress((void**)&wv16, g_wv16);
    cudaGetSymbolAddress((void**)&wo16, g_wo16);
    cudaGetSymbolAddress((void**)&qh16, g_qh16);
    cudaGetSymbolAddress((void**)&ql16, g_ql16);
    cudaGetSymbolAddress((void**)&kh16, g_kh16);
    cudaGetSymbolAddress((void**)&kl16, g_kl16);
    cudaGetSymbolAddress((void**)&v16, g_v16);

    cudaFuncSetAttribute(gemm_qk_kernel,
                         cudaFuncAttributeMaxDynamicSharedMemorySize, QK_SMEM);
    cudaFuncSetAttribute(gemm_v_kernel,
                         cudaFuncAttributeMaxDynamicSharedMemorySize, V_SMEM);
    cudaFuncSetAttribute(gemm_o_kernel,
                         cudaFuncAttributeMaxDynamicSharedMemorySize, O_SMEM);
    cudaFuncSetAttribute(attn_mma_kernel,
                         cudaFuncAttributeMaxDynamicSharedMemorySize, ATTN_SMEM);

    const size_t WSZ = (size_t)D_MODEL * D_MODEL;
    const int n4 = MROWS * D_MODEL / 4;

    split_bf16_kernel<<<(n4 + 255) / 256, 256>>>(x, xbh, xbl, n4);
    tohalf_kernel<<<(n4 + 255) / 256, 256>>>(x, xh16, n4);
    build_idx_kernel<<<BATCH, 256>>>(pm);
    build_gidx_kernel<<<1, 256>>>();
    bias_fill_kernel<<<n4 / 256, 256>>>(bo, out);

    dim3 tgrid(D_MODEL / 32, D_MODEL / 32), tblk(32, 8);
    transpose_split_bf16_kernel<<<tgrid, tblk>>>(Wq, wqkh + 0 * WSZ, wqkl + 0 * WSZ);
    transpose_split_bf16_kernel<<<tgrid, tblk>>>(Wk, wqkh + 1 * WSZ, wqkl + 1 * WSZ);
    transpose_half_kernel<<<tgrid, tblk>>>(Wv, wv16);
    transpose_half_kernel<<<tgrid, tblk>>>(Wo, wo16);

    // Q,K projections: bf16 3-pass (softmax-sensitive)
    dim3 qkgrid(D_MODEL / 128, MROWS / 128, 2);
    gemm_qk_kernel<<<qkgrid, 256, QK_SMEM>>>(xbh, xbl, wqkh, wqkl, bq, bk, Qp, Kp);

    // V projection: fp16 single-pass
    dim3 vgrid(D_MODEL / 128, MROWS / 128);
    gemm_v_kernel<<<vgrid, 256, V_SMEM>>>(xh16, wv16, bv, Vp);

    // convert Q/K to fp16 hi/lo and V to fp16 for the mma attention
    split_half_cnt_kernel<<<(n4 + 255) / 256, 256>>>(Qp, qh16, ql16);
    split_half_cnt_kernel<<<(n4 + 255) / 256, 256>>>(Kp, kh16, kl16);
    tohalf_cnt_kernel<<<(n4 + 255) / 256, 256>>>(Vp, v16);

    // tensor-core attention (compacted)
    dim3 agrid(S_LEN / 64, NHEAD, BATCH);
    attn_mma_kernel<<<agrid, 128, ATTN_SMEM>>>(qh16, ql16, kh16, kl16, v16, Cp);

    // O projection: fp16 2-pass A-split, scatter to out
    split_half_cnt_kernel<<<(n4 + 255) / 256, 256>>>(Cp, chh, chl);
    dim3 ogrid(D_MODEL / 128, MROWS / 128);
    gemm_o_kernel<<<ogrid, 256, O_SMEM>>>(chh, chl, wo16, bo, out);
}

// round 12
// speedup vs baseline: 8.1525x; 1.0579x over previous
#include <cuda_runtime.h>
#include <cuda_bf16.h>
#include <cuda_fp16.h>
#include <math.h>
#include <stdint.h>

#define BATCH   4
#define S_LEN   2048
#define D_MODEL 1024
#define NHEAD   16
#define HDIM    64
#define MROWS   (BATCH * S_LEN)

#define NEG_BIG (-1.0e9f)
typedef __nv_bfloat16 bf16;

// ---------------------------------------------------------------------------
// Scratch (all intermediates fp16 now)
// ---------------------------------------------------------------------------
__device__ __align__(1024) bf16   g_xbh[(size_t)MROWS * D_MODEL];
__device__ __align__(1024) bf16   g_xbl[(size_t)MROWS * D_MODEL];
__device__ __align__(1024) __half g_xh16[(size_t)MROWS * D_MODEL];
__device__ __align__(1024) __half g_qh16[(size_t)MROWS * D_MODEL];
__device__ __align__(1024) __half g_ql16[(size_t)MROWS * D_MODEL];
__device__ __align__(1024) __half g_kh16[(size_t)MROWS * D_MODEL];
__device__ __align__(1024) __half g_kl16[(size_t)MROWS * D_MODEL];
__device__ __align__(1024) __half g_v16[(size_t)MROWS * D_MODEL];
__device__ __align__(1024) __half g_c16[(size_t)MROWS * D_MODEL];
__device__ __align__(1024) bf16   g_wqk_h[2][(size_t)D_MODEL * D_MODEL];
__device__ __align__(1024) bf16   g_wqk_l[2][(size_t)D_MODEL * D_MODEL];
__device__ __align__(1024) __half g_wv16[(size_t)D_MODEL * D_MODEL];
__device__ __align__(1024) __half g_wo16[(size_t)D_MODEL * D_MODEL];

__device__ int g_idx[BATCH][S_LEN];
__device__ int g_cnt[BATCH];
__device__ int g_off[BATCH + 1];
__device__ int g_gidx[MROWS];

// ---------------------------------------------------------------------------
// Helpers
// ---------------------------------------------------------------------------
__device__ __forceinline__ uint32_t smem_u32(const void* p) {
    uint32_t a;
    asm("{ .reg .u64 t; cvta.to.shared.u64 t, %1; cvt.u32.u64 %0, t; }"
        : "=r"(a) : "l"(p));
    return a;
}
__device__ __forceinline__ void cp_async16(uint32_t saddr, const void* gptr) {
    asm volatile("cp.async.cg.shared.global [%0], [%1], 16;"
                 :: "r"(saddr), "l"(__cvta_generic_to_global(gptr)));
}
__device__ __forceinline__ void cp_commit() {
    asm volatile("cp.async.commit_group;" ::: "memory");
}
template <int N>
__device__ __forceinline__ void cp_wait() {
    asm volatile("cp.async.wait_group %0;" :: "n"(N) : "memory");
}
__device__ __forceinline__ void mma_bf16(float* d, const uint32_t* a,
                                         uint32_t b0, uint32_t b1) {
    asm volatile(
        "mma.sync.aligned.m16n8k16.row.col.f32.bf16.bf16.f32 "
        "{%0,%1,%2,%3}, {%4,%5,%6,%7}, {%8,%9}, {%0,%1,%2,%3};"
        : "+f"(d[0]), "+f"(d[1]), "+f"(d[2]), "+f"(d[3])
        : "r"(a[0]), "r"(a[1]), "r"(a[2]), "r"(a[3]), "r"(b0), "r"(b1));
}
__device__ __forceinline__ void mma_fp16(float* d, const uint32_t* a,
                                         uint32_t b0, uint32_t b1) {
    asm volatile(
        "mma.sync.aligned.m16n8k16.row.col.f32.f16.f16.f32 "
        "{%0,%1,%2,%3}, {%4,%5,%6,%7}, {%8,%9}, {%0,%1,%2,%3};"
        : "+f"(d[0]), "+f"(d[1]), "+f"(d[2]), "+f"(d[3])
        : "r"(a[0]), "r"(a[1]), "r"(a[2]), "r"(a[3]), "r"(b0), "r"(b1));
}
__device__ __forceinline__ void ldmatrix_x4_trans(uint32_t* r, uint32_t addr) {
    asm volatile(
        "ldmatrix.sync.aligned.m8n8.x4.trans.shared.b16 {%0,%1,%2,%3}, [%4];"
        : "=r"(r[0]), "=r"(r[1]), "=r"(r[2]), "=r"(r[3]) : "r"(addr));
}
__device__ __forceinline__ uint32_t pack_h(float a, float b) {
    __half2 t = __floats2half2_rn(a, b);
    return *(uint32_t*)&t;
}

// ---------------------------------------------------------------------------
// Prep kernels
// ---------------------------------------------------------------------------
__global__ __launch_bounds__(256) void split_bf16_kernel(
    const float* __restrict__ in, bf16* __restrict__ hi,
    bf16* __restrict__ lo, int n4)
{
    int i = blockIdx.x * blockDim.x + threadIdx.x;
    if (i >= n4) return;
    float4 v = ((const float4*)in)[i];
    bf16 hx = __float2bfloat16(v.x), hy = __float2bfloat16(v.y);
    bf16 hz = __float2bfloat16(v.z), hw = __float2bfloat16(v.w);
    bf16 lx = __float2bfloat16(v.x - __bfloat162float(hx));
    bf16 ly = __float2bfloat16(v.y - __bfloat162float(hy));
    bf16 lz = __float2bfloat16(v.z - __bfloat162float(hz));
    bf16 lw = __float2bfloat16(v.w - __bfloat162float(hw));
    ((__nv_bfloat162*)hi)[2 * i + 0] = __nv_bfloat162(hx, hy);
    ((__nv_bfloat162*)hi)[2 * i + 1] = __nv_bfloat162(hz, hw);
    ((__nv_bfloat162*)lo)[2 * i + 0] = __nv_bfloat162(lx, ly);
    ((__nv_bfloat162*)lo)[2 * i + 1] = __nv_bfloat162(lz, lw);
}

__global__ __launch_bounds__(256) void tohalf_kernel(
    const float* __restrict__ in, __half* __restrict__ out, int n4)
{
    int i = blockIdx.x * blockDim.x + threadIdx.x;
    if (i >= n4) return;
    float4 v = ((const float4*)in)[i];
    ((__half2*)out)[2 * i + 0] = __floats2half2_rn(v.x, v.y);
    ((__half2*)out)[2 * i + 1] = __floats2half2_rn(v.z, v.w);
}

__global__ __launch_bounds__(256) void bias_fill_kernel(
    const float* __restrict__ bias, float* __restrict__ out)
{
    int i = blockIdx.x * blockDim.x + threadIdx.x;
    int c = (i & (D_MODEL / 4 - 1)) * 4;
    ((float4*)out)[i] = *(const float4*)(bias + c);
}

__global__ __launch_bounds__(256) void transpose_split_bf16_kernel(
    const float* __restrict__ W, bf16* __restrict__ Thi, bf16* __restrict__ Tlo)
{
    __shared__ float t[32][33];
    int tx = threadIdx.x, ty = threadIdx.y;
    int n0 = blockIdx.x * 32, k0 = blockIdx.y * 32;
    #pragma unroll
    for (int j = 0; j < 4; j++)
        t[ty + 8 * j][tx] = W[(size_t)(k0 + ty + 8 * j) * D_MODEL + n0 + tx];
    __syncthreads();
    #pragma unroll
    for (int j = 0; j < 4; j++) {
        float v = t[tx][ty + 8 * j];
        bf16 h = __float2bfloat16(v);
        bf16 l = __float2bfloat16(v - __bfloat162float(h));
        size_t o = (size_t)(n0 + ty + 8 * j) * D_MODEL + k0 + tx;
        Thi[o] = h;
        Tlo[o] = l;
    }
}

__global__ __launch_bounds__(256) void transpose_half_kernel(
    const float* __restrict__ W, __half* __restrict__ T)
{
    __shared__ float t[32][33];
    int tx = threadIdx.x, ty = threadIdx.y;
    int n0 = blockIdx.x * 32, k0 = blockIdx.y * 32;
    #pragma unroll
    for (int j = 0; j < 4; j++)
        t[ty + 8 * j][tx] = W[(size_t)(k0 + ty + 8 * j) * D_MODEL + n0 + tx];
    __syncthreads();
    #pragma unroll
    for (int j = 0; j < 4; j++)
        T[(size_t)(n0 + ty + 8 * j) * D_MODEL + k0 + tx] =
            __float2half_rn(t[tx][ty + 8 * j]);
}

__global__ __launch_bounds__(256) void build_idx_kernel(const int* __restrict__ mask) {
    __shared__ int part[256];
    int b = blockIdx.x, t = threadIdx.x;
    const int* m = mask + (size_t)b * S_LEN;
    int loc[8], s = 0;
    #pragma unroll
    for (int j = 0; j < 8; j++) { loc[j] = (m[t * 8 + j] != 0); s += loc[j]; }
    part[t] = s;
    __syncthreads();
    for (int off = 1; off < 256; off <<= 1) {
        int v = (t >= off) ? part[t - off] : 0;
        __syncthreads();
        part[t] += v;
        __syncthreads();
    }
    int p = part[t] - s;
    #pragma unroll
    for (int j = 0; j < 8; j++)
        if (loc[j]) g_idx[b][p++] = t * 8 + j;
    if (t == 255) g_cnt[b] = part[255];
}

__global__ __launch_bounds__(256) void build_gidx_kernel() {
    __shared__ int off[BATCH + 1];
    if (threadIdx.x == 0) {
        off[0] = 0;
        for (int b = 0; b < BATCH; b++) off[b + 1] = off[b] + g_cnt[b];
        for (int b = 0; b <= BATCH; b++) g_off[b] = off[b];
    }
    __syncthreads();
    for (int b = 0; b < BATCH; b++) {
        int c = g_cnt[b], o = off[b];
        for (int i = threadIdx.x; i < c; i += 256)
            g_gidx[o + i] = b * S_LEN + g_idx[b][i];
    }
}

// ---------------------------------------------------------------------------
#define ROWB    80
#define TILEB   (128 * ROWB)

// ========== Q,K GEMM: bf16 3-pass split, 2-stage, fp16 hi/lo epilogue ======
#define QK_STAGEB  (4 * TILEB)
#define QK_SMEM    (2 * QK_STAGEB + 512)

__global__ __launch_bounds__(256, 2) void gemm_qk_kernel(
    const bf16* __restrict__ Ahi, const bf16* __restrict__ Alo,
    const bf16* __restrict__ Whi_base, const bf16* __restrict__ Wlo_base,
    const float* __restrict__ bias0, const float* __restrict__ bias1,
    __half* __restrict__ Qh, __half* __restrict__ Ql,
    __half* __restrict__ Kh, __half* __restrict__ Kl)
{
    extern __shared__ __align__(128) char sm[];
    int* sidx = (int*)(sm + 2 * QK_STAGEB);

    const int cnt = g_off[BATCH];
    const int m0 = blockIdx.y * 128;
    if (m0 >= cnt) return;
    const int n0 = blockIdx.x * 128;
    const int z  = blockIdx.z;

    const bf16* Bhi = Whi_base + (size_t)z * D_MODEL * D_MODEL;
    const bf16* Blo = Wlo_base + (size_t)z * D_MODEL * D_MODEL;
    const float* bias = (z == 0 ? bias0 : bias1);
    __half* oh = (z == 0 ? Qh : Kh);
    __half* ol = (z == 0 ? Ql : Kl);

    const int tid  = threadIdx.x;
    const int lane = tid & 31;
    const int w    = tid >> 5;
    const int wm   = w & 1;
    const int wn   = w >> 1;
    const int g    = lane >> 2;
    const int t4   = lane & 3;

    if (tid < 128)
        sidx[tid] = (m0 + tid < cnt) ? g_gidx[m0 + tid] : g_gidx[0];
    __syncthreads();

    const bf16* gsrc[4] = {Ahi, Alo, Bhi, Blo};

    float acc[4][4][4];
    #pragma unroll
    for (int mt = 0; mt < 4; mt++)
        #pragma unroll
        for (int nt = 0; nt < 4; nt++)
            #pragma unroll
            for (int r = 0; r < 4; r++)
                acc[mt][nt][r] = 0.0f;

    auto load_stage = [&](int kc, int st) {
        char* base = sm + st * QK_STAGEB;
        #pragma unroll
        for (int t = 0; t < 8; t++) {
            const int tile = t >> 1;
            const int wi   = tid + (t & 1) * 256;
            const int row  = wi >> 2;
            const int ch   = wi & 3;
            int grow = (tile < 2) ? sidx[row] : (n0 + row);
            const bf16* src = gsrc[tile] + (size_t)grow * D_MODEL + kc * 32 + ch * 8;
            uint32_t dst = smem_u32(base + tile * TILEB + row * ROWB + ch * 16);
            cp_async16(dst, src);
        }
        cp_commit();
    };

    auto compute_stage = [&](int st) {
        const char* base = sm + st * QK_STAGEB;
        const char* pAh = base;
        const char* pAl = base + TILEB;
        const char* pBh = base + 2 * TILEB;
        const char* pBl = base + 3 * TILEB;
        #pragma unroll
        for (int kk = 0; kk < 2; kk++) {
            const int c = kk * 16 + t4 * 2;
            uint32_t ah[4][4], al[4][4], bh[4][2], bl[4][2];
            #pragma unroll
            for (int mt = 0; mt < 4; mt++) {
                int r = wm * 64 + mt * 16 + g;
                ah[mt][0] = *(const uint32_t*)(pAh + r * ROWB + c * 2);
                ah[mt][1] = *(const uint32_t*)(pAh + (r + 8) * ROWB + c * 2);
                ah[mt][2] = *(const uint32_t*)(pAh + r * ROWB + (c + 8) * 2);
                ah[mt][3] = *(const uint32_t*)(pAh + (r + 8) * ROWB + (c + 8) * 2);
                al[mt][0] = *(const uint32_t*)(pAl + r * ROWB + c * 2);
                al[mt][1] = *(const uint32_t*)(pAl + (r + 8) * ROWB + c * 2);
                al[mt][2] = *(const uint32_t*)(pAl + r * ROWB + (c + 8) * 2);
                al[mt][3] = *(const uint32_t*)(pAl + (r + 8) * ROWB + (c + 8) * 2);
            }
            #pragma unroll
            for (int nt = 0; nt < 4; nt++) {
                int n = wn * 32 + nt * 8 + g;
                bh[nt][0] = *(const uint32_t*)(pBh + n * ROWB + c * 2);
                bh[nt][1] = *(const uint32_t*)(pBh + n * ROWB + (c + 8) * 2);
                bl[nt][0] = *(const uint32_t*)(pBl + n * ROWB + c * 2);
                bl[nt][1] = *(const uint32_t*)(pBl + n * ROWB + (c + 8) * 2);
            }
            #pragma unroll
            for (int mt = 0; mt < 4; mt++)
                #pragma unroll
                for (int nt = 0; nt < 4; nt++) {
                    mma_bf16(acc[mt][nt], ah[mt], bh[nt][0], bh[nt][1]);
                    mma_bf16(acc[mt][nt], ah[mt], bl[nt][0], bl[nt][1]);
                    mma_bf16(acc[mt][nt], al[mt], bh[nt][0], bh[nt][1]);
                }
        }
    };

    const int NIT = D_MODEL / 32;
    load_stage(0, 0);
    load_stage(1, 1);
    for (int it = 0; it < NIT; it++) {
        if (it + 1 < NIT) cp_wait<1>(); else cp_wait<0>();
        __syncthreads();
        compute_stage(it & 1);
        __syncthreads();
        if (it + 2 < NIT) load_stage(it + 2, it & 1);
    }

    #pragma unroll
    for (int mt = 0; mt < 4; mt++) {
        int rl = wm * 64 + mt * 16 + g;
        #pragma unroll
        for (int nt = 0; nt < 4; nt++) {
            int col = n0 + wn * 32 + nt * 8 + t4 * 2;
            float b0 = bias[col], b1 = bias[col + 1];
            float v00 = acc[mt][nt][0] + b0, v01 = acc[mt][nt][1] + b1;
            float v10 = acc[mt][nt][2] + b0, v11 = acc[mt][nt][3] + b1;
            if (m0 + rl < cnt) {
                size_t off = (size_t)(m0 + rl) * D_MODEL + col;
                __half h0 = __float2half_rn(v00), h1 = __float2half_rn(v01);
                *(uint32_t*)(oh + off) = pack_h(v00, v01);
                *(uint32_t*)(ol + off) = pack_h(v00 - __half2float(h0),
                                                v01 - __half2float(h1));
            }
            if (m0 + rl + 8 < cnt) {
                size_t off = (size_t)(m0 + rl + 8) * D_MODEL + col;
                __half h0 = __float2half_rn(v10), h1 = __float2half_rn(v11);
                *(uint32_t*)(oh + off) = pack_h(v10, v11);
                *(uint32_t*)(ol + off) = pack_h(v10 - __half2float(h0),
                                                v11 - __half2float(h1));
            }
        }
    }
}

// ========== fp16 single-pass GEMM, 3-stage. MODE 0: V (gather, fp16 out).
// ========== MODE 1: O (compacted A, fp32 scatter out). =====================
#define F_STAGEB  (2 * TILEB)
#define F_NSTAGE  3
#define F_SMEM    (F_NSTAGE * F_STAGEB + 512)

template<int MODE>
__global__ __launch_bounds__(256, 2) void gemm_f16_kernel(
    const __half* __restrict__ A, const __half* __restrict__ B,
    const float* __restrict__ bias,
    __half* __restrict__ Oh, float* __restrict__ Of)
{
    extern __shared__ __align__(128) char sm[];
    int* sidx = (int*)(sm + F_NSTAGE * F_STAGEB);

    const int cnt = g_off[BATCH];
    const int m0 = blockIdx.y * 128;
    if (m0 >= cnt) return;
    const int n0 = blockIdx.x * 128;

    const int tid  = threadIdx.x;
    const int lane = tid & 31;
    const int w    = tid >> 5;
    const int wm   = w & 1;
    const int wn   = w >> 1;
    const int g    = lane >> 2;
    const int t4   = lane & 3;

    if (tid < 128)
        sidx[tid] = (m0 + tid < cnt) ? g_gidx[m0 + tid] : g_gidx[0];
    __syncthreads();

    float acc[4][4][4];
    #pragma unroll
    for (int mt = 0; mt < 4; mt++)
        #pragma unroll
        for (int nt = 0; nt < 4; nt++)
            #pragma unroll
            for (int r = 0; r < 4; r++)
                acc[mt][nt][r] = 0.0f;

    auto load_stage = [&](int kc, int st) {
        char* base = sm + st * F_STAGEB;
        #pragma unroll
        for (int t = 0; t < 4; t++) {
            const int tile = t >> 1;
            const int wi   = tid + (t & 1) * 256;
            const int row  = wi >> 2;
            const int ch   = wi & 3;
            int grow;
            if (tile == 0) {
                if (MODE == 0) grow = sidx[row];
                else { int ar = m0 + row; grow = (ar < cnt) ? ar : m0; }
            } else grow = n0 + row;
            const __half* src = (tile == 0 ? A : B) +
                                (size_t)grow * D_MODEL + kc * 32 + ch * 8;
            uint32_t dst = smem_u32(base + tile * TILEB + row * ROWB + ch * 16);
            cp_async16(dst, src);
        }
        cp_commit();
    };

    auto compute_stage = [&](int st) {
        const char* base = sm + st * F_STAGEB;
        const char* pA = base;
        const char* pB = base + TILEB;
        #pragma unroll
        for (int kk = 0; kk < 2; kk++) {
            const int c = kk * 16 + t4 * 2;
            uint32_t a[4][4], b[4][2];
            #pragma unroll
            for (int mt = 0; mt < 4; mt++) {
                int r = wm * 64 + mt * 16 + g;
                a[mt][0] = *(const uint32_t*)(pA + r * ROWB + c * 2);
                a[mt][1] = *(const uint32_t*)(pA + (r + 8) * ROWB + c * 2);
                a[mt][2] = *(const uint32_t*)(pA + r * ROWB + (c + 8) * 2);
                a[mt][3] = *(const uint32_t*)(pA + (r + 8) * ROWB + (c + 8) * 2);
            }
            #pragma unroll
            for (int nt = 0; nt < 4; nt++) {
                int n = wn * 32 + nt * 8 + g;
                b[nt][0] = *(const uint32_t*)(pB + n * ROWB + c * 2);
                b[nt][1] = *(const uint32_t*)(pB + n * ROWB + (c + 8) * 2);
            }
            #pragma unroll
            for (int mt = 0; mt < 4; mt++)
                #pragma unroll
                for (int nt = 0; nt < 4; nt++)
                    mma_fp16(acc[mt][nt], a[mt], b[nt][0], b[nt][1]);
        }
    };

    const int NIT = D_MODEL / 32;
    load_stage(0, 0);
    load_stage(1, 1);
    for (int it = 0; it < NIT; it++) {
        if (it + 2 < NIT) { load_stage(it + 2, (it + 2) % F_NSTAGE); cp_wait<2>(); }
        else if (it + 1 < NIT) { cp_wait<1>(); }
        else { cp_wait<0>(); }
        __syncthreads();
        compute_stage(it % F_NSTAGE);
        __syncthreads();
    }

    #pragma unroll
    for (int mt = 0; mt < 4; mt++) {
        int rl = wm * 64 + mt * 16 + g;
        #pragma unroll
        for (int nt = 0; nt < 4; nt++) {
            int col = n0 + wn * 32 + nt * 8 + t4 * 2;
            float b0 = bias[col], b1 = bias[col + 1];
            float v00 = acc[mt][nt][0] + b0, v01 = acc[mt][nt][1] + b1;
            float v10 = acc[mt][nt][2] + b0, v11 = acc[mt][nt][3] + b1;
            if (MODE == 0) {
                if (m0 + rl < cnt)
                    *(uint32_t*)(Oh + (size_t)(m0 + rl) * D_MODEL + col) =
                        pack_h(v00, v01);
                if (m0 + rl + 8 < cnt)
                    *(uint32_t*)(Oh + (size_t)(m0 + rl + 8) * D_MODEL + col) =
                        pack_h(v10, v11);
            } else {
                if (m0 + rl < cnt)
                    *(float2*)(Of + (size_t)sidx[rl] * D_MODEL + col) =
                        make_float2(v00, v01);
                if (m0 + rl + 8 < cnt)
                    *(float2*)(Of + (size_t)sidx[rl + 8] * D_MODEL + col) =
                        make_float2(v10, v11);
            }
        }
    }
}

// ---------------------------------------------------------------------------
// Tensor-core flash attention (R11 proven), epilogue now writes fp16 ctx.
// ---------------------------------------------------------------------------
#define AROW   72
#define QTILE  (64 * AROW)
#define OFF_QH 0
#define OFF_QL QTILE
#define OFF_KV(st, a) (2 * QTILE + ((st) * 3 + (a)) * QTILE)
#define ATTN_SMEM (8 * QTILE * 2)

__global__ __launch_bounds__(128) void attn_mma_kernel(
    const __half* __restrict__ Qh, const __half* __restrict__ Ql,
    const __half* __restrict__ Kh, const __half* __restrict__ Kl,
    const __half* __restrict__ V, __half* __restrict__ ctx)
{
    extern __shared__ __align__(128) char smc[];
    const uint32_t smb = smem_u32(smc);

    const int tid = threadIdx.x;
    const int b   = blockIdx.z;
    const int h   = blockIdx.y;
    const int bcnt = g_cnt[b];
    const int boff = g_off[b];
    const int q0   = blockIdx.x * 64;
    if (q0 >= bcnt) return;

    const int lane = tid & 31;
    const int w    = tid >> 5;
    const int g    = lane >> 2;
    const int t4   = lane & 3;
    const int wr   = w * 16;
    const size_t hcol = (size_t)h * HDIM;

    #pragma unroll
    for (int t = 0; t < 8; t++) {
        int i   = tid + t * 128;
        int arr = i >> 9;
        int rem = i & 511;
        int row = rem >> 3;
        int ch  = rem & 7;
        int gr  = (q0 + row < bcnt) ? (boff + q0 + row) : boff;
        const __half* src = (arr ? Ql : Qh) + (size_t)gr * D_MODEL + hcol + ch * 8;
        cp_async16(smb + ((arr ? OFF_QL : OFF_QH) + row * AROW + ch * 8) * 2, src);
    }
    cp_commit();

    auto load_kv = [&](int kv0, int st) {
        #pragma unroll
        for (int t = 0; t < 12; t++) {
            int i   = tid + t * 128;
            int arr = i / 512;
            int rem = i & 511;
            int row = rem >> 3;
            int ch  = rem & 7;
            int gr  = (kv0 + row < bcnt) ? (boff + kv0 + row) : boff;
            const __half* base = (arr == 0) ? Kh : (arr == 1 ? Kl : V);
            cp_async16(smb + (OFF_KV(st, arr) + row * AROW + ch * 8) * 2,
                       base + (size_t)gr * D_MODEL + hcol + ch * 8);
        }
        cp_commit();
    };

    float o[8][4];
    #pragma unroll
    for (int nt = 0; nt < 8; nt++)
        #pragma unroll
        for (int r = 0; r < 4; r++) o[nt][r] = 0.0f;
    float m0r = -1e30f, m1r = -1e30f, l0r = 0.0f, l1r = 0.0f;

    const int nit = (bcnt + 63) >> 6;
    load_kv(0, 0);

    for (int it = 0; it < nit; it++) {
        if (it + 1 < nit) { load_kv((it + 1) << 6, (it + 1) & 1); cp_wait<1>(); }
        else              { cp_wait<0>(); }
        __syncthreads();

        const int st  = it & 1;
        const int kv0 = it << 6;
        const char* pQH = smc + OFF_QH * 2;
        const char* pQL = smc + OFF_QL * 2;
        const char* pKH = smc + OFF_KV(st, 0) * 2;
        const char* pKL = smc + OFF_KV(st, 1) * 2;
        const uint32_t pV = smb + OFF_KV(st, 2) * 2;

        float sacc[8][4];
        #pragma unroll
        for (int nt = 0; nt < 8; nt++)
            #pragma unroll
            for (int r = 0; r < 4; r++) sacc[nt][r] = 0.0f;

        #pragma unroll
        for (int kt = 0; kt < 4; kt++) {
            const int kc = kt * 16 + t4 * 2;
            uint32_t ah[4], al[4];
            {
                int r0 = (wr + g) * AROW + kc;
                int r1 = (wr + g + 8) * AROW + kc;
                ah[0] = *(const uint32_t*)(pQH + r0 * 2);
                ah[1] = *(const uint32_t*)(pQH + r1 * 2);
                ah[2] = *(const uint32_t*)(pQH + (r0 + 8) * 2);
                ah[3] = *(const uint32_t*)(pQH + (r1 + 8) * 2);
                al[0] = *(const uint32_t*)(pQL + r0 * 2);
                al[1] = *(const uint32_t*)(pQL + r1 * 2);
                al[2] = *(const uint32_t*)(pQL + (r0 + 8) * 2);
                al[3] = *(const uint32_t*)(pQL + (r1 + 8) * 2);
            }
            #pragma unroll
            for (int nt = 0; nt < 8; nt++) {
                int rk = (nt * 8 + g) * AROW + kc;
                uint32_t bh0 = *(const uint32_t*)(pKH + rk * 2);
                uint32_t bh1 = *(const uint32_t*)(pKH + (rk + 8) * 2);
                uint32_t bl0 = *(const uint32_t*)(pKL + rk * 2);
                uint32_t bl1 = *(const uint32_t*)(pKL + (rk + 8) * 2);
                mma_fp16(sacc[nt], ah, bh0, bh1);
                mma_fp16(sacc[nt], ah, bl0, bl1);
                mma_fp16(sacc[nt], al, bh0, bh1);
            }
        }

        float mx0 = -1e30f, mx1 = -1e30f;
        #pragma unroll
        for (int nt = 0; nt < 8; nt++) {
            int c0 = kv0 + nt * 8 + 2 * t4;
            if (c0 >= bcnt)     { sacc[nt][0] = NEG_BIG; sacc[nt][2] = NEG_BIG; }
            if (c0 + 1 >= bcnt) { sacc[nt][1] = NEG_BIG; sacc[nt][3] = NEG_BIG; }
            mx0 = fmaxf(mx0, fmaxf(sacc[nt][0], sacc[nt][1]));
            mx1 = fmaxf(mx1, fmaxf(sacc[nt][2], sacc[nt][3]));
        }
        mx0 = fmaxf(mx0, __shfl_xor_sync(0xffffffffu, mx0, 1));
        mx0 = fmaxf(mx0, __shfl_xor_sync(0xffffffffu, mx0, 2));
        mx1 = fmaxf(mx1, __shfl_xor_sync(0xffffffffu, mx1, 1));
        mx1 = fmaxf(mx1, __shfl_xor_sync(0xffffffffu, mx1, 2));

        float mn0 = fmaxf(m0r, mx0), mn1 = fmaxf(m1r, mx1);
        float al0 = __expf(m0r - mn0), al1 = __expf(m1r - mn1);
        float ls0 = 0.0f, ls1 = 0.0f;
        #pragma unroll
        for (int nt = 0; nt < 8; nt++) {
            sacc[nt][0] = __expf(sacc[nt][0] - mn0);
            sacc[nt][1] = __expf(sacc[nt][1] - mn0);
            sacc[nt][2] = __expf(sacc[nt][2] - mn1);
            sacc[nt][3] = __expf(sacc[nt][3] - mn1);
            ls0 += sacc[nt][0] + sacc[nt][1];
            ls1 += sacc[nt][2] + sacc[nt][3];
        }
        ls0 += __shfl_xor_sync(0xffffffffu, ls0, 1);
        ls0 += __shfl_xor_sync(0xffffffffu, ls0, 2);
        ls1 += __shfl_xor_sync(0xffffffffu, ls1, 1);
        ls1 += __shfl_xor_sync(0xffffffffu, ls1, 2);
        l0r = l0r * al0 + ls0;  m0r = mn0;
        l1r = l1r * al1 + ls1;  m1r = mn1;
        #pragma unroll
        for (int nt = 0; nt < 8; nt++) {
            o[nt][0] *= al0; o[nt][1] *= al0;
            o[nt][2] *= al1; o[nt][3] *= al1;
        }

        #pragma unroll
        for (int kt = 0; kt < 4; kt++) {
            uint32_t pa[4];
            pa[0] = pack_h(sacc[2 * kt][0],     sacc[2 * kt][1]);
            pa[1] = pack_h(sacc[2 * kt][2],     sacc[2 * kt][3]);
            pa[2] = pack_h(sacc[2 * kt + 1][0], sacc[2 * kt + 1][1]);
            pa[3] = pack_h(sacc[2 * kt + 1][2], sacc[2 * kt + 1][3]);
            #pragma unroll
            for (int ntp = 0; ntp < 4; ntp++) {
                int mat = lane >> 3, r = lane & 7;
                int vrow = kt * 16 + (mat & 1) * 8 + r;
                int vcol = ntp * 16 + (mat >> 1) * 8;
                uint32_t vb[4];
                ldmatrix_x4_trans(vb, pV + (vrow * AROW + vcol) * 2);
                mma_fp16(o[2 * ntp],     pa, vb[0], vb[1]);
                mma_fp16(o[2 * ntp + 1], pa, vb[2], vb[3]);
            }
        }
        __syncthreads();
    }

    float inv0 = 1.0f / l0r, inv1 = 1.0f / l1r;
    int row0 = q0 + wr + g, row1 = row0 + 8;
    #pragma unroll
    for (int nt = 0; nt < 8; nt++) {
        int col = (int)hcol + nt * 8 + 2 * t4;
        if (row0 < bcnt)
            *(uint32_t*)(ctx + (size_t)(boff + row0) * D_MODEL + col) =
                pack_h(o[nt][0] * inv0, o[nt][1] * inv0);
        if (row1 < bcnt)
            *(uint32_t*)(ctx + (size_t)(boff + row1) * D_MODEL + col) =
                pack_h(o[nt][2] * inv1, o[nt][3] * inv1);
    }
}

// ---------------------------------------------------------------------------
extern "C" void kernel_launch(void* const* d_in, const int* in_sizes, int n_in,
                              void* d_out, int out_size)
{
    (void)in_sizes; (void)n_in; (void)out_size;
    const float* x  = (const float*)d_in[0];
    const int*   pm = (const int*)  d_in[1];
    const float* Wq = (const float*)d_in[2];
    const float* bq = (const float*)d_in[3];
    const float* Wk = (const float*)d_in[4];
    const float* bk = (const float*)d_in[5];
    const float* Wv = (const float*)d_in[6];
    const float* bv = (const float*)d_in[7];
    const float* Wo = (const float*)d_in[8];
    const float* bo = (const float*)d_in[9];
    float* out = (float*)d_out;

    bf16 *xbh, *xbl, *wqkh, *wqkl;
    __half *xh16, *wv16, *wo16, *qh16, *ql16, *kh16, *kl16, *v16, *c16;
    cudaGetSymbolAddress((void**)&xbh, g_xbh);
    cudaGetSymbolAddress((void**)&xbl, g_xbl);
    cudaGetSymbolAddress((void**)&wqkh, g_wqk_h);
    cudaGetSymbolAddress((void**)&wqkl, g_wqk_l);
    cudaGetSymbolAddress((void**)&xh16, g_xh16);
    cudaGetSymbolAddress((void**)&wv16, g_wv16);
    cudaGetSymbolAddress((void**)&wo16, g_wo16);
    cudaGetSymbolAddress((void**)&qh16, g_qh16);
    cudaGetSymbolAddress((void**)&ql16, g_ql16);
    cudaGetSymbolAddress((void**)&kh16, g_kh16);
    cudaGetSymbolAddress((void**)&kl16, g_kl16);
    cudaGetSymbolAddress((void**)&v16, g_v16);
    cudaGetSymbolAddress((void**)&c16, g_c16);

    cudaFuncSetAttribute(gemm_qk_kernel,
                         cudaFuncAttributeMaxDynamicSharedMemorySize, QK_SMEM);
    cudaFuncSetAttribute(gemm_f16_kernel<0>,
                         cudaFuncAttributeMaxDynamicSharedMemorySize, F_SMEM);
    cudaFuncSetAttribute(gemm_f16_kernel<1>,
                         cudaFuncAttributeMaxDynamicSharedMemorySize, F_SMEM);
    cudaFuncSetAttribute(attn_mma_kernel,
                         cudaFuncAttributeMaxDynamicSharedMemorySize, ATTN_SMEM);

    const size_t WSZ = (size_t)D_MODEL * D_MODEL;
    const int n4 = MROWS * D_MODEL / 4;

    split_bf16_kernel<<<(n4 + 255) / 256, 256>>>(x, xbh, xbl, n4);
    tohalf_kernel<<<(n4 + 255) / 256, 256>>>(x, xh16, n4);
    build_idx_kernel<<<BATCH, 256>>>(pm);
    build_gidx_kernel<<<1, 256>>>();
    bias_fill_kernel<<<n4 / 256, 256>>>(bo, out);

    dim3 tgrid(D_MODEL / 32, D_MODEL / 32), tblk(32, 8);
    transpose_split_bf16_kernel<<<tgrid, tblk>>>(Wq, wqkh + 0 * WSZ, wqkl + 0 * WSZ);
    transpose_split_bf16_kernel<<<tgrid, tblk>>>(Wk, wqkh + 1 * WSZ, wqkl + 1 * WSZ);
    transpose_half_kernel<<<tgrid, tblk>>>(Wv, wv16);
    transpose_half_kernel<<<tgrid, tblk>>>(Wo, wo16);

    // Q,K projections: bf16 3-pass, fp16 hi/lo outputs directly
    dim3 qkgrid(D_MODEL / 128, MROWS / 128, 2);
    gemm_qk_kernel<<<qkgrid, 256, QK_SMEM>>>(xbh, xbl, wqkh, wqkl, bq, bk,
                                             qh16, ql16, kh16, kl16);

    // V projection: fp16 single-pass, fp16 output directly
    dim3 vgrid(D_MODEL / 128, MROWS / 128);
    gemm_f16_kernel<0><<<vgrid, 256, F_SMEM>>>(xh16, wv16, bv, v16, nullptr);

    // tensor-core attention, fp16 ctx output
    dim3 agrid(S_LEN / 64, NHEAD, BATCH);
    attn_mma_kernel<<<agrid, 128, ATTN_SMEM>>>(qh16, ql16, kh16, kl16, v16, c16);

    // O projection: fp16 single-pass, scatter fp32 out
    gemm_f16_kernel<1><<<vgrid, 256, F_SMEM>>>(c16, wo16, bo, nullptr, out);
}

// round 13
// speedup vs baseline: 8.6001x; 1.0549x over previous
#include <cuda_runtime.h>
#include <cuda_bf16.h>
#include <cuda_fp16.h>
#include <math.h>
#include <stdint.h>

#define BATCH   4
#define S_LEN   2048
#define D_MODEL 1024
#define NHEAD   16
#define HDIM    64
#define MROWS   (BATCH * S_LEN)

#define NEG_BIG (-1.0e9f)
typedef __nv_bfloat16 bf16;

// ---------------------------------------------------------------------------
// Scratch
// ---------------------------------------------------------------------------
__device__ __align__(1024) bf16   g_xbh[(size_t)MROWS * D_MODEL];
__device__ __align__(1024) bf16   g_xbl[(size_t)MROWS * D_MODEL];
__device__ __align__(1024) __half g_xh16[(size_t)MROWS * D_MODEL];
__device__ __align__(1024) __half g_qh16[(size_t)MROWS * D_MODEL];
__device__ __align__(1024) __half g_ql16[(size_t)MROWS * D_MODEL];
__device__ __align__(1024) __half g_kh16[(size_t)MROWS * D_MODEL];
__device__ __align__(1024) __half g_kl16[(size_t)MROWS * D_MODEL];
__device__ __align__(1024) __half g_v16[(size_t)MROWS * D_MODEL];
__device__ __align__(1024) __half g_c16[(size_t)MROWS * D_MODEL];
__device__ __align__(1024) bf16   g_wqk_h[2][(size_t)D_MODEL * D_MODEL];
__device__ __align__(1024) bf16   g_wqk_l[2][(size_t)D_MODEL * D_MODEL];
__device__ __align__(1024) __half g_wv16[(size_t)D_MODEL * D_MODEL];
__device__ __align__(1024) __half g_wo16[(size_t)D_MODEL * D_MODEL];

__device__ int g_idx[BATCH][S_LEN];
__device__ int g_cnt[BATCH];
__device__ int g_off[BATCH + 1];
__device__ int g_gidx[MROWS];

// ---------------------------------------------------------------------------
// Helpers
// ---------------------------------------------------------------------------
__device__ __forceinline__ uint32_t smem_u32(const void* p) {
    uint32_t a;
    asm("{ .reg .u64 t; cvta.to.shared.u64 t, %1; cvt.u32.u64 %0, t; }"
        : "=r"(a) : "l"(p));
    return a;
}
__device__ __forceinline__ void cp_async16(uint32_t saddr, const void* gptr) {
    asm volatile("cp.async.cg.shared.global [%0], [%1], 16;"
                 :: "r"(saddr), "l"(__cvta_generic_to_global(gptr)));
}
__device__ __forceinline__ void cp_commit() {
    asm volatile("cp.async.commit_group;" ::: "memory");
}
template <int N>
__device__ __forceinline__ void cp_wait() {
    asm volatile("cp.async.wait_group %0;" :: "n"(N) : "memory");
}
__device__ __forceinline__ void mma_bf16(float* d, const uint32_t* a,
                                         uint32_t b0, uint32_t b1) {
    asm volatile(
        "mma.sync.aligned.m16n8k16.row.col.f32.bf16.bf16.f32 "
        "{%0,%1,%2,%3}, {%4,%5,%6,%7}, {%8,%9}, {%0,%1,%2,%3};"
        : "+f"(d[0]), "+f"(d[1]), "+f"(d[2]), "+f"(d[3])
        : "r"(a[0]), "r"(a[1]), "r"(a[2]), "r"(a[3]), "r"(b0), "r"(b1));
}
__device__ __forceinline__ void mma_fp16(float* d, const uint32_t* a,
                                         uint32_t b0, uint32_t b1) {
    asm volatile(
        "mma.sync.aligned.m16n8k16.row.col.f32.f16.f16.f32 "
        "{%0,%1,%2,%3}, {%4,%5,%6,%7}, {%8,%9}, {%0,%1,%2,%3};"
        : "+f"(d[0]), "+f"(d[1]), "+f"(d[2]), "+f"(d[3])
        : "r"(a[0]), "r"(a[1]), "r"(a[2]), "r"(a[3]), "r"(b0), "r"(b1));
}
__device__ __forceinline__ void ldsm_x4(uint32_t* r, uint32_t addr) {
    asm volatile(
        "ldmatrix.sync.aligned.m8n8.x4.shared.b16 {%0,%1,%2,%3}, [%4];"
        : "=r"(r[0]), "=r"(r[1]), "=r"(r[2]), "=r"(r[3]) : "r"(addr));
}
__device__ __forceinline__ void ldmatrix_x4_trans(uint32_t* r, uint32_t addr) {
    asm volatile(
        "ldmatrix.sync.aligned.m8n8.x4.trans.shared.b16 {%0,%1,%2,%3}, [%4];"
        : "=r"(r[0]), "=r"(r[1]), "=r"(r[2]), "=r"(r[3]) : "r"(addr));
}
__device__ __forceinline__ uint32_t pack_h(float a, float b) {
    __half2 t = __floats2half2_rn(a, b);
    return *(uint32_t*)&t;
}

// ---------------------------------------------------------------------------
// Prep kernels
// ---------------------------------------------------------------------------
__global__ __launch_bounds__(256) void split_bf16_kernel(
    const float* __restrict__ in, bf16* __restrict__ hi,
    bf16* __restrict__ lo, int n4)
{
    int i = blockIdx.x * blockDim.x + threadIdx.x;
    if (i >= n4) return;
    float4 v = ((const float4*)in)[i];
    bf16 hx = __float2bfloat16(v.x), hy = __float2bfloat16(v.y);
    bf16 hz = __float2bfloat16(v.z), hw = __float2bfloat16(v.w);
    bf16 lx = __float2bfloat16(v.x - __bfloat162float(hx));
    bf16 ly = __float2bfloat16(v.y - __bfloat162float(hy));
    bf16 lz = __float2bfloat16(v.z - __bfloat162float(hz));
    bf16 lw = __float2bfloat16(v.w - __bfloat162float(hw));
    ((__nv_bfloat162*)hi)[2 * i + 0] = __nv_bfloat162(hx, hy);
    ((__nv_bfloat162*)hi)[2 * i + 1] = __nv_bfloat162(hz, hw);
    ((__nv_bfloat162*)lo)[2 * i + 0] = __nv_bfloat162(lx, ly);
    ((__nv_bfloat162*)lo)[2 * i + 1] = __nv_bfloat162(lz, lw);
}

__global__ __launch_bounds__(256) void tohalf_kernel(
    const float* __restrict__ in, __half* __restrict__ out, int n4)
{
    int i = blockIdx.x * blockDim.x + threadIdx.x;
    if (i >= n4) return;
    float4 v = ((const float4*)in)[i];
    ((__half2*)out)[2 * i + 0] = __floats2half2_rn(v.x, v.y);
    ((__half2*)out)[2 * i + 1] = __floats2half2_rn(v.z, v.w);
}

__global__ __launch_bounds__(256) void bias_fill_kernel(
    const float* __restrict__ bias, float* __restrict__ out)
{
    int i = blockIdx.x * blockDim.x + threadIdx.x;
    int c = (i & (D_MODEL / 4 - 1)) * 4;
    ((float4*)out)[i] = *(const float4*)(bias + c);
}

__global__ __launch_bounds__(256) void transpose_split_bf16_kernel(
    const float* __restrict__ W, bf16* __restrict__ Thi, bf16* __restrict__ Tlo)
{
    __shared__ float t[32][33];
    int tx = threadIdx.x, ty = threadIdx.y;
    int n0 = blockIdx.x * 32, k0 = blockIdx.y * 32;
    #pragma unroll
    for (int j = 0; j < 4; j++)
        t[ty + 8 * j][tx] = W[(size_t)(k0 + ty + 8 * j) * D_MODEL + n0 + tx];
    __syncthreads();
    #pragma unroll
    for (int j = 0; j < 4; j++) {
        float v = t[tx][ty + 8 * j];
        bf16 h = __float2bfloat16(v);
        bf16 l = __float2bfloat16(v - __bfloat162float(h));
        size_t o = (size_t)(n0 + ty + 8 * j) * D_MODEL + k0 + tx;
        Thi[o] = h;
        Tlo[o] = l;
    }
}

__global__ __launch_bounds__(256) void transpose_half_kernel(
    const float* __restrict__ W, __half* __restrict__ T)
{
    __shared__ float t[32][33];
    int tx = threadIdx.x, ty = threadIdx.y;
    int n0 = blockIdx.x * 32, k0 = blockIdx.y * 32;
    #pragma unroll
    for (int j = 0; j < 4; j++)
        t[ty + 8 * j][tx] = W[(size_t)(k0 + ty + 8 * j) * D_MODEL + n0 + tx];
    __syncthreads();
    #pragma unroll
    for (int j = 0; j < 4; j++)
        T[(size_t)(n0 + ty + 8 * j) * D_MODEL + k0 + tx] =
            __float2half_rn(t[tx][ty + 8 * j]);
}

__global__ __launch_bounds__(256) void build_idx_kernel(const int* __restrict__ mask) {
    __shared__ int part[256];
    int b = blockIdx.x, t = threadIdx.x;
    const int* m = mask + (size_t)b * S_LEN;
    int loc[8], s = 0;
    #pragma unroll
    for (int j = 0; j < 8; j++) { loc[j] = (m[t * 8 + j] != 0); s += loc[j]; }
    part[t] = s;
    __syncthreads();
    for (int off = 1; off < 256; off <<= 1) {
        int v = (t >= off) ? part[t - off] : 0;
        __syncthreads();
        part[t] += v;
        __syncthreads();
    }
    int p = part[t] - s;
    #pragma unroll
    for (int j = 0; j < 8; j++)
        if (loc[j]) g_idx[b][p++] = t * 8 + j;
    if (t == 255) g_cnt[b] = part[255];
}

__global__ __launch_bounds__(256) void build_gidx_kernel() {
    __shared__ int off[BATCH + 1];
    if (threadIdx.x == 0) {
        off[0] = 0;
        for (int b = 0; b < BATCH; b++) off[b + 1] = off[b] + g_cnt[b];
        for (int b = 0; b <= BATCH; b++) g_off[b] = off[b];
    }
    __syncthreads();
    for (int b = 0; b < BATCH; b++) {
        int c = g_cnt[b], o = off[b];
        for (int i = threadIdx.x; i < c; i += 256)
            g_gidx[o + i] = b * S_LEN + g_idx[b][i];
    }
}

// ---------------------------------------------------------------------------
#define ROWB    80
#define TILEB   (128 * ROWB)

// ========== Q,K GEMM: bf16 3-pass split, 2-stage, ldmatrix frags ===========
#define QK_STAGEB  (4 * TILEB)
#define QK_SMEM    (2 * QK_STAGEB + 512)

__global__ __launch_bounds__(256, 2) void gemm_qk_kernel(
    const bf16* __restrict__ Ahi, const bf16* __restrict__ Alo,
    const bf16* __restrict__ Whi_base, const bf16* __restrict__ Wlo_base,
    const float* __restrict__ bias0, const float* __restrict__ bias1,
    __half* __restrict__ Qh, __half* __restrict__ Ql,
    __half* __restrict__ Kh, __half* __restrict__ Kl)
{
    extern __shared__ __align__(128) char sm[];
    int* sidx = (int*)(sm + 2 * QK_STAGEB);
    const uint32_t smb = smem_u32(sm);

    const int cnt = g_off[BATCH];
    const int m0 = blockIdx.y * 128;
    if (m0 >= cnt) return;
    const int n0 = blockIdx.x * 128;
    const int z  = blockIdx.z;

    const bf16* Bhi = Whi_base + (size_t)z * D_MODEL * D_MODEL;
    const bf16* Blo = Wlo_base + (size_t)z * D_MODEL * D_MODEL;
    const float* bias = (z == 0 ? bias0 : bias1);
    __half* oh = (z == 0 ? Qh : Kh);
    __half* ol = (z == 0 ? Ql : Kl);

    const int tid  = threadIdx.x;
    const int lane = tid & 31;
    const int w    = tid >> 5;
    const int wm   = w & 1;
    const int wn   = w >> 1;
    const int g    = lane >> 2;
    const int t4   = lane & 3;

    // ldmatrix per-lane offsets
    const uint32_t aLane = (uint32_t)((lane & 15) * ROWB + (lane >> 4) * 16);
    const uint32_t bLane = (uint32_t)((((lane >> 4) & 1) * 8 + (lane & 7)) * ROWB
                                      + ((lane >> 3) & 1) * 16);

    if (tid < 128)
        sidx[tid] = (m0 + tid < cnt) ? g_gidx[m0 + tid] : g_gidx[0];
    __syncthreads();

    const bf16* gsrc[4] = {Ahi, Alo, Bhi, Blo};

    float acc[4][4][4];
    #pragma unroll
    for (int mt = 0; mt < 4; mt++)
        #pragma unroll
        for (int nt = 0; nt < 4; nt++)
            #pragma unroll
            for (int r = 0; r < 4; r++)
                acc[mt][nt][r] = 0.0f;

    auto load_stage = [&](int kc, int st) {
        char* base = sm + st * QK_STAGEB;
        #pragma unroll
        for (int t = 0; t < 8; t++) {
            const int tile = t >> 1;
            const int wi   = tid + (t & 1) * 256;
            const int row  = wi >> 2;
            const int ch   = wi & 3;
            int grow = (tile < 2) ? sidx[row] : (n0 + row);
            const bf16* src = gsrc[tile] + (size_t)grow * D_MODEL + kc * 32 + ch * 8;
            uint32_t dst = smem_u32(base + tile * TILEB + row * ROWB + ch * 16);
            cp_async16(dst, src);
        }
        cp_commit();
    };

    auto compute_stage = [&](int st) {
        const uint32_t base = smb + st * QK_STAGEB;
        const uint32_t pAh = base;
        const uint32_t pAl = base + TILEB;
        const uint32_t pBh = base + 2 * TILEB;
        const uint32_t pBl = base + 3 * TILEB;
        #pragma unroll
        for (int kk = 0; kk < 2; kk++) {
            const uint32_t cB = kk * 32;   // bytes (16 halfs)
            uint32_t b_h[4][2], b_l[4][2], a[4][4];
            #pragma unroll
            for (int ntp = 0; ntp < 2; ntp++) {
                uint32_t nb = (wn * 32 + ntp * 16) * ROWB + cB;
                uint32_t r4[4];
                ldsm_x4(r4, pBh + nb + bLane);
                b_h[2 * ntp][0] = r4[0]; b_h[2 * ntp][1] = r4[1];
                b_h[2 * ntp + 1][0] = r4[2]; b_h[2 * ntp + 1][1] = r4[3];
                ldsm_x4(r4, pBl + nb + bLane);
                b_l[2 * ntp][0] = r4[0]; b_l[2 * ntp][1] = r4[1];
                b_l[2 * ntp + 1][0] = r4[2]; b_l[2 * ntp + 1][1] = r4[3];
            }
            // hi-A pass: hh + hl
            #pragma unroll
            for (int mt = 0; mt < 4; mt++)
                ldsm_x4(a[mt], pAh + (wm * 64 + mt * 16) * ROWB + cB + aLane);
            #pragma unroll
            for (int mt = 0; mt < 4; mt++)
                #pragma unroll
                for (int nt = 0; nt < 4; nt++) {
                    mma_bf16(acc[mt][nt], a[mt], b_h[nt][0], b_h[nt][1]);
                    mma_bf16(acc[mt][nt], a[mt], b_l[nt][0], b_l[nt][1]);
                }
            // lo-A pass: lh (reuse a regs)
            #pragma unroll
            for (int mt = 0; mt < 4; mt++)
                ldsm_x4(a[mt], pAl + (wm * 64 + mt * 16) * ROWB + cB + aLane);
            #pragma unroll
            for (int mt = 0; mt < 4; mt++)
                #pragma unroll
                for (int nt = 0; nt < 4; nt++)
                    mma_bf16(acc[mt][nt], a[mt], b_h[nt][0], b_h[nt][1]);
        }
    };

    const int NIT = D_MODEL / 32;
    load_stage(0, 0);
    load_stage(1, 1);
    for (int it = 0; it < NIT; it++) {
        if (it + 1 < NIT) cp_wait<1>(); else cp_wait<0>();
        __syncthreads();
        compute_stage(it & 1);
        __syncthreads();
        if (it + 2 < NIT) load_stage(it + 2, it & 1);
    }

    #pragma unroll
    for (int mt = 0; mt < 4; mt++) {
        int rl = wm * 64 + mt * 16 + g;
        #pragma unroll
        for (int nt = 0; nt < 4; nt++) {
            int col = n0 + wn * 32 + nt * 8 + t4 * 2;
            float b0 = bias[col], b1 = bias[col + 1];
            float v00 = acc[mt][nt][0] + b0, v01 = acc[mt][nt][1] + b1;
            float v10 = acc[mt][nt][2] + b0, v11 = acc[mt][nt][3] + b1;
            if (m0 + rl < cnt) {
                size_t off = (size_t)(m0 + rl) * D_MODEL + col;
                __half h0 = __float2half_rn(v00), h1 = __float2half_rn(v01);
                *(uint32_t*)(oh + off) = pack_h(v00, v01);
                *(uint32_t*)(ol + off) = pack_h(v00 - __half2float(h0),
                                                v01 - __half2float(h1));
            }
            if (m0 + rl + 8 < cnt) {
                size_t off = (size_t)(m0 + rl + 8) * D_MODEL + col;
                __half h0 = __float2half_rn(v10), h1 = __float2half_rn(v11);
                *(uint32_t*)(oh + off) = pack_h(v10, v11);
                *(uint32_t*)(ol + off) = pack_h(v10 - __half2float(h0),
                                                v11 - __half2float(h1));
            }
        }
    }
}

// ========== fp16 single-pass GEMM, 3-stage, ldmatrix frags =================
#define F_STAGEB  (2 * TILEB)
#define F_NSTAGE  3
#define F_SMEM    (F_NSTAGE * F_STAGEB + 512)

template<int MODE>   // 0: V (gather A, fp16 out), 1: O (compacted A, fp32 scatter)
__global__ __launch_bounds__(256, 2) void gemm_f16_kernel(
    const __half* __restrict__ A, const __half* __restrict__ B,
    const float* __restrict__ bias,
    __half* __restrict__ Oh, float* __restrict__ Of)
{
    extern __shared__ __align__(128) char sm[];
    int* sidx = (int*)(sm + F_NSTAGE * F_STAGEB);
    const uint32_t smb = smem_u32(sm);

    const int cnt = g_off[BATCH];
    const int m0 = blockIdx.y * 128;
    if (m0 >= cnt) return;
    const int n0 = blockIdx.x * 128;

    const int tid  = threadIdx.x;
    const int lane = tid & 31;
    const int w    = tid >> 5;
    const int wm   = w & 1;
    const int wn   = w >> 1;
    const int g    = lane >> 2;
    const int t4   = lane & 3;

    const uint32_t aLane = (uint32_t)((lane & 15) * ROWB + (lane >> 4) * 16);
    const uint32_t bLane = (uint32_t)((((lane >> 4) & 1) * 8 + (lane & 7)) * ROWB
                                      + ((lane >> 3) & 1) * 16);

    if (tid < 128)
        sidx[tid] = (m0 + tid < cnt) ? g_gidx[m0 + tid] : g_gidx[0];
    __syncthreads();

    float acc[4][4][4];
    #pragma unroll
    for (int mt = 0; mt < 4; mt++)
        #pragma unroll
        for (int nt = 0; nt < 4; nt++)
            #pragma unroll
            for (int r = 0; r < 4; r++)
                acc[mt][nt][r] = 0.0f;

    auto load_stage = [&](int kc, int st) {
        char* base = sm + st * F_STAGEB;
        #pragma unroll
        for (int t = 0; t < 4; t++) {
            const int tile = t >> 1;
            const int wi   = tid + (t & 1) * 256;
            const int row  = wi >> 2;
            const int ch   = wi & 3;
            int grow;
            if (tile == 0) {
                if (MODE == 0) grow = sidx[row];
                else { int ar = m0 + row; grow = (ar < cnt) ? ar : m0; }
            } else grow = n0 + row;
            const __half* src = (tile == 0 ? A : B) +
                                (size_t)grow * D_MODEL + kc * 32 + ch * 8;
            uint32_t dst = smem_u32(base + tile * TILEB + row * ROWB + ch * 16);
            cp_async16(dst, src);
        }
        cp_commit();
    };

    auto compute_stage = [&](int st) {
        const uint32_t base = smb + st * F_STAGEB;
        const uint32_t pA = base;
        const uint32_t pB = base + TILEB;
        #pragma unroll
        for (int kk = 0; kk < 2; kk++) {
            const uint32_t cB = kk * 32;
            uint32_t b[4][2], a[4][4];
            #pragma unroll
            for (int ntp = 0; ntp < 2; ntp++) {
                uint32_t r4[4];
                ldsm_x4(r4, pB + (wn * 32 + ntp * 16) * ROWB + cB + bLane);
                b[2 * ntp][0] = r4[0]; b[2 * ntp][1] = r4[1];
                b[2 * ntp + 1][0] = r4[2]; b[2 * ntp + 1][1] = r4[3];
            }
            #pragma unroll
            for (int mt = 0; mt < 4; mt++)
                ldsm_x4(a[mt], pA + (wm * 64 + mt * 16) * ROWB + cB + aLane);
            #pragma unroll
            for (int mt = 0; mt < 4; mt++)
                #pragma unroll
                for (int nt = 0; nt < 4; nt++)
                    mma_fp16(acc[mt][nt], a[mt], b[nt][0], b[nt][1]);
        }
    };

    const int NIT = D_MODEL / 32;
    load_stage(0, 0);
    load_stage(1, 1);
    for (int it = 0; it < NIT; it++) {
        if (it + 2 < NIT) { load_stage(it + 2, (it + 2) % F_NSTAGE); cp_wait<2>(); }
        else if (it + 1 < NIT) { cp_wait<1>(); }
        else { cp_wait<0>(); }
        __syncthreads();
        compute_stage(it % F_NSTAGE);
        __syncthreads();
    }

    #pragma unroll
    for (int mt = 0; mt < 4; mt++) {
        int rl = wm * 64 + mt * 16 + g;
        #pragma unroll
        for (int nt = 0; nt < 4; nt++) {
            int col = n0 + wn * 32 + nt * 8 + t4 * 2;
            float b0 = bias[col], b1 = bias[col + 1];
            float v00 = acc[mt][nt][0] + b0, v01 = acc[mt][nt][1] + b1;
            float v10 = acc[mt][nt][2] + b0, v11 = acc[mt][nt][3] + b1;
            if (MODE == 0) {
                if (m0 + rl < cnt)
                    *(uint32_t*)(Oh + (size_t)(m0 + rl) * D_MODEL + col) =
                        pack_h(v00, v01);
                if (m0 + rl + 8 < cnt)
                    *(uint32_t*)(Oh + (size_t)(m0 + rl + 8) * D_MODEL + col) =
                        pack_h(v10, v11);
            } else {
                if (m0 + rl < cnt)
                    *(float2*)(Of + (size_t)sidx[rl] * D_MODEL + col) =
                        make_float2(v00, v01);
                if (m0 + rl + 8 < cnt)
                    *(float2*)(Of + (size_t)sidx[rl + 8] * D_MODEL + col) =
                        make_float2(v10, v11);
            }
        }
    }
}

// ---------------------------------------------------------------------------
// Tensor-core flash attention (R12 proven, unchanged).
// ---------------------------------------------------------------------------
#define AROW   72
#define QTILE  (64 * AROW)
#define OFF_QH 0
#define OFF_QL QTILE
#define OFF_KV(st, a) (2 * QTILE + ((st) * 3 + (a)) * QTILE)
#define ATTN_SMEM (8 * QTILE * 2)

__global__ __launch_bounds__(128) void attn_mma_kernel(
    const __half* __restrict__ Qh, const __half* __restrict__ Ql,
    const __half* __restrict__ Kh, const __half* __restrict__ Kl,
    const __half* __restrict__ V, __half* __restrict__ ctx)
{
    extern __shared__ __align__(128) char smc[];
    const uint32_t smb = smem_u32(smc);

    const int tid = threadIdx.x;
    const int b   = blockIdx.z;
    const int h   = blockIdx.y;
    const int bcnt = g_cnt[b];
    const int boff = g_off[b];
    const int q0   = blockIdx.x * 64;
    if (q0 >= bcnt) return;

    const int lane = tid & 31;
    const int w    = tid >> 5;
    const int g    = lane >> 2;
    const int t4   = lane & 3;
    const int wr   = w * 16;
    const size_t hcol = (size_t)h * HDIM;

    #pragma unroll
    for (int t = 0; t < 8; t++) {
        int i   = tid + t * 128;
        int arr = i >> 9;
        int rem = i & 511;
        int row = rem >> 3;
        int ch  = rem & 7;
        int gr  = (q0 + row < bcnt) ? (boff + q0 + row) : boff;
        const __half* src = (arr ? Ql : Qh) + (size_t)gr * D_MODEL + hcol + ch * 8;
        cp_async16(smb + ((arr ? OFF_QL : OFF_QH) + row * AROW + ch * 8) * 2, src);
    }
    cp_commit();

    auto load_kv = [&](int kv0, int st) {
        #pragma unroll
        for (int t = 0; t < 12; t++) {
            int i   = tid + t * 128;
            int arr = i / 512;
            int rem = i & 511;
            int row = rem >> 3;
            int ch  = rem & 7;
            int gr  = (kv0 + row < bcnt) ? (boff + kv0 + row) : boff;
            const __half* base = (arr == 0) ? Kh : (arr == 1 ? Kl : V);
            cp_async16(smb + (OFF_KV(st, arr) + row * AROW + ch * 8) * 2,
                       base + (size_t)gr * D_MODEL + hcol + ch * 8);
        }
        cp_commit();
    };

    float o[8][4];
    #pragma unroll
    for (int nt = 0; nt < 8; nt++)
        #pragma unroll
        for (int r = 0; r < 4; r++) o[nt][r] = 0.0f;
    float m0r = -1e30f, m1r = -1e30f, l0r = 0.0f, l1r = 0.0f;

    const int nit = (bcnt + 63) >> 6;
    load_kv(0, 0);

    for (int it = 0; it < nit; it++) {
        if (it + 1 < nit) { load_kv((it + 1) << 6, (it + 1) & 1); cp_wait<1>(); }
        else              { cp_wait<0>(); }
        __syncthreads();

        const int st  = it & 1;
        const int kv0 = it << 6;
        const char* pQH = smc + OFF_QH * 2;
        const char* pQL = smc + OFF_QL * 2;
        const char* pKH = smc + OFF_KV(st, 0) * 2;
        const char* pKL = smc + OFF_KV(st, 1) * 2;
        const uint32_t pV = smb + OFF_KV(st, 2) * 2;

        float sacc[8][4];
        #pragma unroll
        for (int nt = 0; nt < 8; nt++)
            #pragma unroll
            for (int r = 0; r < 4; r++) sacc[nt][r] = 0.0f;

        #pragma unroll
        for (int kt = 0; kt < 4; kt++) {
            const int kc = kt * 16 + t4 * 2;
            uint32_t ah[4], al[4];
            {
                int r0 = (wr + g) * AROW + kc;
                int r1 = (wr + g + 8) * AROW + kc;
                ah[0] = *(const uint32_t*)(pQH + r0 * 2);
                ah[1] = *(const uint32_t*)(pQH + r1 * 2);
                ah[2] = *(const uint32_t*)(pQH + (r0 + 8) * 2);
                ah[3] = *(const uint32_t*)(pQH + (r1 + 8) * 2);
                al[0] = *(const uint32_t*)(pQL + r0 * 2);
                al[1] = *(const uint32_t*)(pQL + r1 * 2);
                al[2] = *(const uint32_t*)(pQL + (r0 + 8) * 2);
                al[3] = *(const uint32_t*)(pQL + (r1 + 8) * 2);
            }
            #pragma unroll
            for (int nt = 0; nt < 8; nt++) {
                int rk = (nt * 8 + g) * AROW + kc;
                uint32_t bh0 = *(const uint32_t*)(pKH + rk * 2);
                uint32_t bh1 = *(const uint32_t*)(pKH + (rk + 8) * 2);
                uint32_t bl0 = *(const uint32_t*)(pKL + rk * 2);
                uint32_t bl1 = *(const uint32_t*)(pKL + (rk + 8) * 2);
                mma_fp16(sacc[nt], ah, bh0, bh1);
                mma_fp16(sacc[nt], ah, bl0, bl1);
                mma_fp16(sacc[nt], al, bh0, bh1);
            }
        }

        float mx0 = -1e30f, mx1 = -1e30f;
        #pragma unroll
        for (int nt = 0; nt < 8; nt++) {
            int c0 = kv0 + nt * 8 + 2 * t4;
            if (c0 >= bcnt)     { sacc[nt][0] = NEG_BIG; sacc[nt][2] = NEG_BIG; }
            if (c0 + 1 >= bcnt) { sacc[nt][1] = NEG_BIG; sacc[nt][3] = NEG_BIG; }
            mx0 = fmaxf(mx0, fmaxf(sacc[nt][0], sacc[nt][1]));
            mx1 = fmaxf(mx1, fmaxf(sacc[nt][2], sacc[nt][3]));
        }
        mx0 = fmaxf(mx0, __shfl_xor_sync(0xffffffffu, mx0, 1));
        mx0 = fmaxf(mx0, __shfl_xor_sync(0xffffffffu, mx0, 2));
        mx1 = fmaxf(mx1, __shfl_xor_sync(0xffffffffu, mx1, 1));
        mx1 = fmaxf(mx1, __shfl_xor_sync(0xffffffffu, mx1, 2));

        float mn0 = fmaxf(m0r, mx0), mn1 = fmaxf(m1r, mx1);
        float al0 = __expf(m0r - mn0), al1 = __expf(m1r - mn1);
        float ls0 = 0.0f, ls1 = 0.0f;
        #pragma unroll
        for (int nt = 0; nt < 8; nt++) {
            sacc[nt][0] = __expf(sacc[nt][0] - mn0);
            sacc[nt][1] = __expf(sacc[nt][1] - mn0);
            sacc[nt][2] = __expf(sacc[nt][2] - mn1);
            sacc[nt][3] = __expf(sacc[nt][3] - mn1);
            ls0 += sacc[nt][0] + sacc[nt][1];
            ls1 += sacc[nt][2] + sacc[nt][3];
        }
        ls0 += __shfl_xor_sync(0xffffffffu, ls0, 1);
        ls0 += __shfl_xor_sync(0xffffffffu, ls0, 2);
        ls1 += __shfl_xor_sync(0xffffffffu, ls1, 1);
        ls1 += __shfl_xor_sync(0xffffffffu, ls1, 2);
        l0r = l0r * al0 + ls0;  m0r = mn0;
        l1r = l1r * al1 + ls1;  m1r = mn1;
        #pragma unroll
        for (int nt = 0; nt < 8; nt++) {
            o[nt][0] *= al0; o[nt][1] *= al0;
            o[nt][2] *= al1; o[nt][3] *= al1;
        }

        #pragma unroll
        for (int kt = 0; kt < 4; kt++) {
            uint32_t pa[4];
            pa[0] = pack_h(sacc[2 * kt][0],     sacc[2 * kt][1]);
            pa[1] = pack_h(sacc[2 * kt][2],     sacc[2 * kt][3]);
            pa[2] = pack_h(sacc[2 * kt + 1][0], sacc[2 * kt + 1][1]);
            pa[3] = pack_h(sacc[2 * kt + 1][2], sacc[2 * kt + 1][3]);
            #pragma unroll
            for (int ntp = 0; ntp < 4; ntp++) {
                int mat = lane >> 3, r = lane & 7;
                int vrow = kt * 16 + (mat & 1) * 8 + r;
                int vcol = ntp * 16 + (mat >> 1) * 8;
                uint32_t vb[4];
                ldmatrix_x4_trans(vb, pV + (vrow * AROW + vcol) * 2);
                mma_fp16(o[2 * ntp],     pa, vb[0], vb[1]);
                mma_fp16(o[2 * ntp + 1], pa, vb[2], vb[3]);
            }
        }
        __syncthreads();
    }

    float inv0 = 1.0f / l0r, inv1 = 1.0f / l1r;
    int row0 = q0 + wr + g, row1 = row0 + 8;
    #pragma unroll
    for (int nt = 0; nt < 8; nt++) {
        int col = (int)hcol + nt * 8 + 2 * t4;
        if (row0 < bcnt)
            *(uint32_t*)(ctx + (size_t)(boff + row0) * D_MODEL + col) =
                pack_h(o[nt][0] * inv0, o[nt][1] * inv0);
        if (row1 < bcnt)
            *(uint32_t*)(ctx + (size_t)(boff + row1) * D_MODEL + col) =
                pack_h(o[nt][2] * inv1, o[nt][3] * inv1);
    }
}

// ---------------------------------------------------------------------------
extern "C" void kernel_launch(void* const* d_in, const int* in_sizes, int n_in,
                              void* d_out, int out_size)
{
    (void)in_sizes; (void)n_in; (void)out_size;
    const float* x  = (const float*)d_in[0];
    const int*   pm = (const int*)  d_in[1];
    const float* Wq = (const float*)d_in[2];
    const float* bq = (const float*)d_in[3];
    const float* Wk = (const float*)d_in[4];
    const float* bk = (const float*)d_in[5];
    const float* Wv = (const float*)d_in[6];
    const float* bv = (const float*)d_in[7];
    const float* Wo = (const float*)d_in[8];
    const float* bo = (const float*)d_in[9];
    float* out = (float*)d_out;

    bf16 *xbh, *xbl, *wqkh, *wqkl;
    __half *xh16, *wv16, *wo16, *qh16, *ql16, *kh16, *kl16, *v16, *c16;
    cudaGetSymbolAddress((void**)&xbh, g_xbh);
    cudaGetSymbolAddress((void**)&xbl, g_xbl);
    cudaGetSymbolAddress((void**)&wqkh, g_wqk_h);
    cudaGetSymbolAddress((void**)&wqkl, g_wqk_l);
    cudaGetSymbolAddress((void**)&xh16, g_xh16);
    cudaGetSymbolAddress((void**)&wv16, g_wv16);
    cudaGetSymbolAddress((void**)&wo16, g_wo16);
    cudaGetSymbolAddress((void**)&qh16, g_qh16);
    cudaGetSymbolAddress((void**)&ql16, g_ql16);
    cudaGetSymbolAddress((void**)&kh16, g_kh16);
    cudaGetSymbolAddress((void**)&kl16, g_kl16);
    cudaGetSymbolAddress((void**)&v16, g_v16);
    cudaGetSymbolAddress((void**)&c16, g_c16);

    cudaFuncSetAttribute(gemm_qk_kernel,
                         cudaFuncAttributeMaxDynamicSharedMemorySize, QK_SMEM);
    cudaFuncSetAttribute(gemm_f16_kernel<0>,
                         cudaFuncAttributeMaxDynamicSharedMemorySize, F_SMEM);
    cudaFuncSetAttribute(gemm_f16_kernel<1>,
                         cudaFuncAttributeMaxDynamicSharedMemorySize, F_SMEM);
    cudaFuncSetAttribute(attn_mma_kernel,
                         cudaFuncAttributeMaxDynamicSharedMemorySize, ATTN_SMEM);

    const size_t WSZ = (size_t)D_MODEL * D_MODEL;
    const int n4 = MROWS * D_MODEL / 4;

    split_bf16_kernel<<<(n4 + 255) / 256, 256>>>(x, xbh, xbl, n4);
    tohalf_kernel<<<(n4 + 255) / 256, 256>>>(x, xh16, n4);
    build_idx_kernel<<<BATCH, 256>>>(pm);
    build_gidx_kernel<<<1, 256>>>();
    bias_fill_kernel<<<n4 / 256, 256>>>(bo, out);

    dim3 tgrid(D_MODEL / 32, D_MODEL / 32), tblk(32, 8);
    transpose_split_bf16_kernel<<<tgrid, tblk>>>(Wq, wqkh + 0 * WSZ, wqkl + 0 * WSZ);
    transpose_split_bf16_kernel<<<tgrid, tblk>>>(Wk, wqkh + 1 * WSZ, wqkl + 1 * WSZ);
    transpose_half_kernel<<<tgrid, tblk>>>(Wv, wv16);
    transpose_half_kernel<<<tgrid, tblk>>>(Wo, wo16);

    // Q,K projections
    dim3 qkgrid(D_MODEL / 128, MROWS / 128, 2);
    gemm_qk_kernel<<<qkgrid, 256, QK_SMEM>>>(xbh, xbl, wqkh, wqkl, bq, bk,
                                             qh16, ql16, kh16, kl16);

    // V projection
    dim3 vgrid(D_MODEL / 128, MROWS / 128);
    gemm_f16_kernel<0><<<vgrid, 256, F_SMEM>>>(xh16, wv16, bv, v16, nullptr);

    // attention
    dim3 agrid(S_LEN / 64, NHEAD, BATCH);
    attn_mma_kernel<<<agrid, 128, ATTN_SMEM>>>(qh16, ql16, kh16, kl16, v16, c16);

    // O projection
    gemm_f16_kernel<1><<<vgrid, 256, F_SMEM>>>(c16, wo16, bo, nullptr, out);
}

// round 14
// speedup vs baseline: 8.8367x; 1.0275x over previous
#include <cuda_runtime.h>
#include <cuda_bf16.h>
#include <cuda_fp16.h>
#include <math.h>
#include <stdint.h>

#define BATCH   4
#define S_LEN   2048
#define D_MODEL 1024
#define NHEAD   16
#define HDIM    64
#define MROWS   (BATCH * S_LEN)

#define NEG_BIG (-1.0e9f)
typedef __nv_bfloat16 bf16;

// ---------------------------------------------------------------------------
// Scratch
// ---------------------------------------------------------------------------
__device__ __align__(1024) bf16   g_xbh[(size_t)MROWS * D_MODEL];
__device__ __align__(1024) bf16   g_xbl[(size_t)MROWS * D_MODEL];
__device__ __align__(1024) __half g_xh16[(size_t)MROWS * D_MODEL];
__device__ __align__(1024) __half g_qh16[(size_t)MROWS * D_MODEL];
__device__ __align__(1024) __half g_ql16[(size_t)MROWS * D_MODEL];
__device__ __align__(1024) __half g_kh16[(size_t)MROWS * D_MODEL];
__device__ __align__(1024) __half g_kl16[(size_t)MROWS * D_MODEL];
__device__ __align__(1024) __half g_v16[(size_t)MROWS * D_MODEL];
__device__ __align__(1024) __half g_c16[(size_t)MROWS * D_MODEL];
__device__ __align__(1024) bf16   g_wqk_h[2][(size_t)D_MODEL * D_MODEL];
__device__ __align__(1024) bf16   g_wqk_l[2][(size_t)D_MODEL * D_MODEL];
__device__ __align__(1024) __half g_wv16[(size_t)D_MODEL * D_MODEL];
__device__ __align__(1024) __half g_wo16[(size_t)D_MODEL * D_MODEL];

__device__ int g_idx[BATCH][S_LEN];
__device__ int g_cnt[BATCH];
__device__ int g_off[BATCH + 1];
__device__ int g_gidx[MROWS];

// ---------------------------------------------------------------------------
// Helpers
// ---------------------------------------------------------------------------
__device__ __forceinline__ uint32_t smem_u32(const void* p) {
    uint32_t a;
    asm("{ .reg .u64 t; cvta.to.shared.u64 t, %1; cvt.u32.u64 %0, t; }"
        : "=r"(a) : "l"(p));
    return a;
}
__device__ __forceinline__ void cp_async16(uint32_t saddr, const void* gptr) {
    asm volatile("cp.async.cg.shared.global [%0], [%1], 16;"
                 :: "r"(saddr), "l"(__cvta_generic_to_global(gptr)));
}
__device__ __forceinline__ void cp_commit() {
    asm volatile("cp.async.commit_group;" ::: "memory");
}
template <int N>
__device__ __forceinline__ void cp_wait() {
    asm volatile("cp.async.wait_group %0;" :: "n"(N) : "memory");
}
__device__ __forceinline__ void mma_bf16(float* d, const uint32_t* a,
                                         uint32_t b0, uint32_t b1) {
    asm volatile(
        "mma.sync.aligned.m16n8k16.row.col.f32.bf16.bf16.f32 "
        "{%0,%1,%2,%3}, {%4,%5,%6,%7}, {%8,%9}, {%0,%1,%2,%3};"
        : "+f"(d[0]), "+f"(d[1]), "+f"(d[2]), "+f"(d[3])
        : "r"(a[0]), "r"(a[1]), "r"(a[2]), "r"(a[3]), "r"(b0), "r"(b1));
}
__device__ __forceinline__ void mma_fp16(float* d, const uint32_t* a,
                                         uint32_t b0, uint32_t b1) {
    asm volatile(
        "mma.sync.aligned.m16n8k16.row.col.f32.f16.f16.f32 "
        "{%0,%1,%2,%3}, {%4,%5,%6,%7}, {%8,%9}, {%0,%1,%2,%3};"
        : "+f"(d[0]), "+f"(d[1]), "+f"(d[2]), "+f"(d[3])
        : "r"(a[0]), "r"(a[1]), "r"(a[2]), "r"(a[3]), "r"(b0), "r"(b1));
}
__device__ __forceinline__ void ldsm_x4(uint32_t* r, uint32_t addr) {
    asm volatile(
        "ldmatrix.sync.aligned.m8n8.x4.shared.b16 {%0,%1,%2,%3}, [%4];"
        : "=r"(r[0]), "=r"(r[1]), "=r"(r[2]), "=r"(r[3]) : "r"(addr));
}
__device__ __forceinline__ void ldmatrix_x4_trans(uint32_t* r, uint32_t addr) {
    asm volatile(
        "ldmatrix.sync.aligned.m8n8.x4.trans.shared.b16 {%0,%1,%2,%3}, [%4];"
        : "=r"(r[0]), "=r"(r[1]), "=r"(r[2]), "=r"(r[3]) : "r"(addr));
}
__device__ __forceinline__ uint32_t pack_h(float a, float b) {
    __half2 t = __floats2half2_rn(a, b);
    return *(uint32_t*)&t;
}

// ---------------------------------------------------------------------------
// Prep kernels
// ---------------------------------------------------------------------------
// x -> bf16 hi/lo + fp16, one read
__global__ __launch_bounds__(256) void split_x_kernel(
    const float* __restrict__ in, bf16* __restrict__ hi,
    bf16* __restrict__ lo, __half* __restrict__ h16, int n4)
{
    int i = blockIdx.x * blockDim.x + threadIdx.x;
    if (i >= n4) return;
    float4 v = ((const float4*)in)[i];
    bf16 hx = __float2bfloat16(v.x), hy = __float2bfloat16(v.y);
    bf16 hz = __float2bfloat16(v.z), hw = __float2bfloat16(v.w);
    bf16 lx = __float2bfloat16(v.x - __bfloat162float(hx));
    bf16 ly = __float2bfloat16(v.y - __bfloat162float(hy));
    bf16 lz = __float2bfloat16(v.z - __bfloat162float(hz));
    bf16 lw = __float2bfloat16(v.w - __bfloat162float(hw));
    ((__nv_bfloat162*)hi)[2 * i + 0] = __nv_bfloat162(hx, hy);
    ((__nv_bfloat162*)hi)[2 * i + 1] = __nv_bfloat162(hz, hw);
    ((__nv_bfloat162*)lo)[2 * i + 0] = __nv_bfloat162(lx, ly);
    ((__nv_bfloat162*)lo)[2 * i + 1] = __nv_bfloat162(lz, lw);
    ((__half2*)h16)[2 * i + 0] = __floats2half2_rn(v.x, v.y);
    ((__half2*)h16)[2 * i + 1] = __floats2half2_rn(v.z, v.w);
}

__global__ __launch_bounds__(256) void bias_fill_kernel(
    const float* __restrict__ bias, float* __restrict__ out)
{
    int i = blockIdx.x * blockDim.x + threadIdx.x;
    int c = (i & (D_MODEL / 4 - 1)) * 4;
    ((float4*)out)[i] = *(const float4*)(bias + c);
}

// All 4 weight transposes in one launch; z picks source/dest/format.
__global__ __launch_bounds__(256) void transpose_all_kernel(
    const float* __restrict__ Wq, const float* __restrict__ Wk,
    const float* __restrict__ Wv, const float* __restrict__ Wo,
    bf16* __restrict__ Th0, bf16* __restrict__ Tl0,
    bf16* __restrict__ Th1, bf16* __restrict__ Tl1,
    __half* __restrict__ Tv, __half* __restrict__ To)
{
    __shared__ float t[32][33];
    int z = blockIdx.z;
    const float* W = (z == 0) ? Wq : (z == 1) ? Wk : (z == 2) ? Wv : Wo;
    int tx = threadIdx.x, ty = threadIdx.y;
    int n0 = blockIdx.x * 32, k0 = blockIdx.y * 32;
    #pragma unroll
    for (int j = 0; j < 4; j++)
        t[ty + 8 * j][tx] = W[(size_t)(k0 + ty + 8 * j) * D_MODEL + n0 + tx];
    __syncthreads();
    if (z < 2) {
        bf16* Th = (z == 0) ? Th0 : Th1;
        bf16* Tl = (z == 0) ? Tl0 : Tl1;
        #pragma unroll
        for (int j = 0; j < 4; j++) {
            float v = t[tx][ty + 8 * j];
            bf16 h = __float2bfloat16(v);
            bf16 l = __float2bfloat16(v - __bfloat162float(h));
            size_t o = (size_t)(n0 + ty + 8 * j) * D_MODEL + k0 + tx;
            Th[o] = h;
            Tl[o] = l;
        }
    } else {
        __half* T = (z == 2) ? Tv : To;
        #pragma unroll
        for (int j = 0; j < 4; j++)
            T[(size_t)(n0 + ty + 8 * j) * D_MODEL + k0 + tx] =
                __float2half_rn(t[tx][ty + 8 * j]);
    }
}

__global__ __launch_bounds__(256) void build_idx_kernel(const int* __restrict__ mask) {
    __shared__ int part[256];
    int b = blockIdx.x, t = threadIdx.x;
    const int* m = mask + (size_t)b * S_LEN;
    int loc[8], s = 0;
    #pragma unroll
    for (int j = 0; j < 8; j++) { loc[j] = (m[t * 8 + j] != 0); s += loc[j]; }
    part[t] = s;
    __syncthreads();
    for (int off = 1; off < 256; off <<= 1) {
        int v = (t >= off) ? part[t - off] : 0;
        __syncthreads();
        part[t] += v;
        __syncthreads();
    }
    int p = part[t] - s;
    #pragma unroll
    for (int j = 0; j < 8; j++)
        if (loc[j]) g_idx[b][p++] = t * 8 + j;
    if (t == 255) g_cnt[b] = part[255];
}

__global__ __launch_bounds__(256) void build_gidx_kernel() {
    __shared__ int off[BATCH + 1];
    if (threadIdx.x == 0) {
        off[0] = 0;
        for (int b = 0; b < BATCH; b++) off[b + 1] = off[b] + g_cnt[b];
        for (int b = 0; b <= BATCH; b++) g_off[b] = off[b];
    }
    __syncthreads();
    for (int b = 0; b < BATCH; b++) {
        int c = g_cnt[b], o = off[b];
        for (int i = threadIdx.x; i < c; i += 256)
            g_gidx[o + i] = b * S_LEN + g_idx[b][i];
    }
}

// ---------------------------------------------------------------------------
#define ROWB    80
#define TILEB   (128 * ROWB)

// ========== Q,K GEMM: bf16 3-pass, 2-stage, register-lean sequencing =======
#define QK_STAGEB  (4 * TILEB)
#define QK_SMEM    (2 * QK_STAGEB + 512)

__global__ __launch_bounds__(256, 2) void gemm_qk_kernel(
    const bf16* __restrict__ Ahi, const bf16* __restrict__ Alo,
    const bf16* __restrict__ Whi_base, const bf16* __restrict__ Wlo_base,
    const float* __restrict__ bias0, const float* __restrict__ bias1,
    __half* __restrict__ Qh, __half* __restrict__ Ql,
    __half* __restrict__ Kh, __half* __restrict__ Kl)
{
    extern __shared__ __align__(128) char sm[];
    int* sidx = (int*)(sm + 2 * QK_STAGEB);
    const uint32_t smb = smem_u32(sm);

    const int cnt = g_off[BATCH];
    const int m0 = blockIdx.y * 128;
    if (m0 >= cnt) return;
    const int n0 = blockIdx.x * 128;
    const int z  = blockIdx.z;

    const bf16* Bhi = Whi_base + (size_t)z * D_MODEL * D_MODEL;
    const bf16* Blo = Wlo_base + (size_t)z * D_MODEL * D_MODEL;
    const float* bias = (z == 0 ? bias0 : bias1);
    __half* oh = (z == 0 ? Qh : Kh);
    __half* ol = (z == 0 ? Ql : Kl);

    const int tid  = threadIdx.x;
    const int lane = tid & 31;
    const int w    = tid >> 5;
    const int wm   = w & 1;
    const int wn   = w >> 1;
    const int g    = lane >> 2;
    const int t4   = lane & 3;

    const uint32_t aLane = (uint32_t)((lane & 15) * ROWB + (lane >> 4) * 16);
    const uint32_t bLane = (uint32_t)((((lane >> 4) & 1) * 8 + (lane & 7)) * ROWB
                                      + ((lane >> 3) & 1) * 16);

    if (tid < 128)
        sidx[tid] = (m0 + tid < cnt) ? g_gidx[m0 + tid] : g_gidx[0];
    __syncthreads();

    const bf16* gsrc[4] = {Ahi, Alo, Bhi, Blo};

    float acc[4][4][4];
    #pragma unroll
    for (int mt = 0; mt < 4; mt++)
        #pragma unroll
        for (int nt = 0; nt < 4; nt++)
            #pragma unroll
            for (int r = 0; r < 4; r++)
                acc[mt][nt][r] = 0.0f;

    auto load_stage = [&](int kc, int st) {
        char* base = sm + st * QK_STAGEB;
        #pragma unroll
        for (int t = 0; t < 8; t++) {
            const int tile = t >> 1;
            const int wi   = tid + (t & 1) * 256;
            const int row  = wi >> 2;
            const int ch   = wi & 3;
            int grow = (tile < 2) ? sidx[row] : (n0 + row);
            const bf16* src = gsrc[tile] + (size_t)grow * D_MODEL + kc * 32 + ch * 8;
            uint32_t dst = smem_u32(base + tile * TILEB + row * ROWB + ch * 16);
            cp_async16(dst, src);
        }
        cp_commit();
    };

    auto ldB = [&](uint32_t p, uint32_t cB, uint32_t (*b)[2]) {
        #pragma unroll
        for (int ntp = 0; ntp < 2; ntp++) {
            uint32_t r4[4];
            ldsm_x4(r4, p + (wn * 32 + ntp * 16) * ROWB + cB + bLane);
            b[2 * ntp][0] = r4[0]; b[2 * ntp][1] = r4[1];
            b[2 * ntp + 1][0] = r4[2]; b[2 * ntp + 1][1] = r4[3];
        }
    };
    auto ldA = [&](uint32_t p, uint32_t cB, uint32_t (*a)[4]) {
        #pragma unroll
        for (int mt = 0; mt < 4; mt++)
            ldsm_x4(a[mt], p + (wm * 64 + mt * 16) * ROWB + cB + aLane);
    };

    auto compute_stage = [&](int st) {
        const uint32_t base = smb + st * QK_STAGEB;
        const uint32_t pAh = base;
        const uint32_t pAl = base + TILEB;
        const uint32_t pBh = base + 2 * TILEB;
        const uint32_t pBl = base + 3 * TILEB;
        #pragma unroll
        for (int kk = 0; kk < 2; kk++) {
            const uint32_t cB = kk * 32;
            uint32_t a[4][4], b[4][2];
            // pass 1: Ah * Bh
            ldB(pBh, cB, b);
            ldA(pAh, cB, a);
            #pragma unroll
            for (int mt = 0; mt < 4; mt++)
                #pragma unroll
                for (int nt = 0; nt < 4; nt++)
                    mma_bf16(acc[mt][nt], a[mt], b[nt][0], b[nt][1]);
            // pass 2: Ah * Bl (overwrite b)
            ldB(pBl, cB, b);
            #pragma unroll
            for (int mt = 0; mt < 4; mt++)
                #pragma unroll
                for (int nt = 0; nt < 4; nt++)
                    mma_bf16(acc[mt][nt], a[mt], b[nt][0], b[nt][1]);
            // pass 3: Al * Bh (overwrite a, reload bh)
            ldA(pAl, cB, a);
            ldB(pBh, cB, b);
            #pragma unroll
            for (int mt = 0; mt < 4; mt++)
                #pragma unroll
                for (int nt = 0; nt < 4; nt++)
                    mma_bf16(acc[mt][nt], a[mt], b[nt][0], b[nt][1]);
        }
    };

    const int NIT = D_MODEL / 32;
    load_stage(0, 0);
    load_stage(1, 1);
    for (int it = 0; it < NIT; it++) {
        if (it + 1 < NIT) cp_wait<1>(); else cp_wait<0>();
        __syncthreads();
        compute_stage(it & 1);
        __syncthreads();
        if (it + 2 < NIT) load_stage(it + 2, it & 1);
    }

    #pragma unroll
    for (int mt = 0; mt < 4; mt++) {
        int rl = wm * 64 + mt * 16 + g;
        #pragma unroll
        for (int nt = 0; nt < 4; nt++) {
            int col = n0 + wn * 32 + nt * 8 + t4 * 2;
            float b0 = bias[col], b1 = bias[col + 1];
            float v00 = acc[mt][nt][0] + b0, v01 = acc[mt][nt][1] + b1;
            float v10 = acc[mt][nt][2] + b0, v11 = acc[mt][nt][3] + b1;
            if (m0 + rl < cnt) {
                size_t off = (size_t)(m0 + rl) * D_MODEL + col;
                __half h0 = __float2half_rn(v00), h1 = __float2half_rn(v01);
                *(uint32_t*)(oh + off) = pack_h(v00, v01);
                *(uint32_t*)(ol + off) = pack_h(v00 - __half2float(h0),
                                                v01 - __half2float(h1));
            }
            if (m0 + rl + 8 < cnt) {
                size_t off = (size_t)(m0 + rl + 8) * D_MODEL + col;
                __half h0 = __float2half_rn(v10), h1 = __float2half_rn(v11);
                *(uint32_t*)(oh + off) = pack_h(v10, v11);
                *(uint32_t*)(ol + off) = pack_h(v10 - __half2float(h0),
                                                v11 - __half2float(h1));
            }
        }
    }
}

// ========== fp16 single-pass GEMM, 3-stage, ldmatrix frags =================
#define F_STAGEB  (2 * TILEB)
#define F_NSTAGE  3
#define F_SMEM    (F_NSTAGE * F_STAGEB + 512)

template<int MODE>   // 0: V (gather A, fp16 out), 1: O (compacted A, fp32 scatter)
__global__ __launch_bounds__(256, 2) void gemm_f16_kernel(
    const __half* __restrict__ A, const __half* __restrict__ B,
    const float* __restrict__ bias,
    __half* __restrict__ Oh, float* __restrict__ Of)
{
    extern __shared__ __align__(128) char sm[];
    int* sidx = (int*)(sm + F_NSTAGE * F_STAGEB);
    const uint32_t smb = smem_u32(sm);

    const int cnt = g_off[BATCH];
    const int m0 = blockIdx.y * 128;
    if (m0 >= cnt) return;
    const int n0 = blockIdx.x * 128;

    const int tid  = threadIdx.x;
    const int lane = tid & 31;
    const int w    = tid >> 5;
    const int wm   = w & 1;
    const int wn   = w >> 1;
    const int g    = lane >> 2;
    const int t4   = lane & 3;

    const uint32_t aLane = (uint32_t)((lane & 15) * ROWB + (lane >> 4) * 16);
    const uint32_t bLane = (uint32_t)((((lane >> 4) & 1) * 8 + (lane & 7)) * ROWB
                                      + ((lane >> 3) & 1) * 16);

    if (tid < 128)
        sidx[tid] = (m0 + tid < cnt) ? g_gidx[m0 + tid] : g_gidx[0];
    __syncthreads();

    float acc[4][4][4];
    #pragma unroll
    for (int mt = 0; mt < 4; mt++)
        #pragma unroll
        for (int nt = 0; nt < 4; nt++)
            #pragma unroll
            for (int r = 0; r < 4; r++)
                acc[mt][nt][r] = 0.0f;

    auto load_stage = [&](int kc, int st) {
        char* base = sm + st * F_STAGEB;
        #pragma unroll
        for (int t = 0; t < 4; t++) {
            const int tile = t >> 1;
            const int wi   = tid + (t & 1) * 256;
            const int row  = wi >> 2;
            const int ch   = wi & 3;
            int grow;
            if (tile == 0) {
                if (MODE == 0) grow = sidx[row];
                else { int ar = m0 + row; grow = (ar < cnt) ? ar : m0; }
            } else grow = n0 + row;
            const __half* src = (tile == 0 ? A : B) +
                                (size_t)grow * D_MODEL + kc * 32 + ch * 8;
            uint32_t dst = smem_u32(base + tile * TILEB + row * ROWB + ch * 16);
            cp_async16(dst, src);
        }
        cp_commit();
    };

    auto compute_stage = [&](int st) {
        const uint32_t base = smb + st * F_STAGEB;
        const uint32_t pA = base;
        const uint32_t pB = base + TILEB;
        #pragma unroll
        for (int kk = 0; kk < 2; kk++) {
            const uint32_t cB = kk * 32;
            uint32_t b[4][2], a[4][4];
            #pragma unroll
            for (int ntp = 0; ntp < 2; ntp++) {
                uint32_t r4[4];
                ldsm_x4(r4, pB + (wn * 32 + ntp * 16) * ROWB + cB + bLane);
                b[2 * ntp][0] = r4[0]; b[2 * ntp][1] = r4[1];
                b[2 * ntp + 1][0] = r4[2]; b[2 * ntp + 1][1] = r4[3];
            }
            #pragma unroll
            for (int mt = 0; mt < 4; mt++)
                ldsm_x4(a[mt], pA + (wm * 64 + mt * 16) * ROWB + cB + aLane);
            #pragma unroll
            for (int mt = 0; mt < 4; mt++)
                #pragma unroll
                for (int nt = 0; nt < 4; nt++)
                    mma_fp16(acc[mt][nt], a[mt], b[nt][0], b[nt][1]);
        }
    };

    const int NIT = D_MODEL / 32;
    load_stage(0, 0);
    load_stage(1, 1);
    for (int it = 0; it < NIT; it++) {
        if (it + 2 < NIT) { load_stage(it + 2, (it + 2) % F_NSTAGE); cp_wait<2>(); }
        else if (it + 1 < NIT) { cp_wait<1>(); }
        else { cp_wait<0>(); }
        __syncthreads();
        compute_stage(it % F_NSTAGE);
        __syncthreads();
    }

    #pragma unroll
    for (int mt = 0; mt < 4; mt++) {
        int rl = wm * 64 + mt * 16 + g;
        #pragma unroll
        for (int nt = 0; nt < 4; nt++) {
            int col = n0 + wn * 32 + nt * 8 + t4 * 2;
            float b0 = bias[col], b1 = bias[col + 1];
            float v00 = acc[mt][nt][0] + b0, v01 = acc[mt][nt][1] + b1;
            float v10 = acc[mt][nt][2] + b0, v11 = acc[mt][nt][3] + b1;
            if (MODE == 0) {
                if (m0 + rl < cnt)
                    *(uint32_t*)(Oh + (size_t)(m0 + rl) * D_MODEL + col) =
                        pack_h(v00, v01);
                if (m0 + rl + 8 < cnt)
                    *(uint32_t*)(Oh + (size_t)(m0 + rl + 8) * D_MODEL + col) =
                        pack_h(v10, v11);
            } else {
                if (m0 + rl < cnt)
                    *(float2*)(Of + (size_t)sidx[rl] * D_MODEL + col) =
                        make_float2(v00, v01);
                if (m0 + rl + 8 < cnt)
                    *(float2*)(Of + (size_t)sidx[rl + 8] * D_MODEL + col) =
                        make_float2(v10, v11);
            }
        }
    }
}

// ---------------------------------------------------------------------------
// Tensor-core flash attention (R12/R13 proven, unchanged).
// ---------------------------------------------------------------------------
#define AROW   72
#define QTILE  (64 * AROW)
#define OFF_QH 0
#define OFF_QL QTILE
#define OFF_KV(st, a) (2 * QTILE + ((st) * 3 + (a)) * QTILE)
#define ATTN_SMEM (8 * QTILE * 2)

__global__ __launch_bounds__(128) void attn_mma_kernel(
    const __half* __restrict__ Qh, const __half* __restrict__ Ql,
    const __half* __restrict__ Kh, const __half* __restrict__ Kl,
    const __half* __restrict__ V, __half* __restrict__ ctx)
{
    extern __shared__ __align__(128) char smc[];
    const uint32_t smb = smem_u32(smc);

    const int tid = threadIdx.x;
    const int b   = blockIdx.z;
    const int h   = blockIdx.y;
    const int bcnt = g_cnt[b];
    const int boff = g_off[b];
    const int q0   = blockIdx.x * 64;
    if (q0 >= bcnt) return;

    const int lane = tid & 31;
    const int w    = tid >> 5;
    const int g    = lane >> 2;
    const int t4   = lane & 3;
    const int wr   = w * 16;
    const size_t hcol = (size_t)h * HDIM;

    #pragma unroll
    for (int t = 0; t < 8; t++) {
        int i   = tid + t * 128;
        int arr = i >> 9;
        int rem = i & 511;
        int row = rem >> 3;
        int ch  = rem & 7;
        int gr  = (q0 + row < bcnt) ? (boff + q0 + row) : boff;
        const __half* src = (arr ? Ql : Qh) + (size_t)gr * D_MODEL + hcol + ch * 8;
        cp_async16(smb + ((arr ? OFF_QL : OFF_QH) + row * AROW + ch * 8) * 2, src);
    }
    cp_commit();

    auto load_kv = [&](int kv0, int st) {
        #pragma unroll
        for (int t = 0; t < 12; t++) {
            int i   = tid + t * 128;
            int arr = i / 512;
            int rem = i & 511;
            int row = rem >> 3;
            int ch  = rem & 7;
            int gr  = (kv0 + row < bcnt) ? (boff + kv0 + row) : boff;
            const __half* base = (arr == 0) ? Kh : (arr == 1 ? Kl : V);
            cp_async16(smb + (OFF_KV(st, arr) + row * AROW + ch * 8) * 2,
                       base + (size_t)gr * D_MODEL + hcol + ch * 8);
        }
        cp_commit();
    };

    float o[8][4];
    #pragma unroll
    for (int nt = 0; nt < 8; nt++)
        #pragma unroll
        for (int r = 0; r < 4; r++) o[nt][r] = 0.0f;
    float m0r = -1e30f, m1r = -1e30f, l0r = 0.0f, l1r = 0.0f;

    const int nit = (bcnt + 63) >> 6;
    load_kv(0, 0);

    for (int it = 0; it < nit; it++) {
        if (it + 1 < nit) { load_kv((it + 1) << 6, (it + 1) & 1); cp_wait<1>(); }
        else              { cp_wait<0>(); }
        __syncthreads();

        const int st  = it & 1;
        const int kv0 = it << 6;
        const char* pQH = smc + OFF_QH * 2;
        const char* pQL = smc + OFF_QL * 2;
        const char* pKH = smc + OFF_KV(st, 0) * 2;
        const char* pKL = smc + OFF_KV(st, 1) * 2;
        const uint32_t pV = smb + OFF_KV(st, 2) * 2;

        float sacc[8][4];
        #pragma unroll
        for (int nt = 0; nt < 8; nt++)
            #pragma unroll
            for (int r = 0; r < 4; r++) sacc[nt][r] = 0.0f;

        #pragma unroll
        for (int kt = 0; kt < 4; kt++) {
            const int kc = kt * 16 + t4 * 2;
            uint32_t ah[4], al[4];
            {
                int r0 = (wr + g) * AROW + kc;
                int r1 = (wr + g + 8) * AROW + kc;
                ah[0] = *(const uint32_t*)(pQH + r0 * 2);
                ah[1] = *(const uint32_t*)(pQH + r1 * 2);
                ah[2] = *(const uint32_t*)(pQH + (r0 + 8) * 2);
                ah[3] = *(const uint32_t*)(pQH + (r1 + 8) * 2);
                al[0] = *(const uint32_t*)(pQL + r0 * 2);
                al[1] = *(const uint32_t*)(pQL + r1 * 2);
                al[2] = *(const uint32_t*)(pQL + (r0 + 8) * 2);
                al[3] = *(const uint32_t*)(pQL + (r1 + 8) * 2);
            }
            #pragma unroll
            for (int nt = 0; nt < 8; nt++) {
                int rk = (nt * 8 + g) * AROW + kc;
                uint32_t bh0 = *(const uint32_t*)(pKH + rk * 2);
                uint32_t bh1 = *(const uint32_t*)(pKH + (rk + 8) * 2);
                uint32_t bl0 = *(const uint32_t*)(pKL + rk * 2);
                uint32_t bl1 = *(const uint32_t*)(pKL + (rk + 8) * 2);
                mma_fp16(sacc[nt], ah, bh0, bh1);
                mma_fp16(sacc[nt], ah, bl0, bl1);
                mma_fp16(sacc[nt], al, bh0, bh1);
            }
        }

        float mx0 = -1e30f, mx1 = -1e30f;
        #pragma unroll
        for (int nt = 0; nt < 8; nt++) {
            int c0 = kv0 + nt * 8 + 2 * t4;
            if (c0 >= bcnt)     { sacc[nt][0] = NEG_BIG; sacc[nt][2] = NEG_BIG; }
            if (c0 + 1 >= bcnt) { sacc[nt][1] = NEG_BIG; sacc[nt][3] = NEG_BIG; }
            mx0 = fmaxf(mx0, fmaxf(sacc[nt][0], sacc[nt][1]));
            mx1 = fmaxf(mx1, fmaxf(sacc[nt][2], sacc[nt][3]));
        }
        mx0 = fmaxf(mx0, __shfl_xor_sync(0xffffffffu, mx0, 1));
        mx0 = fmaxf(mx0, __shfl_xor_sync(0xffffffffu, mx0, 2));
        mx1 = fmaxf(mx1, __shfl_xor_sync(0xffffffffu, mx1, 1));
        mx1 = fmaxf(mx1, __shfl_xor_sync(0xffffffffu, mx1, 2));

        float mn0 = fmaxf(m0r, mx0), mn1 = fmaxf(m1r, mx1);
        float al0 = __expf(m0r - mn0), al1 = __expf(m1r - mn1);
        float ls0 = 0.0f, ls1 = 0.0f;
        #pragma unroll
        for (int nt = 0; nt < 8; nt++) {
            sacc[nt][0] = __expf(sacc[nt][0] - mn0);
            sacc[nt][1] = __expf(sacc[nt][1] - mn0);
            sacc[nt][2] = __expf(sacc[nt][2] - mn1);
            sacc[nt][3] = __expf(sacc[nt][3] - mn1);
            ls0 += sacc[nt][0] + sacc[nt][1];
            ls1 += sacc[nt][2] + sacc[nt][3];
        }
        ls0 += __shfl_xor_sync(0xffffffffu, ls0, 1);
        ls0 += __shfl_xor_sync(0xffffffffu, ls0, 2);
        ls1 += __shfl_xor_sync(0xffffffffu, ls1, 1);
        ls1 += __shfl_xor_sync(0xffffffffu, ls1, 2);
        l0r = l0r * al0 + ls0;  m0r = mn0;
        l1r = l1r * al1 + ls1;  m1r = mn1;
        #pragma unroll
        for (int nt = 0; nt < 8; nt++) {
            o[nt][0] *= al0; o[nt][1] *= al0;
            o[nt][2] *= al1; o[nt][3] *= al1;
        }

        #pragma unroll
        for (int kt = 0; kt < 4; kt++) {
            uint32_t pa[4];
            pa[0] = pack_h(sacc[2 * kt][0],     sacc[2 * kt][1]);
            pa[1] = pack_h(sacc[2 * kt][2],     sacc[2 * kt][3]);
            pa[2] = pack_h(sacc[2 * kt + 1][0], sacc[2 * kt + 1][1]);
            pa[3] = pack_h(sacc[2 * kt + 1][2], sacc[2 * kt + 1][3]);
            #pragma unroll
            for (int ntp = 0; ntp < 4; ntp++) {
                int mat = lane >> 3, r = lane & 7;
                int vrow = kt * 16 + (mat & 1) * 8 + r;
                int vcol = ntp * 16 + (mat >> 1) * 8;
                uint32_t vb[4];
                ldmatrix_x4_trans(vb, pV + (vrow * AROW + vcol) * 2);
                mma_fp16(o[2 * ntp],     pa, vb[0], vb[1]);
                mma_fp16(o[2 * ntp + 1], pa, vb[2], vb[3]);
            }
        }
        __syncthreads();
    }

    float inv0 = 1.0f / l0r, inv1 = 1.0f / l1r;
    int row0 = q0 + wr + g, row1 = row0 + 8;
    #pragma unroll
    for (int nt = 0; nt < 8; nt++) {
        int col = (int)hcol + nt * 8 + 2 * t4;
        if (row0 < bcnt)
            *(uint32_t*)(ctx + (size_t)(boff + row0) * D_MODEL + col) =
                pack_h(o[nt][0] * inv0, o[nt][1] * inv0);
        if (row1 < bcnt)
            *(uint32_t*)(ctx + (size_t)(boff + row1) * D_MODEL + col) =
                pack_h(o[nt][2] * inv1, o[nt][3] * inv1);
    }
}

// ---------------------------------------------------------------------------
extern "C" void kernel_launch(void* const* d_in, const int* in_sizes, int n_in,
                              void* d_out, int out_size)
{
    (void)in_sizes; (void)n_in; (void)out_size;
    const float* x  = (const float*)d_in[0];
    const int*   pm = (const int*)  d_in[1];
    const float* Wq = (const float*)d_in[2];
    const float* bq = (const float*)d_in[3];
    const float* Wk = (const float*)d_in[4];
    const float* bk = (const float*)d_in[5];
    const float* Wv = (const float*)d_in[6];
    const float* bv = (const float*)d_in[7];
    const float* Wo = (const float*)d_in[8];
    const float* bo = (const float*)d_in[9];
    float* out = (float*)d_out;

    bf16 *xbh, *xbl, *wqkh, *wqkl;
    __half *xh16, *wv16, *wo16, *qh16, *ql16, *kh16, *kl16, *v16, *c16;
    cudaGetSymbolAddress((void**)&xbh, g_xbh);
    cudaGetSymbolAddress((void**)&xbl, g_xbl);
    cudaGetSymbolAddress((void**)&wqkh, g_wqk_h);
    cudaGetSymbolAddress((void**)&wqkl, g_wqk_l);
    cudaGetSymbolAddress((void**)&xh16, g_xh16);
    cudaGetSymbolAddress((void**)&wv16, g_wv16);
    cudaGetSymbolAddress((void**)&wo16, g_wo16);
    cudaGetSymbolAddress((void**)&qh16, g_qh16);
    cudaGetSymbolAddress((void**)&ql16, g_ql16);
    cudaGetSymbolAddress((void**)&kh16, g_kh16);
    cudaGetSymbolAddress((void**)&kl16, g_kl16);
    cudaGetSymbolAddress((void**)&v16, g_v16);
    cudaGetSymbolAddress((void**)&c16, g_c16);

    cudaFuncSetAttribute(gemm_qk_kernel,
                         cudaFuncAttributeMaxDynamicSharedMemorySize, QK_SMEM);
    cudaFuncSetAttribute(gemm_f16_kernel<0>,
                         cudaFuncAttributeMaxDynamicSharedMemorySize, F_SMEM);
    cudaFuncSetAttribute(gemm_f16_kernel<1>,
                         cudaFuncAttributeMaxDynamicSharedMemorySize, F_SMEM);
    cudaFuncSetAttribute(attn_mma_kernel,
                         cudaFuncAttributeMaxDynamicSharedMemorySize, ATTN_SMEM);

    const size_t WSZ = (size_t)D_MODEL * D_MODEL;
    const int n4 = MROWS * D_MODEL / 4;

    split_x_kernel<<<(n4 + 255) / 256, 256>>>(x, xbh, xbl, xh16, n4);
    build_idx_kernel<<<BATCH, 256>>>(pm);
    build_gidx_kernel<<<1, 256>>>();
    bias_fill_kernel<<<n4 / 256, 256>>>(bo, out);

    dim3 tgrid(D_MODEL / 32, D_MODEL / 32, 4), tblk(32, 8);
    transpose_all_kernel<<<tgrid, tblk>>>(Wq, Wk, Wv, Wo,
                                          wqkh + 0 * WSZ, wqkl + 0 * WSZ,
                                          wqkh + 1 * WSZ, wqkl + 1 * WSZ,
                                          wv16, wo16);

    // Q,K projections
    dim3 qkgrid(D_MODEL / 128, MROWS / 128, 2);
    gemm_qk_kernel<<<qkgrid, 256, QK_SMEM>>>(xbh, xbl, wqkh, wqkl, bq, bk,
                                             qh16, ql16, kh16, kl16);

    // V projection
    dim3 vgrid(D_MODEL / 128, MROWS / 128);
    gemm_f16_kernel<0><<<vgrid, 256, F_SMEM>>>(xh16, wv16, bv, v16, nullptr);

    // attention
    dim3 agrid(S_LEN / 64, NHEAD, BATCH);
    attn_mma_kernel<<<agrid, 128, ATTN_SMEM>>>(qh16, ql16, kh16, kl16, v16, c16);

    // O projection
    gemm_f16_kernel<1><<<vgrid, 256, F_SMEM>>>(c16, wo16, bo, nullptr, out);
}

// round 15
// speedup vs baseline: 8.9033x; 1.0075x over previous
#include <cuda_runtime.h>
#include <cuda_fp16.h>
#include <math.h>
#include <stdint.h>

#define BATCH   4
#define S_LEN   2048
#define D_MODEL 1024
#define NHEAD   16
#define HDIM    64
#define MROWS   (BATCH * S_LEN)

#define NEG_BIG (-1.0e9f)

// ---------------------------------------------------------------------------
// Scratch (fp16 everywhere)
// ---------------------------------------------------------------------------
__device__ __align__(1024) __half g_xh[(size_t)MROWS * D_MODEL];   // x fp16 hi
__device__ __align__(1024) __half g_xl[(size_t)MROWS * D_MODEL];   // x fp16 lo
__device__ __align__(1024) __half g_qh16[(size_t)MROWS * D_MODEL];
__device__ __align__(1024) __half g_ql16[(size_t)MROWS * D_MODEL];
__device__ __align__(1024) __half g_kh16[(size_t)MROWS * D_MODEL];
__device__ __align__(1024) __half g_kl16[(size_t)MROWS * D_MODEL];
__device__ __align__(1024) __half g_v16[(size_t)MROWS * D_MODEL];
__device__ __align__(1024) __half g_c16[(size_t)MROWS * D_MODEL];
__device__ __align__(1024) __half g_wqk_h[2][(size_t)D_MODEL * D_MODEL];
__device__ __align__(1024) __half g_wqk_l[2][(size_t)D_MODEL * D_MODEL];
__device__ __align__(1024) __half g_wv16[(size_t)D_MODEL * D_MODEL];
__device__ __align__(1024) __half g_wo16[(size_t)D_MODEL * D_MODEL];

__device__ int g_idx[BATCH][S_LEN];
__device__ int g_cnt[BATCH];
__device__ int g_off[BATCH + 1];
__device__ int g_gidx[MROWS];

// ---------------------------------------------------------------------------
// Helpers
// ---------------------------------------------------------------------------
__device__ __forceinline__ uint32_t smem_u32(const void* p) {
    uint32_t a;
    asm("{ .reg .u64 t; cvta.to.shared.u64 t, %1; cvt.u32.u64 %0, t; }"
        : "=r"(a) : "l"(p));
    return a;
}
__device__ __forceinline__ void cp_async16(uint32_t saddr, const void* gptr) {
    asm volatile("cp.async.cg.shared.global [%0], [%1], 16;"
                 :: "r"(saddr), "l"(__cvta_generic_to_global(gptr)));
}
__device__ __forceinline__ void cp_commit() {
    asm volatile("cp.async.commit_group;" ::: "memory");
}
template <int N>
__device__ __forceinline__ void cp_wait() {
    asm volatile("cp.async.wait_group %0;" :: "n"(N) : "memory");
}
__device__ __forceinline__ void mma_fp16(float* d, const uint32_t* a,
                                         uint32_t b0, uint32_t b1) {
    asm volatile(
        "mma.sync.aligned.m16n8k16.row.col.f32.f16.f16.f32 "
        "{%0,%1,%2,%3}, {%4,%5,%6,%7}, {%8,%9}, {%0,%1,%2,%3};"
        : "+f"(d[0]), "+f"(d[1]), "+f"(d[2]), "+f"(d[3])
        : "r"(a[0]), "r"(a[1]), "r"(a[2]), "r"(a[3]), "r"(b0), "r"(b1));
}
__device__ __forceinline__ void ldsm_x4(uint32_t* r, uint32_t addr) {
    asm volatile(
        "ldmatrix.sync.aligned.m8n8.x4.shared.b16 {%0,%1,%2,%3}, [%4];"
        : "=r"(r[0]), "=r"(r[1]), "=r"(r[2]), "=r"(r[3]) : "r"(addr));
}
__device__ __forceinline__ void ldmatrix_x4_trans(uint32_t* r, uint32_t addr) {
    asm volatile(
        "ldmatrix.sync.aligned.m8n8.x4.trans.shared.b16 {%0,%1,%2,%3}, [%4];"
        : "=r"(r[0]), "=r"(r[1]), "=r"(r[2]), "=r"(r[3]) : "r"(addr));
}
__device__ __forceinline__ uint32_t pack_h(float a, float b) {
    __half2 t = __floats2half2_rn(a, b);
    return *(uint32_t*)&t;
}

// ---------------------------------------------------------------------------
// Prep kernels
// ---------------------------------------------------------------------------
// x -> fp16 hi/lo, one read
__global__ __launch_bounds__(256) void split_x_kernel(
    const float* __restrict__ in, __half* __restrict__ hi,
    __half* __restrict__ lo, int n4)
{
    int i = blockIdx.x * blockDim.x + threadIdx.x;
    if (i >= n4) return;
    float4 v = ((const float4*)in)[i];
    __half hx = __float2half_rn(v.x), hy = __float2half_rn(v.y);
    __half hz = __float2half_rn(v.z), hw = __float2half_rn(v.w);
    __half lx = __float2half_rn(v.x - __half2float(hx));
    __half ly = __float2half_rn(v.y - __half2float(hy));
    __half lz = __float2half_rn(v.z - __half2float(hz));
    __half lw = __float2half_rn(v.w - __half2float(hw));
    ((__half2*)hi)[2 * i + 0] = __half2(hx, hy);
    ((__half2*)hi)[2 * i + 1] = __half2(hz, hw);
    ((__half2*)lo)[2 * i + 0] = __half2(lx, ly);
    ((__half2*)lo)[2 * i + 1] = __half2(lz, lw);
}

__global__ __launch_bounds__(256) void bias_fill_kernel(
    const float* __restrict__ bias, float* __restrict__ out)
{
    int i = blockIdx.x * blockDim.x + threadIdx.x;
    int c = (i & (D_MODEL / 4 - 1)) * 4;
    ((float4*)out)[i] = *(const float4*)(bias + c);
}

// All 4 weight transposes; z<2 -> fp16 hi/lo, z>=2 -> fp16 single.
__global__ __launch_bounds__(256) void transpose_all_kernel(
    const float* __restrict__ Wq, const float* __restrict__ Wk,
    const float* __restrict__ Wv, const float* __restrict__ Wo,
    __half* __restrict__ Th0, __half* __restrict__ Tl0,
    __half* __restrict__ Th1, __half* __restrict__ Tl1,
    __half* __restrict__ Tv, __half* __restrict__ To)
{
    __shared__ float t[32][33];
    int z = blockIdx.z;
    const float* W = (z == 0) ? Wq : (z == 1) ? Wk : (z == 2) ? Wv : Wo;
    int tx = threadIdx.x, ty = threadIdx.y;
    int n0 = blockIdx.x * 32, k0 = blockIdx.y * 32;
    #pragma unroll
    for (int j = 0; j < 4; j++)
        t[ty + 8 * j][tx] = W[(size_t)(k0 + ty + 8 * j) * D_MODEL + n0 + tx];
    __syncthreads();
    if (z < 2) {
        __half* Th = (z == 0) ? Th0 : Th1;
        __half* Tl = (z == 0) ? Tl0 : Tl1;
        #pragma unroll
        for (int j = 0; j < 4; j++) {
            float v = t[tx][ty + 8 * j];
            __half h = __float2half_rn(v);
            __half l = __float2half_rn(v - __half2float(h));
            size_t o = (size_t)(n0 + ty + 8 * j) * D_MODEL + k0 + tx;
            Th[o] = h;
            Tl[o] = l;
        }
    } else {
        __half* T = (z == 2) ? Tv : To;
        #pragma unroll
        for (int j = 0; j < 4; j++)
            T[(size_t)(n0 + ty + 8 * j) * D_MODEL + k0 + tx] =
                __float2half_rn(t[tx][ty + 8 * j]);
    }
}

__global__ __launch_bounds__(256) void build_idx_kernel(const int* __restrict__ mask) {
    __shared__ int part[256];
    int b = blockIdx.x, t = threadIdx.x;
    const int* m = mask + (size_t)b * S_LEN;
    int loc[8], s = 0;
    #pragma unroll
    for (int j = 0; j < 8; j++) { loc[j] = (m[t * 8 + j] != 0); s += loc[j]; }
    part[t] = s;
    __syncthreads();
    for (int off = 1; off < 256; off <<= 1) {
        int v = (t >= off) ? part[t - off] : 0;
        __syncthreads();
        part[t] += v;
        __syncthreads();
    }
    int p = part[t] - s;
    #pragma unroll
    for (int j = 0; j < 8; j++)
        if (loc[j]) g_idx[b][p++] = t * 8 + j;
    if (t == 255) g_cnt[b] = part[255];
}

__global__ __launch_bounds__(256) void build_gidx_kernel() {
    __shared__ int off[BATCH + 1];
    if (threadIdx.x == 0) {
        off[0] = 0;
        for (int b = 0; b < BATCH; b++) off[b + 1] = off[b] + g_cnt[b];
        for (int b = 0; b <= BATCH; b++) g_off[b] = off[b];
    }
    __syncthreads();
    for (int b = 0; b < BATCH; b++) {
        int c = g_cnt[b], o = off[b];
        for (int i = threadIdx.x; i < c; i += 256)
            g_gidx[o + i] = b * S_LEN + g_idx[b][i];
    }
}

// ---------------------------------------------------------------------------
#define ROWB    80
#define TILEB   (128 * ROWB)

// ========== Q,K GEMM: fp16 3-pass hi/lo split, 2-stage =====================
#define QK_STAGEB  (4 * TILEB)
#define QK_SMEM    (2 * QK_STAGEB + 512)

__global__ __launch_bounds__(256, 2) void gemm_qk_kernel(
    const __half* __restrict__ Ahi, const __half* __restrict__ Alo,
    const __half* __restrict__ Whi_base, const __half* __restrict__ Wlo_base,
    const float* __restrict__ bias0, const float* __restrict__ bias1,
    __half* __restrict__ Qh, __half* __restrict__ Ql,
    __half* __restrict__ Kh, __half* __restrict__ Kl)
{
    extern __shared__ __align__(128) char sm[];
    int* sidx = (int*)(sm + 2 * QK_STAGEB);
    const uint32_t smb = smem_u32(sm);

    const int cnt = g_off[BATCH];
    const int m0 = blockIdx.y * 128;
    if (m0 >= cnt) return;
    const int n0 = blockIdx.x * 128;
    const int z  = blockIdx.z;

    const __half* Bhi = Whi_base + (size_t)z * D_MODEL * D_MODEL;
    const __half* Blo = Wlo_base + (size_t)z * D_MODEL * D_MODEL;
    const float* bias = (z == 0 ? bias0 : bias1);
    __half* oh = (z == 0 ? Qh : Kh);
    __half* ol = (z == 0 ? Ql : Kl);

    const int tid  = threadIdx.x;
    const int lane = tid & 31;
    const int w    = tid >> 5;
    const int wm   = w & 1;
    const int wn   = w >> 1;
    const int g    = lane >> 2;
    const int t4   = lane & 3;

    const uint32_t aLane = (uint32_t)((lane & 15) * ROWB + (lane >> 4) * 16);
    const uint32_t bLane = (uint32_t)((((lane >> 4) & 1) * 8 + (lane & 7)) * ROWB
                                      + ((lane >> 3) & 1) * 16);

    if (tid < 128)
        sidx[tid] = (m0 + tid < cnt) ? g_gidx[m0 + tid] : g_gidx[0];
    __syncthreads();

    const __half* gsrc[4] = {Ahi, Alo, Bhi, Blo};

    float acc[4][4][4];
    #pragma unroll
    for (int mt = 0; mt < 4; mt++)
        #pragma unroll
        for (int nt = 0; nt < 4; nt++)
            #pragma unroll
            for (int r = 0; r < 4; r++)
                acc[mt][nt][r] = 0.0f;

    auto load_stage = [&](int kc, int st) {
        char* base = sm + st * QK_STAGEB;
        #pragma unroll
        for (int t = 0; t < 8; t++) {
            const int tile = t >> 1;
            const int wi   = tid + (t & 1) * 256;
            const int row  = wi >> 2;
            const int ch   = wi & 3;
            int grow = (tile < 2) ? sidx[row] : (n0 + row);
            const __half* src = gsrc[tile] + (size_t)grow * D_MODEL + kc * 32 + ch * 8;
            uint32_t dst = smem_u32(base + tile * TILEB + row * ROWB + ch * 16);
            cp_async16(dst, src);
        }
        cp_commit();
    };

    auto ldB = [&](uint32_t p, uint32_t cB, uint32_t (*b)[2]) {
        #pragma unroll
        for (int ntp = 0; ntp < 2; ntp++) {
            uint32_t r4[4];
            ldsm_x4(r4, p + (wn * 32 + ntp * 16) * ROWB + cB + bLane);
            b[2 * ntp][0] = r4[0]; b[2 * ntp][1] = r4[1];
            b[2 * ntp + 1][0] = r4[2]; b[2 * ntp + 1][1] = r4[3];
        }
    };
    auto ldA = [&](uint32_t p, uint32_t cB, uint32_t (*a)[4]) {
        #pragma unroll
        for (int mt = 0; mt < 4; mt++)
            ldsm_x4(a[mt], p + (wm * 64 + mt * 16) * ROWB + cB + aLane);
    };

    auto compute_stage = [&](int st) {
        const uint32_t base = smb + st * QK_STAGEB;
        const uint32_t pAh = base;
        const uint32_t pAl = base + TILEB;
        const uint32_t pBh = base + 2 * TILEB;
        const uint32_t pBl = base + 3 * TILEB;
        #pragma unroll
        for (int kk = 0; kk < 2; kk++) {
            const uint32_t cB = kk * 32;
            uint32_t a[4][4], b[4][2];
            // pass 1: Ah * Bh
            ldB(pBh, cB, b);
            ldA(pAh, cB, a);
            #pragma unroll
            for (int mt = 0; mt < 4; mt++)
                #pragma unroll
                for (int nt = 0; nt < 4; nt++)
                    mma_fp16(acc[mt][nt], a[mt], b[nt][0], b[nt][1]);
            // pass 2: Ah * Bl
            ldB(pBl, cB, b);
            #pragma unroll
            for (int mt = 0; mt < 4; mt++)
                #pragma unroll
                for (int nt = 0; nt < 4; nt++)
                    mma_fp16(acc[mt][nt], a[mt], b[nt][0], b[nt][1]);
            // pass 3: Al * Bh
            ldA(pAl, cB, a);
            ldB(pBh, cB, b);
            #pragma unroll
            for (int mt = 0; mt < 4; mt++)
                #pragma unroll
                for (int nt = 0; nt < 4; nt++)
                    mma_fp16(acc[mt][nt], a[mt], b[nt][0], b[nt][1]);
        }
    };

    const int NIT = D_MODEL / 32;
    load_stage(0, 0);
    load_stage(1, 1);
    for (int it = 0; it < NIT; it++) {
        if (it + 1 < NIT) cp_wait<1>(); else cp_wait<0>();
        __syncthreads();
        compute_stage(it & 1);
        __syncthreads();
        if (it + 2 < NIT) load_stage(it + 2, it & 1);
    }

    #pragma unroll
    for (int mt = 0; mt < 4; mt++) {
        int rl = wm * 64 + mt * 16 + g;
        #pragma unroll
        for (int nt = 0; nt < 4; nt++) {
            int col = n0 + wn * 32 + nt * 8 + t4 * 2;
            float b0 = bias[col], b1 = bias[col + 1];
            float v00 = acc[mt][nt][0] + b0, v01 = acc[mt][nt][1] + b1;
            float v10 = acc[mt][nt][2] + b0, v11 = acc[mt][nt][3] + b1;
            if (m0 + rl < cnt) {
                size_t off = (size_t)(m0 + rl) * D_MODEL + col;
                __half h0 = __float2half_rn(v00), h1 = __float2half_rn(v01);
                *(uint32_t*)(oh + off) = pack_h(v00, v01);
                *(uint32_t*)(ol + off) = pack_h(v00 - __half2float(h0),
                                                v01 - __half2float(h1));
            }
            if (m0 + rl + 8 < cnt) {
                size_t off = (size_t)(m0 + rl + 8) * D_MODEL + col;
                __half h0 = __float2half_rn(v10), h1 = __float2half_rn(v11);
                *(uint32_t*)(oh + off) = pack_h(v10, v11);
                *(uint32_t*)(ol + off) = pack_h(v10 - __half2float(h0),
                                                v11 - __half2float(h1));
            }
        }
    }
}

// ========== fp16 single-pass GEMM, 3-stage =================================
#define F_STAGEB  (2 * TILEB)
#define F_NSTAGE  3
#define F_SMEM    (F_NSTAGE * F_STAGEB + 512)

template<int MODE>   // 0: V (gather A, fp16 out), 1: O (compacted A, fp32 scatter)
__global__ __launch_bounds__(256, 2) void gemm_f16_kernel(
    const __half* __restrict__ A, const __half* __restrict__ B,
    const float* __restrict__ bias,
    __half* __restrict__ Oh, float* __restrict__ Of)
{
    extern __shared__ __align__(128) char sm[];
    int* sidx = (int*)(sm + F_NSTAGE * F_STAGEB);
    const uint32_t smb = smem_u32(sm);

    const int cnt = g_off[BATCH];
    const int m0 = blockIdx.y * 128;
    if (m0 >= cnt) return;
    const int n0 = blockIdx.x * 128;

    const int tid  = threadIdx.x;
    const int lane = tid & 31;
    const int w    = tid >> 5;
    const int wm   = w & 1;
    const int wn   = w >> 1;
    const int g    = lane >> 2;
    const int t4   = lane & 3;

    const uint32_t aLane = (uint32_t)((lane & 15) * ROWB + (lane >> 4) * 16);
    const uint32_t bLane = (uint32_t)((((lane >> 4) & 1) * 8 + (lane & 7)) * ROWB
                                      + ((lane >> 3) & 1) * 16);

    if (tid < 128)
        sidx[tid] = (m0 + tid < cnt) ? g_gidx[m0 + tid] : g_gidx[0];
    __syncthreads();

    float acc[4][4][4];
    #pragma unroll
    for (int mt = 0; mt < 4; mt++)
        #pragma unroll
        for (int nt = 0; nt < 4; nt++)
            #pragma unroll
            for (int r = 0; r < 4; r++)
                acc[mt][nt][r] = 0.0f;

    auto load_stage = [&](int kc, int st) {
        char* base = sm + st * F_STAGEB;
        #pragma unroll
        for (int t = 0; t < 4; t++) {
            const int tile = t >> 1;
            const int wi   = tid + (t & 1) * 256;
            const int row  = wi >> 2;
            const int ch   = wi & 3;
            int grow;
            if (tile == 0) {
                if (MODE == 0) grow = sidx[row];
                else { int ar = m0 + row; grow = (ar < cnt) ? ar : m0; }
            } else grow = n0 + row;
            const __half* src = (tile == 0 ? A : B) +
                                (size_t)grow * D_MODEL + kc * 32 + ch * 8;
            uint32_t dst = smem_u32(base + tile * TILEB + row * ROWB + ch * 16);
            cp_async16(dst, src);
        }
        cp_commit();
    };

    auto compute_stage = [&](int st) {
        const uint32_t base = smb + st * F_STAGEB;
        const uint32_t pA = base;
        const uint32_t pB = base + TILEB;
        #pragma unroll
        for (int kk = 0; kk < 2; kk++) {
            const uint32_t cB = kk * 32;
            uint32_t b[4][2], a[4][4];
            #pragma unroll
            for (int ntp = 0; ntp < 2; ntp++) {
                uint32_t r4[4];
                ldsm_x4(r4, pB + (wn * 32 + ntp * 16) * ROWB + cB + bLane);
                b[2 * ntp][0] = r4[0]; b[2 * ntp][1] = r4[1];
                b[2 * ntp + 1][0] = r4[2]; b[2 * ntp + 1][1] = r4[3];
            }
            #pragma unroll
            for (int mt = 0; mt < 4; mt++)
                ldsm_x4(a[mt], pA + (wm * 64 + mt * 16) * ROWB + cB + aLane);
            #pragma unroll
            for (int mt = 0; mt < 4; mt++)
                #pragma unroll
                for (int nt = 0; nt < 4; nt++)
                    mma_fp16(acc[mt][nt], a[mt], b[nt][0], b[nt][1]);
        }
    };

    const int NIT = D_MODEL / 32;
    load_stage(0, 0);
    load_stage(1, 1);
    for (int it = 0; it < NIT; it++) {
        if (it + 2 < NIT) { load_stage(it + 2, (it + 2) % F_NSTAGE); cp_wait<2>(); }
        else if (it + 1 < NIT) { cp_wait<1>(); }
        else { cp_wait<0>(); }
        __syncthreads();
        compute_stage(it % F_NSTAGE);
        __syncthreads();
    }

    #pragma unroll
    for (int mt = 0; mt < 4; mt++) {
        int rl = wm * 64 + mt * 16 + g;
        #pragma unroll
        for (int nt = 0; nt < 4; nt++) {
            int col = n0 + wn * 32 + nt * 8 + t4 * 2;
            float b0 = bias[col], b1 = bias[col + 1];
            float v00 = acc[mt][nt][0] + b0, v01 = acc[mt][nt][1] + b1;
            float v10 = acc[mt][nt][2] + b0, v11 = acc[mt][nt][3] + b1;
            if (MODE == 0) {
                if (m0 + rl < cnt)
                    *(uint32_t*)(Oh + (size_t)(m0 + rl) * D_MODEL + col) =
                        pack_h(v00, v01);
                if (m0 + rl + 8 < cnt)
                    *(uint32_t*)(Oh + (size_t)(m0 + rl + 8) * D_MODEL + col) =
                        pack_h(v10, v11);
            } else {
                if (m0 + rl < cnt)
                    *(float2*)(Of + (size_t)sidx[rl] * D_MODEL + col) =
                        make_float2(v00, v01);
                if (m0 + rl + 8 < cnt)
                    *(float2*)(Of + (size_t)sidx[rl + 8] * D_MODEL + col) =
                        make_float2(v10, v11);
            }
        }
    }
}

// ---------------------------------------------------------------------------
// Tensor-core flash attention (proven, unchanged).
// ---------------------------------------------------------------------------
#define AROW   72
#define QTILE  (64 * AROW)
#define OFF_QH 0
#define OFF_QL QTILE
#define OFF_KV(st, a) (2 * QTILE + ((st) * 3 + (a)) * QTILE)
#define ATTN_SMEM (8 * QTILE * 2)

__global__ __launch_bounds__(128) void attn_mma_kernel(
    const __half* __restrict__ Qh, const __half* __restrict__ Ql,
    const __half* __restrict__ Kh, const __half* __restrict__ Kl,
    const __half* __restrict__ V, __half* __restrict__ ctx)
{
    extern __shared__ __align__(128) char smc[];
    const uint32_t smb = smem_u32(smc);

    const int tid = threadIdx.x;
    const int b   = blockIdx.z;
    const int h   = blockIdx.y;
    const int bcnt = g_cnt[b];
    const int boff = g_off[b];
    const int q0   = blockIdx.x * 64;
    if (q0 >= bcnt) return;

    const int lane = tid & 31;
    const int w    = tid >> 5;
    const int g    = lane >> 2;
    const int t4   = lane & 3;
    const int wr   = w * 16;
    const size_t hcol = (size_t)h * HDIM;

    #pragma unroll
    for (int t = 0; t < 8; t++) {
        int i   = tid + t * 128;
        int arr = i >> 9;
        int rem = i & 511;
        int row = rem >> 3;
        int ch  = rem & 7;
        int gr  = (q0 + row < bcnt) ? (boff + q0 + row) : boff;
        const __half* src = (arr ? Ql : Qh) + (size_t)gr * D_MODEL + hcol + ch * 8;
        cp_async16(smb + ((arr ? OFF_QL : OFF_QH) + row * AROW + ch * 8) * 2, src);
    }
    cp_commit();

    auto load_kv = [&](int kv0, int st) {
        #pragma unroll
        for (int t = 0; t < 12; t++) {
            int i   = tid + t * 128;
            int arr = i / 512;
            int rem = i & 511;
            int row = rem >> 3;
            int ch  = rem & 7;
            int gr  = (kv0 + row < bcnt) ? (boff + kv0 + row) : boff;
            const __half* base = (arr == 0) ? Kh : (arr == 1 ? Kl : V);
            cp_async16(smb + (OFF_KV(st, arr) + row * AROW + ch * 8) * 2,
                       base + (size_t)gr * D_MODEL + hcol + ch * 8);
        }
        cp_commit();
    };

    float o[8][4];
    #pragma unroll
    for (int nt = 0; nt < 8; nt++)
        #pragma unroll
        for (int r = 0; r < 4; r++) o[nt][r] = 0.0f;
    float m0r = -1e30f, m1r = -1e30f, l0r = 0.0f, l1r = 0.0f;

    const int nit = (bcnt + 63) >> 6;
    load_kv(0, 0);

    for (int it = 0; it < nit; it++) {
        if (it + 1 < nit) { load_kv((it + 1) << 6, (it + 1) & 1); cp_wait<1>(); }
        else              { cp_wait<0>(); }
        __syncthreads();

        const int st  = it & 1;
        const int kv0 = it << 6;
        const char* pQH = smc + OFF_QH * 2;
        const char* pQL = smc + OFF_QL * 2;
        const char* pKH = smc + OFF_KV(st, 0) * 2;
        const char* pKL = smc + OFF_KV(st, 1) * 2;
        const uint32_t pV = smb + OFF_KV(st, 2) * 2;

        float sacc[8][4];
        #pragma unroll
        for (int nt = 0; nt < 8; nt++)
            #pragma unroll
            for (int r = 0; r < 4; r++) sacc[nt][r] = 0.0f;

        #pragma unroll
        for (int kt = 0; kt < 4; kt++) {
            const int kc = kt * 16 + t4 * 2;
            uint32_t ah[4], al[4];
            {
                int r0 = (wr + g) * AROW + kc;
                int r1 = (wr + g + 8) * AROW + kc;
                ah[0] = *(const uint32_t*)(pQH + r0 * 2);
                ah[1] = *(const uint32_t*)(pQH + r1 * 2);
                ah[2] = *(const uint32_t*)(pQH + (r0 + 8) * 2);
                ah[3] = *(const uint32_t*)(pQH + (r1 + 8) * 2);
                al[0] = *(const uint32_t*)(pQL + r0 * 2);
                al[1] = *(const uint32_t*)(pQL + r1 * 2);
                al[2] = *(const uint32_t*)(pQL + (r0 + 8) * 2);
                al[3] = *(const uint32_t*)(pQL + (r1 + 8) * 2);
            }
            #pragma unroll
            for (int nt = 0; nt < 8; nt++) {
                int rk = (nt * 8 + g) * AROW + kc;
                uint32_t bh0 = *(const uint32_t*)(pKH + rk * 2);
                uint32_t bh1 = *(const uint32_t*)(pKH + (rk + 8) * 2);
                uint32_t bl0 = *(const uint32_t*)(pKL + rk * 2);
                uint32_t bl1 = *(const uint32_t*)(pKL + (rk + 8) * 2);
                mma_fp16(sacc[nt], ah, bh0, bh1);
                mma_fp16(sacc[nt], ah, bl0, bl1);
                mma_fp16(sacc[nt], al, bh0, bh1);
            }
        }

        float mx0 = -1e30f, mx1 = -1e30f;
        #pragma unroll
        for (int nt = 0; nt < 8; nt++) {
            int c0 = kv0 + nt * 8 + 2 * t4;
            if (c0 >= bcnt)     { sacc[nt][0] = NEG_BIG; sacc[nt][2] = NEG_BIG; }
            if (c0 + 1 >= bcnt) { sacc[nt][1] = NEG_BIG; sacc[nt][3] = NEG_BIG; }
            mx0 = fmaxf(mx0, fmaxf(sacc[nt][0], sacc[nt][1]));
            mx1 = fmaxf(mx1, fmaxf(sacc[nt][2], sacc[nt][3]));
        }
        mx0 = fmaxf(mx0, __shfl_xor_sync(0xffffffffu, mx0, 1));
        mx0 = fmaxf(mx0, __shfl_xor_sync(0xffffffffu, mx0, 2));
        mx1 = fmaxf(mx1, __shfl_xor_sync(0xffffffffu, mx1, 1));
        mx1 = fmaxf(mx1, __shfl_xor_sync(0xffffffffu, mx1, 2));

        float mn0 = fmaxf(m0r, mx0), mn1 = fmaxf(m1r, mx1);
        float al0 = __expf(m0r - mn0), al1 = __expf(m1r - mn1);
        float ls0 = 0.0f, ls1 = 0.0f;
        #pragma unroll
        for (int nt = 0; nt < 8; nt++) {
            sacc[nt][0] = __expf(sacc[nt][0] - mn0);
            sacc[nt][1] = __expf(sacc[nt][1] - mn0);
            sacc[nt][2] = __expf(sacc[nt][2] - mn1);
            sacc[nt][3] = __expf(sacc[nt][3] - mn1);
            ls0 += sacc[nt][0] + sacc[nt][1];
            ls1 += sacc[nt][2] + sacc[nt][3];
        }
        ls0 += __shfl_xor_sync(0xffffffffu, ls0, 1);
        ls0 += __shfl_xor_sync(0xffffffffu, ls0, 2);
        ls1 += __shfl_xor_sync(0xffffffffu, ls1, 1);
        ls1 += __shfl_xor_sync(0xffffffffu, ls1, 2);
        l0r = l0r * al0 + ls0;  m0r = mn0;
        l1r = l1r * al1 + ls1;  m1r = mn1;
        #pragma unroll
        for (int nt = 0; nt < 8; nt++) {
            o[nt][0] *= al0; o[nt][1] *= al0;
            o[nt][2] *= al1; o[nt][3] *= al1;
        }

        #pragma unroll
        for (int kt = 0; kt < 4; kt++) {
            uint32_t pa[4];
            pa[0] = pack_h(sacc[2 * kt][0],     sacc[2 * kt][1]);
            pa[1] = pack_h(sacc[2 * kt][2],     sacc[2 * kt][3]);
            pa[2] = pack_h(sacc[2 * kt + 1][0], sacc[2 * kt + 1][1]);
            pa[3] = pack_h(sacc[2 * kt + 1][2], sacc[2 * kt + 1][3]);
            #pragma unroll
            for (int ntp = 0; ntp < 4; ntp++) {
                int mat = lane >> 3, r = lane & 7;
                int vrow = kt * 16 + (mat & 1) * 8 + r;
                int vcol = ntp * 16 + (mat >> 1) * 8;
                uint32_t vb[4];
                ldmatrix_x4_trans(vb, pV + (vrow * AROW + vcol) * 2);
                mma_fp16(o[2 * ntp],     pa, vb[0], vb[1]);
                mma_fp16(o[2 * ntp + 1], pa, vb[2], vb[3]);
            }
        }
        __syncthreads();
    }

    float inv0 = 1.0f / l0r, inv1 = 1.0f / l1r;
    int row0 = q0 + wr + g, row1 = row0 + 8;
    #pragma unroll
    for (int nt = 0; nt < 8; nt++) {
        int col = (int)hcol + nt * 8 + 2 * t4;
        if (row0 < bcnt)
            *(uint32_t*)(ctx + (size_t)(boff + row0) * D_MODEL + col) =
                pack_h(o[nt][0] * inv0, o[nt][1] * inv0);
        if (row1 < bcnt)
            *(uint32_t*)(ctx + (size_t)(boff + row1) * D_MODEL + col) =
                pack_h(o[nt][2] * inv1, o[nt][3] * inv1);
    }
}

// ---------------------------------------------------------------------------
extern "C" void kernel_launch(void* const* d_in, const int* in_sizes, int n_in,
                              void* d_out, int out_size)
{
    (void)in_sizes; (void)n_in; (void)out_size;
    const float* x  = (const float*)d_in[0];
    const int*   pm = (const int*)  d_in[1];
    const float* Wq = (const float*)d_in[2];
    const float* bq = (const float*)d_in[3];
    const float* Wk = (const float*)d_in[4];
    const float* bk = (const float*)d_in[5];
    const float* Wv = (const float*)d_in[6];
    const float* bv = (const float*)d_in[7];
    const float* Wo = (const float*)d_in[8];
    const float* bo = (const float*)d_in[9];
    float* out = (float*)d_out;

    __half *xh, *xl, *wqkh, *wqkl, *wv16, *wo16;
    __half *qh16, *ql16, *kh16, *kl16, *v16, *c16;
    cudaGetSymbolAddress((void**)&xh, g_xh);
    cudaGetSymbolAddress((void**)&xl, g_xl);
    cudaGetSymbolAddress((void**)&wqkh, g_wqk_h);
    cudaGetSymbolAddress((void**)&wqkl, g_wqk_l);
    cudaGetSymbolAddress((void**)&wv16, g_wv16);
    cudaGetSymbolAddress((void**)&wo16, g_wo16);
    cudaGetSymbolAddress((void**)&qh16, g_qh16);
    cudaGetSymbolAddress((void**)&ql16, g_ql16);
    cudaGetSymbolAddress((void**)&kh16, g_kh16);
    cudaGetSymbolAddress((void**)&kl16, g_kl16);
    cudaGetSymbolAddress((void**)&v16, g_v16);
    cudaGetSymbolAddress((void**)&c16, g_c16);

    cudaFuncSetAttribute(gemm_qk_kernel,
                         cudaFuncAttributeMaxDynamicSharedMemorySize, QK_SMEM);
    cudaFuncSetAttribute(gemm_f16_kernel<0>,
                         cudaFuncAttributeMaxDynamicSharedMemorySize, F_SMEM);
    cudaFuncSetAttribute(gemm_f16_kernel<1>,
                         cudaFuncAttributeMaxDynamicSharedMemorySize, F_SMEM);
    cudaFuncSetAttribute(attn_mma_kernel,
                         cudaFuncAttributeMaxDynamicSharedMemorySize, ATTN_SMEM);

    const size_t WSZ = (size_t)D_MODEL * D_MODEL;
    const int n4 = MROWS * D_MODEL / 4;

    split_x_kernel<<<(n4 + 255) / 256, 256>>>(x, xh, xl, n4);
    build_idx_kernel<<<BATCH, 256>>>(pm);
    build_gidx_kernel<<<1, 256>>>();
    bias_fill_kernel<<<n4 / 256, 256>>>(bo, out);

    dim3 tgrid(D_MODEL / 32, D_MODEL / 32, 4), tblk(32, 8);
    transpose_all_kernel<<<tgrid, tblk>>>(Wq, Wk, Wv, Wo,
                                          wqkh + 0 * WSZ, wqkl + 0 * WSZ,
                                          wqkh + 1 * WSZ, wqkl + 1 * WSZ,
                                          wv16, wo16);

    // Q,K projections (fp16 3-pass hi/lo)
    dim3 qkgrid(D_MODEL / 128, MROWS / 128, 2);
    gemm_qk_kernel<<<qkgrid, 256, QK_SMEM>>>(xh, xl, wqkh, wqkl, bq, bk,
                                             qh16, ql16, kh16, kl16);

    // V projection (fp16 single-pass on x-hi = fp16(x))
    dim3 vgrid(D_MODEL / 128, MROWS / 128);
    gemm_f16_kernel<0><<<vgrid, 256, F_SMEM>>>(xh, wv16, bv, v16, nullptr);

    // attention
    dim3 agrid(S_LEN / 64, NHEAD, BATCH);
    attn_mma_kernel<<<agrid, 128, ATTN_SMEM>>>(qh16, ql16, kh16, kl16, v16, c16);

    // O projection (fp16 single-pass, fp32 scatter)
    gemm_f16_kernel<1><<<vgrid, 256, F_SMEM>>>(c16, wo16, bo, nullptr, out);
}

// round 17
// speedup vs baseline: 9.3457x; 1.0497x over previous
#include <cuda_runtime.h>
#include <cuda_fp16.h>
#include <math.h>
#include <stdint.h>

#define BATCH   4
#define S_LEN   2048
#define D_MODEL 1024
#define NHEAD   16
#define HDIM    64
#define MROWS   (BATCH * S_LEN)

#define NEG_BIG (-1.0e9f)

// ---------------------------------------------------------------------------
// Scratch (fp16 everywhere)
// ---------------------------------------------------------------------------
__device__ __align__(1024) __half g_xh[(size_t)MROWS * D_MODEL];
__device__ __align__(1024) __half g_xl[(size_t)MROWS * D_MODEL];
__device__ __align__(1024) __half g_qh16[(size_t)MROWS * D_MODEL];
__device__ __align__(1024) __half g_ql16[(size_t)MROWS * D_MODEL];
__device__ __align__(1024) __half g_kh16[(size_t)MROWS * D_MODEL];
__device__ __align__(1024) __half g_kl16[(size_t)MROWS * D_MODEL];
__device__ __align__(1024) __half g_v16[(size_t)MROWS * D_MODEL];
__device__ __align__(1024) __half g_c16[(size_t)MROWS * D_MODEL];
__device__ __align__(1024) __half g_wqk_h[2][(size_t)D_MODEL * D_MODEL];
__device__ __align__(1024) __half g_wqk_l[2][(size_t)D_MODEL * D_MODEL];
__device__ __align__(1024) __half g_wv16[(size_t)D_MODEL * D_MODEL];
__device__ __align__(1024) __half g_wo16[(size_t)D_MODEL * D_MODEL];

__device__ int g_idx[BATCH][S_LEN];
__device__ int g_cnt[BATCH];
__device__ int g_off[BATCH + 1];
__device__ int g_gidx[MROWS];

// ---------------------------------------------------------------------------
// Helpers
// ---------------------------------------------------------------------------
__device__ __forceinline__ uint32_t smem_u32(const void* p) {
    uint32_t a;
    asm("{ .reg .u64 t; cvta.to.shared.u64 t, %1; cvt.u32.u64 %0, t; }"
        : "=r"(a) : "l"(p));
    return a;
}
__device__ __forceinline__ void cp_async16(uint32_t saddr, const void* gptr) {
    asm volatile("cp.async.cg.shared.global [%0], [%1], 16;"
                 :: "r"(saddr), "l"(__cvta_generic_to_global(gptr)));
}
__device__ __forceinline__ void cp_commit() {
    asm volatile("cp.async.commit_group;" ::: "memory");
}
template <int N>
__device__ __forceinline__ void cp_wait() {
    asm volatile("cp.async.wait_group %0;" :: "n"(N) : "memory");
}
__device__ __forceinline__ void mma_fp16(float* d, const uint32_t* a,
                                         uint32_t b0, uint32_t b1) {
    asm volatile(
        "mma.sync.aligned.m16n8k16.row.col.f32.f16.f16.f32 "
        "{%0,%1,%2,%3}, {%4,%5,%6,%7}, {%8,%9}, {%0,%1,%2,%3};"
        : "+f"(d[0]), "+f"(d[1]), "+f"(d[2]), "+f"(d[3])
        : "r"(a[0]), "r"(a[1]), "r"(a[2]), "r"(a[3]), "r"(b0), "r"(b1));
}
__device__ __forceinline__ void ldsm_x4(uint32_t* r, uint32_t addr) {
    asm volatile(
        "ldmatrix.sync.aligned.m8n8.x4.shared.b16 {%0,%1,%2,%3}, [%4];"
        : "=r"(r[0]), "=r"(r[1]), "=r"(r[2]), "=r"(r[3]) : "r"(addr));
}
__device__ __forceinline__ void ldmatrix_x4_trans(uint32_t* r, uint32_t addr) {
    asm volatile(
        "ldmatrix.sync.aligned.m8n8.x4.trans.shared.b16 {%0,%1,%2,%3}, [%4];"
        : "=r"(r[0]), "=r"(r[1]), "=r"(r[2]), "=r"(r[3]) : "r"(addr));
}
__device__ __forceinline__ uint32_t pack_h(float a, float b) {
    __half2 t = __floats2half2_rn(a, b);
    return *(uint32_t*)&t;
}

// ---------------------------------------------------------------------------
// Prep kernels
// ---------------------------------------------------------------------------
__global__ __launch_bounds__(256) void split_x_kernel(
    const float* __restrict__ in, __half* __restrict__ hi,
    __half* __restrict__ lo, int n4)
{
    int i = blockIdx.x * blockDim.x + threadIdx.x;
    if (i >= n4) return;
    float4 v = ((const float4*)in)[i];
    __half hx = __float2half_rn(v.x), hy = __float2half_rn(v.y);
    __half hz = __float2half_rn(v.z), hw = __float2half_rn(v.w);
    __half lx = __float2half_rn(v.x - __half2float(hx));
    __half ly = __float2half_rn(v.y - __half2float(hy));
    __half lz = __float2half_rn(v.z - __half2float(hz));
    __half lw = __float2half_rn(v.w - __half2float(hw));
    ((__half2*)hi)[2 * i + 0] = __half2(hx, hy);
    ((__half2*)hi)[2 * i + 1] = __half2(hz, hw);
    ((__half2*)lo)[2 * i + 0] = __half2(lx, ly);
    ((__half2*)lo)[2 * i + 1] = __half2(lz, lw);
}

__global__ __launch_bounds__(256) void bias_fill_kernel(
    const float* __restrict__ bias, float* __restrict__ out)
{
    int i = blockIdx.x * blockDim.x + threadIdx.x;
    int c = (i & (D_MODEL / 4 - 1)) * 4;
    ((float4*)out)[i] = *(const float4*)(bias + c);
}

__global__ __launch_bounds__(256) void transpose_all_kernel(
    const float* __restrict__ Wq, const float* __restrict__ Wk,
    const float* __restrict__ Wv, const float* __restrict__ Wo,
    __half* __restrict__ Th0, __half* __restrict__ Tl0,
    __half* __restrict__ Th1, __half* __restrict__ Tl1,
    __half* __restrict__ Tv, __half* __restrict__ To)
{
    __shared__ float t[32][33];
    int z = blockIdx.z;
    const float* W = (z == 0) ? Wq : (z == 1) ? Wk : (z == 2) ? Wv : Wo;
    int tx = threadIdx.x, ty = threadIdx.y;
    int n0 = blockIdx.x * 32, k0 = blockIdx.y * 32;
    #pragma unroll
    for (int j = 0; j < 4; j++)
        t[ty + 8 * j][tx] = W[(size_t)(k0 + ty + 8 * j) * D_MODEL + n0 + tx];
    __syncthreads();
    if (z < 2) {
        __half* Th = (z == 0) ? Th0 : Th1;
        __half* Tl = (z == 0) ? Tl0 : Tl1;
        #pragma unroll
        for (int j = 0; j < 4; j++) {
            float v = t[tx][ty + 8 * j];
            __half h = __float2half_rn(v);
            __half l = __float2half_rn(v - __half2float(h));
            size_t o = (size_t)(n0 + ty + 8 * j) * D_MODEL + k0 + tx;
            Th[o] = h;
            Tl[o] = l;
        }
    } else {
        __half* T = (z == 2) ? Tv : To;
        #pragma unroll
        for (int j = 0; j < 4; j++)
            T[(size_t)(n0 + ty + 8 * j) * D_MODEL + k0 + tx] =
                __float2half_rn(t[tx][ty + 8 * j]);
    }
}

__global__ __launch_bounds__(256) void build_idx_kernel(const int* __restrict__ mask) {
    __shared__ int part[256];
    int b = blockIdx.x, t = threadIdx.x;
    const int* m = mask + (size_t)b * S_LEN;
    int loc[8], s = 0;
    #pragma unroll
    for (int j = 0; j < 8; j++) { loc[j] = (m[t * 8 + j] != 0); s += loc[j]; }
    part[t] = s;
    __syncthreads();
    for (int off = 1; off < 256; off <<= 1) {
        int v = (t >= off) ? part[t - off] : 0;
        __syncthreads();
        part[t] += v;
        __syncthreads();
    }
    int p = part[t] - s;
    #pragma unroll
    for (int j = 0; j < 8; j++)
        if (loc[j]) g_idx[b][p++] = t * 8 + j;
    if (t == 255) g_cnt[b] = part[255];
}

__global__ __launch_bounds__(256) void build_gidx_kernel() {
    __shared__ int off[BATCH + 1];
    if (threadIdx.x == 0) {
        off[0] = 0;
        for (int b = 0; b < BATCH; b++) off[b + 1] = off[b] + g_cnt[b];
        for (int b = 0; b <= BATCH; b++) g_off[b] = off[b];
    }
    __syncthreads();
    for (int b = 0; b < BATCH; b++) {
        int c = g_cnt[b], o = off[b];
        for (int i = threadIdx.x; i < c; i += 256)
            g_gidx[o + i] = b * S_LEN + g_idx[b][i];
    }
}

// ---------------------------------------------------------------------------
#define ROWB    80                 // padded rows (V/O + attention kernels)
#define TILEB   (128 * ROWB)

// ========== Q,K GEMM: fp16 3-pass hi/lo, 3-stage, 64B swizzled rows ========
// swizzle: 16B-chunk index ch -> ch ^ ((row>>1)&3); tile = 128 rows x 64 B.
#define QT64       8192                  // 128 * 64
#define QK_STAGEB  (4 * QT64)            // 32768
#define QK_NSTAGE  3
#define QK_SMEM    (QK_NSTAGE * QK_STAGEB + 512)   // 98816

__global__ __launch_bounds__(256, 2) void gemm_qk_kernel(
    const __half* __restrict__ Ahi, const __half* __restrict__ Alo,
    const __half* __restrict__ Whi_base, const __half* __restrict__ Wlo_base,
    const float* __restrict__ bias0, const float* __restrict__ bias1,
    __half* __restrict__ Qh, __half* __restrict__ Ql,
    __half* __restrict__ Kh, __half* __restrict__ Kl)
{
    extern __shared__ __align__(128) char sm[];
    int* sidx = (int*)(sm + QK_NSTAGE * QK_STAGEB);
    const uint32_t smb = smem_u32(sm);

    const int cnt = g_off[BATCH];
    const int m0 = blockIdx.y * 128;
    if (m0 >= cnt) return;
    const int n0 = blockIdx.x * 128;
    const int z  = blockIdx.z;

    const __half* Bhi = Whi_base + (size_t)z * D_MODEL * D_MODEL;
    const __half* Blo = Wlo_base + (size_t)z * D_MODEL * D_MODEL;
    const float* bias = (z == 0 ? bias0 : bias1);
    __half* oh = (z == 0 ? Qh : Kh);
    __half* ol = (z == 0 ? Ql : Kl);

    const int tid  = threadIdx.x;
    const int lane = tid & 31;
    const int w    = tid >> 5;
    const int wm   = w & 1;
    const int wn   = w >> 1;
    const int g    = lane >> 2;
    const int t4   = lane & 3;

    // swizzled ldmatrix lane geometry (tile bases are multiples of 16 rows)
    const int rlA = lane & 15, cbA = lane >> 4,        swA = (rlA >> 1) & 3;
    const int rlB = ((lane >> 4) & 1) * 8 + (lane & 7), cbB = (lane >> 3) & 1,
              swB = (rlB >> 1) & 3;

    if (tid < 128)
        sidx[tid] = (m0 + tid < cnt) ? g_gidx[m0 + tid] : g_gidx[0];
    __syncthreads();

    const __half* gsrc[4] = {Ahi, Alo, Bhi, Blo};

    float acc[4][4][4];
    #pragma unroll
    for (int mt = 0; mt < 4; mt++)
        #pragma unroll
        for (int nt = 0; nt < 4; nt++)
            #pragma unroll
            for (int r = 0; r < 4; r++)
                acc[mt][nt][r] = 0.0f;

    auto load_stage = [&](int kc, int st) {
        uint32_t base = smb + st * QK_STAGEB;
        #pragma unroll
        for (int t = 0; t < 8; t++) {
            const int tile = t >> 1;
            const int wi   = tid + (t & 1) * 256;
            const int row  = wi >> 2;
            const int ch   = wi & 3;
            int grow = (tile < 2) ? sidx[row] : (n0 + row);
            const __half* src = gsrc[tile] + (size_t)grow * D_MODEL + kc * 32 + ch * 8;
            uint32_t dst = base + tile * QT64 + row * 64
                         + ((ch ^ ((row >> 1) & 3)) << 4);
            cp_async16(dst, src);
        }
        cp_commit();
    };

    auto ldB = [&](uint32_t p, int kk, uint32_t (*b)[2]) {
        const uint32_t chB = (uint32_t)((((kk << 1) | cbB) ^ swB) << 4);
        #pragma unroll
        for (int ntp = 0; ntp < 2; ntp++) {
            uint32_t r4[4];
            ldsm_x4(r4, p + (wn * 32 + ntp * 16 + rlB) * 64 + chB);
            b[2 * ntp][0] = r4[0]; b[2 * ntp][1] = r4[1];
            b[2 * ntp + 1][0] = r4[2]; b[2 * ntp + 1][1] = r4[3];
        }
    };
    auto ldA = [&](uint32_t p, int kk, uint32_t (*a)[4]) {
        const uint32_t chA = (uint32_t)((((kk << 1) | cbA) ^ swA) << 4);
        #pragma unroll
        for (int mt = 0; mt < 4; mt++)
            ldsm_x4(a[mt], p + (wm * 64 + mt * 16 + rlA) * 64 + chA);
    };

    auto compute_stage = [&](int st) {
        const uint32_t base = smb + st * QK_STAGEB;
        const uint32_t pAh = base;
        const uint32_t pAl = base + QT64;
        const uint32_t pBh = base + 2 * QT64;
        const uint32_t pBl = base + 3 * QT64;
        #pragma unroll
        for (int kk = 0; kk < 2; kk++) {
            uint32_t a[4][4], b[4][2];
            // pass 1: Ah * Bh
            ldB(pBh, kk, b);
            ldA(pAh, kk, a);
            #pragma unroll
            for (int mt = 0; mt < 4; mt++)
                #pragma unroll
                for (int nt = 0; nt < 4; nt++)
                    mma_fp16(acc[mt][nt], a[mt], b[nt][0], b[nt][1]);
            // pass 2: Ah * Bl
            ldB(pBl, kk, b);
            #pragma unroll
            for (int mt = 0; mt < 4; mt++)
                #pragma unroll
                for (int nt = 0; nt < 4; nt++)
                    mma_fp16(acc[mt][nt], a[mt], b[nt][0], b[nt][1]);
            // pass 3: Al * Bh
            ldA(pAl, kk, a);
            ldB(pBh, kk, b);
            #pragma unroll
            for (int mt = 0; mt < 4; mt++)
                #pragma unroll
                for (int nt = 0; nt < 4; nt++)
                    mma_fp16(acc[mt][nt], a[mt], b[nt][0], b[nt][1]);
        }
    };

    const int NIT = D_MODEL / 32;
    load_stage(0, 0);
    load_stage(1, 1);
    for (int it = 0; it < NIT; it++) {
        if (it + 2 < NIT) { load_stage(it + 2, (it + 2) % QK_NSTAGE); cp_wait<2>(); }
        else if (it + 1 < NIT) { cp_wait<1>(); }
        else { cp_wait<0>(); }
        __syncthreads();
        compute_stage(it % QK_NSTAGE);
        __syncthreads();
    }

    #pragma unroll
    for (int mt = 0; mt < 4; mt++) {
        int rl = wm * 64 + mt * 16 + g;
        #pragma unroll
        for (int nt = 0; nt < 4; nt++) {
            int col = n0 + wn * 32 + nt * 8 + t4 * 2;
            float b0 = bias[col], b1 = bias[col + 1];
            float v00 = acc[mt][nt][0] + b0, v01 = acc[mt][nt][1] + b1;
            float v10 = acc[mt][nt][2] + b0, v11 = acc[mt][nt][3] + b1;
            if (m0 + rl < cnt) {
                size_t off = (size_t)(m0 + rl) * D_MODEL + col;
                __half h0 = __float2half_rn(v00), h1 = __float2half_rn(v01);
                *(uint32_t*)(oh + off) = pack_h(v00, v01);
                *(uint32_t*)(ol + off) = pack_h(v00 - __half2float(h0),
                                                v01 - __half2float(h1));
            }
            if (m0 + rl + 8 < cnt) {
                size_t off = (size_t)(m0 + rl + 8) * D_MODEL + col;
                __half h0 = __float2half_rn(v10), h1 = __float2half_rn(v11);
                *(uint32_t*)(oh + off) = pack_h(v10, v11);
                *(uint32_t*)(ol + off) = pack_h(v10 - __half2float(h0),
                                                v11 - __half2float(h1));
            }
        }
    }
}

// ========== fp16 single-pass GEMM, 3-stage (proven, unchanged) =============
#define F_STAGEB  (2 * TILEB)
#define F_NSTAGE  3
#define F_SMEM    (F_NSTAGE * F_STAGEB + 512)

template<int MODE>   // 0: V (gather A, fp16 out), 1: O (compacted A, fp32 scatter)
__global__ __launch_bounds__(256, 2) void gemm_f16_kernel(
    const __half* __restrict__ A, const __half* __restrict__ B,
    const float* __restrict__ bias,
    __half* __restrict__ Oh, float* __restrict__ Of)
{
    extern __shared__ __align__(128) char sm[];
    int* sidx = (int*)(sm + F_NSTAGE * F_STAGEB);
    const uint32_t smb = smem_u32(sm);

    const int cnt = g_off[BATCH];
    const int m0 = blockIdx.y * 128;
    if (m0 >= cnt) return;
    const int n0 = blockIdx.x * 128;

    const int tid  = threadIdx.x;
    const int lane = tid & 31;
    const int w    = tid >> 5;
    const int wm   = w & 1;
    const int wn   = w >> 1;
    const int g    = lane >> 2;
    const int t4   = lane & 3;

    const uint32_t aLane = (uint32_t)((lane & 15) * ROWB + (lane >> 4) * 16);
    const uint32_t bLane = (uint32_t)((((lane >> 4) & 1) * 8 + (lane & 7)) * ROWB
                                      + ((lane >> 3) & 1) * 16);

    if (tid < 128)
        sidx[tid] = (m0 + tid < cnt) ? g_gidx[m0 + tid] : g_gidx[0];
    __syncthreads();

    float acc[4][4][4];
    #pragma unroll
    for (int mt = 0; mt < 4; mt++)
        #pragma unroll
        for (int nt = 0; nt < 4; nt++)
            #pragma unroll
            for (int r = 0; r < 4; r++)
                acc[mt][nt][r] = 0.0f;

    auto load_stage = [&](int kc, int st) {
        char* base = sm + st * F_STAGEB;
        #pragma unroll
        for (int t = 0; t < 4; t++) {
            const int tile = t >> 1;
            const int wi   = tid + (t & 1) * 256;
            const int row  = wi >> 2;
            const int ch   = wi & 3;
            int grow;
            if (tile == 0) {
                if (MODE == 0) grow = sidx[row];
                else { int ar = m0 + row; grow = (ar < cnt) ? ar : m0; }
            } else grow = n0 + row;
            const __half* src = (tile == 0 ? A : B) +
                                (size_t)grow * D_MODEL + kc * 32 + ch * 8;
            uint32_t dst = smem_u32(base + tile * TILEB + row * ROWB + ch * 16);
            cp_async16(dst, src);
        }
        cp_commit();
    };

    auto compute_stage = [&](int st) {
        const uint32_t base = smb + st * F_STAGEB;
        const uint32_t pA = base;
        const uint32_t pB = base + TILEB;
        #pragma unroll
        for (int kk = 0; kk < 2; kk++) {
            const uint32_t cB = kk * 32;
            uint32_t b[4][2], a[4][4];
            #pragma unroll
            for (int ntp = 0; ntp < 2; ntp++) {
                uint32_t r4[4];
                ldsm_x4(r4, pB + (wn * 32 + ntp * 16) * ROWB + cB + bLane);
                b[2 * ntp][0] = r4[0]; b[2 * ntp][1] = r4[1];
                b[2 * ntp + 1][0] = r4[2]; b[2 * ntp + 1][1] = r4[3];
            }
            #pragma unroll
            for (int mt = 0; mt < 4; mt++)
                ldsm_x4(a[mt], pA + (wm * 64 + mt * 16) * ROWB + cB + aLane);
            #pragma unroll
            for (int mt = 0; mt < 4; mt++)
                #pragma unroll
                for (int nt = 0; nt < 4; nt++)
                    mma_fp16(acc[mt][nt], a[mt], b[nt][0], b[nt][1]);
        }
    };

    const int NIT = D_MODEL / 32;
    load_stage(0, 0);
    load_stage(1, 1);
    for (int it = 0; it < NIT; it++) {
        if (it + 2 < NIT) { load_stage(it + 2, (it + 2) % F_NSTAGE); cp_wait<2>(); }
        else if (it + 1 < NIT) { cp_wait<1>(); }
        else { cp_wait<0>(); }
        __syncthreads();
        compute_stage(it % F_NSTAGE);
        __syncthreads();
    }

    #pragma unroll
    for (int mt = 0; mt < 4; mt++) {
        int rl = wm * 64 + mt * 16 + g;
        #pragma unroll
        for (int nt = 0; nt < 4; nt++) {
            int col = n0 + wn * 32 + nt * 8 + t4 * 2;
            float b0 = bias[col], b1 = bias[col + 1];
            float v00 = acc[mt][nt][0] + b0, v01 = acc[mt][nt][1] + b1;
            float v10 = acc[mt][nt][2] + b0, v11 = acc[mt][nt][3] + b1;
            if (MODE == 0) {
                if (m0 + rl < cnt)
                    *(uint32_t*)(Oh + (size_t)(m0 + rl) * D_MODEL + col) =
                        pack_h(v00, v01);
                if (m0 + rl + 8 < cnt)
                    *(uint32_t*)(Oh + (size_t)(m0 + rl + 8) * D_MODEL + col) =
                        pack_h(v10, v11);
            } else {
                if (m0 + rl < cnt)
                    *(float2*)(Of + (size_t)sidx[rl] * D_MODEL + col) =
                        make_float2(v00, v01);
                if (m0 + rl + 8 < cnt)
                    *(float2*)(Of + (size_t)sidx[rl + 8] * D_MODEL + col) =
                        make_float2(v10, v11);
            }
        }
    }
}

// ---------------------------------------------------------------------------
// Tensor-core flash attention (proven, unchanged).
// ---------------------------------------------------------------------------
#define AROW   72
#define QTILE  (64 * AROW)
#define OFF_QH 0
#define OFF_QL QTILE
#define OFF_KV(st, a) (2 * QTILE + ((st) * 3 + (a)) * QTILE)
#define ATTN_SMEM (8 * QTILE * 2)

__global__ __launch_bounds__(128) void attn_mma_kernel(
    const __half* __restrict__ Qh, const __half* __restrict__ Ql,
    const __half* __restrict__ Kh, const __half* __restrict__ Kl,
    const __half* __restrict__ V, __half* __restrict__ ctx)
{
    extern __shared__ __align__(128) char smc[];
    const uint32_t smb = smem_u32(smc);

    const int tid = threadIdx.x;
    const int b   = blockIdx.z;
    const int h   = blockIdx.y;
    const int bcnt = g_cnt[b];
    const int boff = g_off[b];
    const int q0   = blockIdx.x * 64;
    if (q0 >= bcnt) return;

    const int lane = tid & 31;
    const int w    = tid >> 5;
    const int g    = lane >> 2;
    const int t4   = lane & 3;
    const int wr   = w * 16;
    const size_t hcol = (size_t)h * HDIM;

    #pragma unroll
    for (int t = 0; t < 8; t++) {
        int i   = tid + t * 128;
        int arr = i >> 9;
        int rem = i & 511;
        int row = rem >> 3;
        int ch  = rem & 7;
        int gr  = (q0 + row < bcnt) ? (boff + q0 + row) : boff;
        const __half* src = (arr ? Ql : Qh) + (size_t)gr * D_MODEL + hcol + ch * 8;
        cp_async16(smb + ((arr ? OFF_QL : OFF_QH) + row * AROW + ch * 8) * 2, src);
    }
    cp_commit();

    auto load_kv = [&](int kv0, int st) {
        #pragma unroll
        for (int t = 0; t < 12; t++) {
            int i   = tid + t * 128;
            int arr = i / 512;
            int rem = i & 511;
            int row = rem >> 3;
            int ch  = rem & 7;
            int gr  = (kv0 + row < bcnt) ? (boff + kv0 + row) : boff;
            const __half* base = (arr == 0) ? Kh : (arr == 1 ? Kl : V);
            cp_async16(smb + (OFF_KV(st, arr) + row * AROW + ch * 8) * 2,
                       base + (size_t)gr * D_MODEL + hcol + ch * 8);
        }
        cp_commit();
    };

    float o[8][4];
    #pragma unroll
    for (int nt = 0; nt < 8; nt++)
        #pragma unroll
        for (int r = 0; r < 4; r++) o[nt][r] = 0.0f;
    float m0r = -1e30f, m1r = -1e30f, l0r = 0.0f, l1r = 0.0f;

    const int nit = (bcnt + 63) >> 6;
    load_kv(0, 0);

    for (int it = 0; it < nit; it++) {
        if (it + 1 < nit) { load_kv((it + 1) << 6, (it + 1) & 1); cp_wait<1>(); }
        else              { cp_wait<0>(); }
        __syncthreads();

        const int st  = it & 1;
        const int kv0 = it << 6;
        const char* pQH = smc + OFF_QH * 2;
        const char* pQL = smc + OFF_QL * 2;
        const char* pKH = smc + OFF_KV(st, 0) * 2;
        const char* pKL = smc + OFF_KV(st, 1) * 2;
        const uint32_t pV = smb + OFF_KV(st, 2) * 2;

        float sacc[8][4];
        #pragma unroll
        for (int nt = 0; nt < 8; nt++)
            #pragma unroll
            for (int r = 0; r < 4; r++) sacc[nt][r] = 0.0f;

        #pragma unroll
        for (int kt = 0; kt < 4; kt++) {
            const int kc = kt * 16 + t4 * 2;
            uint32_t ah[4], al[4];
            {
                int r0 = (wr + g) * AROW + kc;
                int r1 = (wr + g + 8) * AROW + kc;
                ah[0] = *(const uint32_t*)(pQH + r0 * 2);
                ah[1] = *(const uint32_t*)(pQH + r1 * 2);
                ah[2] = *(const uint32_t*)(pQH + (r0 + 8) * 2);
                ah[3] = *(const uint32_t*)(pQH + (r1 + 8) * 2);
                al[0] = *(const uint32_t*)(pQL + r0 * 2);
                al[1] = *(const uint32_t*)(pQL + r1 * 2);
                al[2] = *(const uint32_t*)(pQL + (r0 + 8) * 2);
                al[3] = *(const uint32_t*)(pQL + (r1 + 8) * 2);
            }
            #pragma unroll
            for (int nt = 0; nt < 8; nt++) {
                int rk = (nt * 8 + g) * AROW + kc;
                uint32_t bh0 = *(const uint32_t*)(pKH + rk * 2);
                uint32_t bh1 = *(const uint32_t*)(pKH + (rk + 8) * 2);
                uint32_t bl0 = *(const uint32_t*)(pKL + rk * 2);
                uint32_t bl1 = *(const uint32_t*)(pKL + (rk + 8) * 2);
                mma_fp16(sacc[nt], ah, bh0, bh1);
                mma_fp16(sacc[nt], ah, bl0, bl1);
                mma_fp16(sacc[nt], al, bh0, bh1);
            }
        }

        float mx0 = -1e30f, mx1 = -1e30f;
        #pragma unroll
        for (int nt = 0; nt < 8; nt++) {
            int c0 = kv0 + nt * 8 + 2 * t4;
            if (c0 >= bcnt)     { sacc[nt][0] = NEG_BIG; sacc[nt][2] = NEG_BIG; }
            if (c0 + 1 >= bcnt) { sacc[nt][1] = NEG_BIG; sacc[nt][3] = NEG_BIG; }
            mx0 = fmaxf(mx0, fmaxf(sacc[nt][0], sacc[nt][1]));
            mx1 = fmaxf(mx1, fmaxf(sacc[nt][2], sacc[nt][3]));
        }
        mx0 = fmaxf(mx0, __shfl_xor_sync(0xffffffffu, mx0, 1));
        mx0 = fmaxf(mx0, __shfl_xor_sync(0xffffffffu, mx0, 2));
        mx1 = fmaxf(mx1, __shfl_xor_sync(0xffffffffu, mx1, 1));
        mx1 = fmaxf(mx1, __shfl_xor_sync(0xffffffffu, mx1, 2));

        float mn0 = fmaxf(m0r, mx0), mn1 = fmaxf(m1r, mx1);
        float al0 = __expf(m0r - mn0), al1 = __expf(m1r - mn1);
        float ls0 = 0.0f, ls1 = 0.0f;
        #pragma unroll
        for (int nt = 0; nt < 8; nt++) {
            sacc[nt][0] = __expf(sacc[nt][0] - mn0);
            sacc[nt][1] = __expf(sacc[nt][1] - mn0);
            sacc[nt][2] = __expf(sacc[nt][2] - mn1);
            sacc[nt][3] = __expf(sacc[nt][3] - mn1);
            ls0 += sacc[nt][0] + sacc[nt][1];
            ls1 += sacc[nt][2] + sacc[nt][3];
        }
        ls0 += __shfl_xor_sync(0xffffffffu, ls0, 1);
        ls0 += __shfl_xor_sync(0xffffffffu, ls0, 2);
        ls1 += __shfl_xor_sync(0xffffffffu, ls1, 1);
        ls1 += __shfl_xor_sync(0xffffffffu, ls1, 2);
        l0r = l0r * al0 + ls0;  m0r = mn0;
        l1r = l1r * al1 + ls1;  m1r = mn1;
        #pragma unroll
        for (int nt = 0; nt < 8; nt++) {
            o[nt][0] *= al0; o[nt][1] *= al0;
            o[nt][2] *= al1; o[nt][3] *= al1;
        }

        #pragma unroll
        for (int kt = 0; kt < 4; kt++) {
            uint32_t pa[4];
            pa[0] = pack_h(sacc[2 * kt][0],     sacc[2 * kt][1]);
            pa[1] = pack_h(sacc[2 * kt][2],     sacc[2 * kt][3]);
            pa[2] = pack_h(sacc[2 * kt + 1][0], sacc[2 * kt + 1][1]);
            pa[3] = pack_h(sacc[2 * kt + 1][2], sacc[2 * kt + 1][3]);
            #pragma unroll
            for (int ntp = 0; ntp < 4; ntp++) {
                int mat = lane >> 3, r = lane & 7;
                int vrow = kt * 16 + (mat & 1) * 8 + r;
                int vcol = ntp * 16 + (mat >> 1) * 8;
                uint32_t vb[4];
                ldmatrix_x4_trans(vb, pV + (vrow * AROW + vcol) * 2);
                mma_fp16(o[2 * ntp],     pa, vb[0], vb[1]);
                mma_fp16(o[2 * ntp + 1], pa, vb[2], vb[3]);
            }
        }
        __syncthreads();
    }

    float inv0 = 1.0f / l0r, inv1 = 1.0f / l1r;
    int row0 = q0 + wr + g, row1 = row0 + 8;
    #pragma unroll
    for (int nt = 0; nt < 8; nt++) {
        int col = (int)hcol + nt * 8 + 2 * t4;
        if (row0 < bcnt)
            *(uint32_t*)(ctx + (size_t)(boff + row0) * D_MODEL + col) =
                pack_h(o[nt][0] * inv0, o[nt][1] * inv0);
        if (row1 < bcnt)
            *(uint32_t*)(ctx + (size_t)(boff + row1) * D_MODEL + col) =
                pack_h(o[nt][2] * inv1, o[nt][3] * inv1);
    }
}

// ---------------------------------------------------------------------------
extern "C" void kernel_launch(void* const* d_in, const int* in_sizes, int n_in,
                              void* d_out, int out_size)
{
    (void)in_sizes; (void)n_in; (void)out_size;
    const float* x  = (const float*)d_in[0];
    const int*   pm = (const int*)  d_in[1];
    const float* Wq = (const float*)d_in[2];
    const float* bq = (const float*)d_in[3];
    const float* Wk = (const float*)d_in[4];
    const float* bk = (const float*)d_in[5];
    const float* Wv = (const float*)d_in[6];
    const float* bv = (const float*)d_in[7];
    const float* Wo = (const float*)d_in[8];
    const float* bo = (const float*)d_in[9];
    float* out = (float*)d_out;

    __half *xh, *xl, *wqkh, *wqkl, *wv16, *wo16;
    __half *qh16, *ql16, *kh16, *kl16, *v16, *c16;
    cudaGetSymbolAddress((void**)&xh, g_xh);
    cudaGetSymbolAddress((void**)&xl, g_xl);
    cudaGetSymbolAddress((void**)&wqkh, g_wqk_h);
    cudaGetSymbolAddress((void**)&wqkl, g_wqk_l);
    cudaGetSymbolAddress((void**)&wv16, g_wv16);
    cudaGetSymbolAddress((void**)&wo16, g_wo16);
    cudaGetSymbolAddress((void**)&qh16, g_qh16);
    cudaGetSymbolAddress((void**)&ql16, g_ql16);
    cudaGetSymbolAddress((void**)&kh16, g_kh16);
    cudaGetSymbolAddress((void**)&kl16, g_kl16);
    cudaGetSymbolAddress((void**)&v16, g_v16);
    cudaGetSymbolAddress((void**)&c16, g_c16);

    cudaFuncSetAttribute(gemm_qk_kernel,
                         cudaFuncAttributeMaxDynamicSharedMemorySize, QK_SMEM);
    cudaFuncSetAttribute(gemm_f16_kernel<0>,
                         cudaFuncAttributeMaxDynamicSharedMemorySize, F_SMEM);
    cudaFuncSetAttribute(gemm_f16_kernel<1>,
                         cudaFuncAttributeMaxDynamicSharedMemorySize, F_SMEM);
    cudaFuncSetAttribute(attn_mma_kernel,
                         cudaFuncAttributeMaxDynamicSharedMemorySize, ATTN_SMEM);

    const size_t WSZ = (size_t)D_MODEL * D_MODEL;
    const int n4 = MROWS * D_MODEL / 4;

    split_x_kernel<<<(n4 + 255) / 256, 256>>>(x, xh, xl, n4);
    build_idx_kernel<<<BATCH, 256>>>(pm);
    build_gidx_kernel<<<1, 256>>>();
    bias_fill_kernel<<<n4 / 256, 256>>>(bo, out);

    dim3 tgrid(D_MODEL / 32, D_MODEL / 32, 4), tblk(32, 8);
    transpose_all_kernel<<<tgrid, tblk>>>(Wq, Wk, Wv, Wo,
                                          wqkh + 0 * WSZ, wqkl + 0 * WSZ,
                                          wqkh + 1 * WSZ, wqkl + 1 * WSZ,
                                          wv16, wo16);

    // Q,K projections (fp16 3-pass hi/lo, 3-stage swizzled)
    dim3 qkgrid(D_MODEL / 128, MROWS / 128, 2);
    gemm_qk_kernel<<<qkgrid, 256, QK_SMEM>>>(xh, xl, wqkh, wqkl, bq, bk,
                                             qh16, ql16, kh16, kl16);

    // V projection (fp16 single-pass on x-hi = fp16(x))
    dim3 vgrid(D_MODEL / 128, MROWS / 128);
    gemm_f16_kernel<0><<<vgrid, 256, F_SMEM>>>(xh, wv16, bv, v16, nullptr);

    // attention
    dim3 agrid(S_LEN / 64, NHEAD, BATCH);
    attn_mma_kernel<<<agrid, 128, ATTN_SMEM>>>(qh16, ql16, kh16, kl16, v16, c16);

    // O projection (fp16 single-pass, fp32 scatter)
    gemm_f16_kernel<1><<<vgrid, 256, F_SMEM>>>(c16, wo16, bo, nullptr, out);
}